// round 10
// baseline (speedup 1.0000x reference)
#include <cuda_runtime.h>
#include <cuda_fp16.h>
#include <math.h>
#include <stdint.h>

#define DEV_INLINE __device__ __forceinline__

DEV_INLINE unsigned long long pk2(float lo, float hi) {
    unsigned long long r;
    asm("mov.b64 %0, {%1, %2};" : "=l"(r) : "f"(lo), "f"(hi));
    return r;
}
DEV_INLINE void unpk2(unsigned long long v, float& lo, float& hi) {
    asm("mov.b64 {%0, %1}, %2;" : "=f"(lo), "=f"(hi) : "l"(v));
}
#define FFMA2(d, a, b) asm("fma.rn.f32x2 %0, %1, %2, %0;" : "+l"(d) : "l"(a), "l"(b))

DEV_INLINE void mma_f16(float* c, const uint32_t* a, const uint32_t* b) {
    asm volatile(
        "mma.sync.aligned.m16n8k16.row.col.f32.f16.f16.f32 "
        "{%0,%1,%2,%3}, {%4,%5,%6,%7}, {%8,%9}, {%0,%1,%2,%3};"
        : "+f"(c[0]), "+f"(c[1]), "+f"(c[2]), "+f"(c[3])
        : "r"(a[0]), "r"(a[1]), "r"(a[2]), "r"(a[3]), "r"(b[0]), "r"(b[1]));
}
DEV_INLINE uint32_t ld32s(const __half* p) { return *(const uint32_t*)p; }

// ============================ scratch ============================
__device__ float g_part[5 * 1024 * 1024];
__device__ float g_t2[64 * 1024];
__device__ float g_c1r[64 * 4096];
__device__ float g_c2r[64 * 4096];
__device__ float g_att[9 * 4096];
__device__ float g_gap[4096];
__device__ float g_f4[512];
__device__ float g_b4[512];
__device__ float g_outb[512 * 1024];
__device__ float g_z[19 * 1024];
__device__ float g_zup[19 * 4096];
__device__ __align__(16) __half g_whi[43360256];          // fp16 weights (all segments)
__device__ __align__(16) __half g_xthi[1024 * 4096];      // x transposed [pix][k] hi
__device__ __align__(16) __half g_xtlo[1024 * 4096];
__device__ __align__(16) __half g_fhi[1024 * 2048];       // fcat transposed hi
__device__ __align__(16) __half g_flo[1024 * 2048];
__device__ __align__(16) __half g_c1thi[4096 * 256];      // c1 transposed hi
__device__ __align__(16) __half g_c1tlo[4096 * 256];
__device__ __align__(16) __half g_t1thi[4096 * 64];       // refine1 out transposed hi
__device__ __align__(16) __half g_t1tlo[4096 * 64];

static const size_t S_A0 = 0;
static const size_t S_A1 = 2097152;
static const size_t S_A2 = 20971520;
static const size_t S_A3 = 39845888;
static const size_t S_AP = 41943040;
static const size_t S_RF1 = 42991616;   // 9 taps x 128(pad) x 256
static const size_t S_RF2 = 43286528;   // 9 taps x 128(pad) x 64

// ============================ HMMA GEMM (fp16, generalized) ============================
// part[s][m][pix] = sum_k W[(tap),m][k] * X[pix+shift][k]   (+ optional B-lo pass)
// CTA: 128(m) x 128(pix), 8 warps of 64x32. k-chunks of 64 in smem (stride 72).
template <int USE_LO>
__global__ void __launch_bounds__(256, 2)
hgemm(const __half* __restrict__ Wh,
      const __half* __restrict__ Xhi, const __half* __restrict__ Xlo,
      float* __restrict__ part,
      int Ktot, int Kc, int Kx, int tapMode, int dil, int wshift, int HW, int skipEn)
{
    extern __shared__ __half sm[];
    __half* sAh = sm;                 // 128*72
    __half* sBh = sm + 9216;
    __half* sBl = USE_LO ? sm + 18432 : sm + 9216;

    const int tid = threadIdx.x;
    const int wid = tid >> 5, lane = tid & 31;
    const int s = blockIdx.z;
    const int m0 = blockIdx.y * 128;
    const int n0 = blockIdx.x * 128;
    const int Mpad = gridDim.y * 128;
    const int Wimg = 1 << wshift;

    int dy = 0, dx = 0, k0s = 0;
    size_t wbase = 0;
    if (tapMode) {
        dy = (s / 3 - 1) * dil;
        dx = (s % 3 - 1) * dil;
        wbase = (size_t)s * Mpad * Ktot;
        if (skipEn) {
            int tileRows = 128 >> wshift;
            int r0 = n0 >> wshift;
            if (r0 + tileRows - 1 + dy < 0 || r0 + dy >= Wimg) return;  // masked in reduce
        }
    } else k0s = s * Kc;

    const int wm = (wid & 1) * 64;
    const int wn = (wid >> 1) * 32;
    const int r = lane >> 2;
    const int cp = (lane & 3) * 2;

    float acc[4][4][4];
#pragma unroll
    for (int i = 0; i < 4; i++)
#pragma unroll
        for (int j = 0; j < 4; j++)
#pragma unroll
            for (int q = 0; q < 4; q++) acc[i][j][q] = 0.f;

    const int nChunks = Kc / 64;
    for (int c = 0; c < nChunks; c++) {
        const int kg = k0s + c * 64;
#pragma unroll
        for (int i = 0; i < 4; i++) {
            int v = tid + 256 * i;
            int mr = v >> 3, ko = (v & 7) * 8;
            size_t ga = wbase + (size_t)(m0 + mr) * Ktot + kg + ko;
            *(uint4*)&sAh[mr * 72 + ko] = *(const uint4*)(Wh + ga);
        }
#pragma unroll
        for (int i = 0; i < 4; i++) {
            int v = tid + 256 * i;
            int nr = v >> 3, ko = (v & 7) * 8;
            int q = n0 + nr;
            int iy = (q >> wshift) + dy, ix = (q & (Wimg - 1)) + dx;
            uint4 h = make_uint4(0u, 0u, 0u, 0u);
            uint4 l = make_uint4(0u, 0u, 0u, 0u);
            if ((unsigned)iy < (unsigned)Wimg && (unsigned)ix < (unsigned)Wimg) {
                size_t gb = (size_t)((iy << wshift) + ix) * Kx + kg + ko;
                h = *(const uint4*)(Xhi + gb);
                if (USE_LO) l = *(const uint4*)(Xlo + gb);
            }
            *(uint4*)&sBh[nr * 72 + ko] = h;
            if (USE_LO) *(uint4*)&sBl[nr * 72 + ko] = l;
        }
        __syncthreads();

#pragma unroll
        for (int kk = 0; kk < 64; kk += 16) {
            uint32_t af[4][4], bh[4][2];
#pragma unroll
            for (int im = 0; im < 4; im++) {
                const __half* p = sAh + (wm + im * 16 + r) * 72 + kk + cp;
                af[im][0] = ld32s(p);
                af[im][1] = ld32s(p + 8 * 72);
                af[im][2] = ld32s(p + 8);
                af[im][3] = ld32s(p + 8 * 72 + 8);
            }
#pragma unroll
            for (int in_ = 0; in_ < 4; in_++) {
                const __half* ph = sBh + (wn + in_ * 8 + r) * 72 + kk + cp;
                bh[in_][0] = ld32s(ph);
                bh[in_][1] = ld32s(ph + 8);
            }
#pragma unroll
            for (int im = 0; im < 4; im++)
#pragma unroll
                for (int in_ = 0; in_ < 4; in_++) mma_f16(acc[im][in_], af[im], bh[in_]);
            if (USE_LO) {
                uint32_t bl[4][2];
#pragma unroll
                for (int in_ = 0; in_ < 4; in_++) {
                    const __half* pl = sBl + (wn + in_ * 8 + r) * 72 + kk + cp;
                    bl[in_][0] = ld32s(pl);
                    bl[in_][1] = ld32s(pl + 8);
                }
#pragma unroll
                for (int im = 0; im < 4; im++)
#pragma unroll
                    for (int in_ = 0; in_ < 4; in_++) mma_f16(acc[im][in_], af[im], bl[in_]);
            }
        }
        __syncthreads();
    }

    float* po = part + (size_t)s * Mpad * HW;
    const int rbase = m0 + wm + r;
    const int cbase = n0 + wn + cp;
#pragma unroll
    for (int im = 0; im < 4; im++)
#pragma unroll
        for (int in_ = 0; in_ < 4; in_++) {
            int m = rbase + im * 16, n = cbase + in_ * 8;
            float2 v0 = make_float2(acc[im][in_][0], acc[im][in_][1]);
            float2 v1 = make_float2(acc[im][in_][2], acc[im][in_][3]);
            *(float2*)&po[(size_t)m * HW + n] = v0;
            *(float2*)&po[(size_t)(m + 8) * HW + n] = v1;
        }
}

// reduce slices + bn_relu, write TRANSPOSED fp16 hi/lo (tap-masked by row)
__global__ void reduce_ht(const float* __restrict__ part, int S, int Mpad, int HW,
                          const float* __restrict__ sc, const float* __restrict__ bi,
                          __half* __restrict__ ohi, __half* __restrict__ olo,
                          int ostride, int colOff, int tapDil, int wshift)
{
    __shared__ float t[32][33];
    int tx = threadIdx.x & 31, ty = threadIdx.x >> 5;
    int q0 = blockIdx.x * 32, m0 = blockIdx.y * 32;
    int y = q0 >> wshift;
    int Wimg = 1 << wshift;
#pragma unroll
    for (int r = 0; r < 4; r++) {
        int ml = ty + 8 * r;
        int m = m0 + ml;
        float a = 0.f;
        for (int s = 0; s < S; s++) {
            if (tapDil) {
                int dy = (s / 3 - 1) * tapDil;
                if ((unsigned)(y + dy) >= (unsigned)Wimg) continue;
            }
            a += part[(size_t)s * Mpad * HW + (size_t)m * HW + q0 + tx];
        }
        t[ml][tx] = fmaxf(sc[m] * a + bi[m], 0.f);
    }
    __syncthreads();
#pragma unroll
    for (int r = 0; r < 4; r++) {
        int ql = ty + 8 * r;
        float v = t[tx][ql];
        __half h = __float2half_rn(v);
        size_t o = (size_t)(q0 + ql) * ostride + colOff + m0 + tx;
        ohi[o] = h;
        olo[o] = __float2half_rn(v - __half2float(h));
    }
}

// reduce slices + epilogue to plain fp32 (flags: 2=scale/bias 4=relu 8=pre-bias)
__global__ void reduce_pl(const float* __restrict__ part, float* __restrict__ out,
                          int S, int Mpad, int HW, int Mtot, int flags,
                          const float* __restrict__ sc, const float* __restrict__ bi,
                          const float* __restrict__ eb, int tapDil, int wshift)
{
    int idx = blockIdx.x * 256 + threadIdx.x;
    if (idx >= Mtot * HW) return;
    int m = idx / HW;
    int p = idx - m * HW;
    int y = p >> wshift;
    int Wimg = 1 << wshift;
    float a = 0.f;
    for (int s = 0; s < S; s++) {
        if (tapDil) {
            int dy = (s / 3 - 1) * tapDil;
            if ((unsigned)(y + dy) >= (unsigned)Wimg) continue;
        }
        a += part[(size_t)s * Mpad * HW + idx];
    }
    if (flags & 8) a += eb[m];
    if (flags & 2) a = sc[m] * a + bi[m];
    if (flags & 4) a = fmaxf(a, 0.f);
    out[idx] = a;
}

// ============================ conversion pre-passes ============================
// in [K][HW] fp32 -> out [HW][K] fp16 hi/lo
__global__ void xtrans_g(const float* __restrict__ in,
                         __half* __restrict__ ohi, __half* __restrict__ olo,
                         int HW, int K) {
    __shared__ float t[32][33];
    int tx = threadIdx.x & 31, ty = threadIdx.x >> 5;
    int q0 = blockIdx.x * 32, k0 = blockIdx.y * 32;
#pragma unroll
    for (int r = 0; r < 4; r++)
        t[ty + 8 * r][tx] = in[(size_t)(k0 + ty + 8 * r) * HW + q0 + tx];
    __syncthreads();
#pragma unroll
    for (int r = 0; r < 4; r++) {
        int ql = ty + 8 * r;
        float v = t[tx][ql];
        __half h = __float2half_rn(v);
        size_t o = (size_t)(q0 + ql) * K + k0 + tx;
        ohi[o] = h;
        olo[o] = __float2half_rn(v - __half2float(h));
    }
}

__global__ void wconv1x1(const float* __restrict__ in, int rowStride, int K,
                         __half* __restrict__ whi, int total4) {
    int i = blockIdx.x * 256 + threadIdx.x;
    if (i >= total4) return;
    int e = i * 4, m = e / K, k = e - m * K;
    float4 v = *(const float4*)(in + (size_t)m * rowStride + k);
    size_t o = (size_t)m * K + k;
    *(__half2*)(whi + o) = __floats2half2_rn(v.x, v.y);
    *(__half2*)(whi + o + 2) = __floats2half2_rn(v.z, v.w);
}

// 3x3 weights [m][k][tap] -> tap-major [tap][512][k] fp16
__global__ void wconv3x3(const float* __restrict__ in, __half* __restrict__ whi) {
    __shared__ float st[4608];
    int m = blockIdx.x, kb = blockIdx.y;
    const float* src = in + (size_t)m * 36864 + (size_t)kb * 4608;
    for (int i = threadIdx.x; i < 1152; i += 256)
        *(float4*)(st + 4 * i) = *(const float4*)(src + 4 * i);
    __syncthreads();
    for (int j = threadIdx.x; j < 2304; j += 256) {
        int t = j / 256, k = (j & 255) * 2;
        size_t o = ((size_t)t * 512 + m) * 4096 + kb * 512 + k;
        *(__half2*)(whi + o) = __floats2half2_rn(st[k * 9 + t], st[(k + 1) * 9 + t]);
    }
}

__global__ void wcenter(const float* __restrict__ in, __half* __restrict__ whi) {
    int i = blockIdx.x * 256 + threadIdx.x;
    if (i >= 512 * 2048) return;
    int e = i * 2, m = e >> 12, k = e & 4095;
    const float* p = in + (size_t)m * 36864 + k * 9 + 4;
    *(__half2*)(whi + e) = __floats2half2_rn(p[0], p[9]);
}

// refine weights [m][k][tap] (m<64) -> [tap][128 pad][K] fp16 (pad rows stay 0)
__global__ void wrf_k(const float* __restrict__ in, __half* __restrict__ out, int M, int K) {
    int i = blockIdx.x * 256 + threadIdx.x;
    if (i >= M * K * 9) return;
    int m = i / (K * 9);
    int rem = i - m * K * 9;
    int k = rem / 9, t = rem - k * 9;
    out[((size_t)t * 128 + m) * K + k] = __float2half_rn(in[i]);
}

// ============================ FFMA2 path (r2, c6) ============================
DEV_INLINE void tap_rect(int ti, int d, int centerOnly, int H, int W,
                         int& dy, int& dx, int& y0, int& x0, int& rh, int& rw) {
    if (centerOnly || d == 0) { dy = dx = 0; y0 = x0 = 0; rh = H; rw = W; return; }
    dy = (ti / 3 - 1) * d;
    dx = (ti % 3 - 1) * d;
    y0 = dy < 0 ? -dy : 0;
    x0 = dx < 0 ? -dx : 0;
    rh = H - (dy < 0 ? -dy : dy);
    rw = W - (dx < 0 ? -dx : dx);
}

template <int MT>
__global__ void __launch_bounds__(256, 2)
gemm2(const float* __restrict__ W, int Arow, int wstride, int wofs0, int centerOnly,
      const float* __restrict__ X, float* __restrict__ part,
      int M, int Kc, int kch, int H, int Wd, int d)
{
    constexpr int NT = 64, KT = 16;
    constexpr int ROWS = MT / 16;
    __shared__ float sA[KT][MT + 4];
    __shared__ float sB[KT][NT + 4];

    const int tid = threadIdx.x;
    const int s = blockIdx.z;
    const int ti = s / kch;
    const int kc = s - ti * kch;
    int dy, dx, y0, x0, rh, rw;
    tap_rect(ti, d, centerOnly, H, Wd, dy, dx, y0, x0, rh, rw);
    const int rectN = rh * rw;
    const int HW = H * Wd;
    const int n0 = blockIdx.x * NT;
    if (n0 >= rectN) return;
    const int m0 = blockIdx.y * MT;
    const int wofs = centerOnly ? wofs0 : ti;
    const int kcS = kc * Kc;

    const int nB = tid & 63, kB = tid >> 6;
    bool bval = false;
    const float* pB[4];
    {
        int pofs = 0;
        int nn = n0 + nB;
        if (nn < rectN) {
            int yy = nn / rw, xx = nn - yy * rw;
            bval = true;
            pofs = (y0 + yy + dy) * Wd + (x0 + xx + dx);
        }
#pragma unroll
        for (int t = 0; t < 4; t++) pB[t] = X + (size_t)(kcS + kB + 4 * t) * HW + pofs;
    }
    const int kA = tid & 15, mA = tid >> 4;
    const float* pA[ROWS];
    bool aval[ROWS];
#pragma unroll
    for (int t = 0; t < ROWS; t++) {
        int mg = m0 + mA + 16 * t;
        aval[t] = (mg < M);
        pA[t] = W + (aval[t] ? ((size_t)mg * Arow + wofs + (size_t)(kcS + kA) * wstride) : 0);
    }

    unsigned long long acc[ROWS][2];
#pragma unroll
    for (int i = 0; i < ROWS; i++) { acc[i][0] = 0ull; acc[i][1] = 0ull; }

    float rA[ROWS], rB[4];
#pragma unroll
    for (int t = 0; t < ROWS; t++) { rA[t] = aval[t] ? __ldg(pA[t]) : 0.f; pA[t] += (size_t)KT * wstride; }
#pragma unroll
    for (int t = 0; t < 4; t++) { rB[t] = bval ? __ldg(pB[t]) : 0.f; pB[t] += (size_t)KT * HW; }

    const int tx = tid & 15, ty = tid >> 4;

    for (int k0 = 0; k0 < Kc; k0 += KT) {
#pragma unroll
        for (int t = 0; t < ROWS; t++) sA[kA][mA + 16 * t] = rA[t];
#pragma unroll
        for (int t = 0; t < 4; t++) sB[kB + 4 * t][nB] = rB[t];
        __syncthreads();
        if (k0 + KT < Kc) {
#pragma unroll
            for (int t = 0; t < ROWS; t++) { rA[t] = aval[t] ? __ldg(pA[t]) : 0.f; pA[t] += (size_t)KT * wstride; }
#pragma unroll
            for (int t = 0; t < 4; t++) { rB[t] = bval ? __ldg(pB[t]) : 0.f; pB[t] += (size_t)KT * HW; }
        }
#pragma unroll
        for (int kk = 0; kk < KT; kk++) {
            const unsigned long long* bp =
                reinterpret_cast<const unsigned long long*>(&sB[kk][tx * 4]);
            unsigned long long b0 = bp[0], b1 = bp[1];
            const float* ar = &sA[kk][ty * ROWS];
#pragma unroll
            for (int i = 0; i < ROWS; i++) {
                float a = ar[i];
                unsigned long long ap = pk2(a, a);
                FFMA2(acc[i][0], ap, b0);
                FFMA2(acc[i][1], ap, b1);
            }
        }
        __syncthreads();
    }

    float* po = part + (size_t)s * M * HW;
#pragma unroll
    for (int i = 0; i < ROWS; i++) {
        int m = m0 + ty * ROWS + i;
        if (m >= M) continue;
        float vals[4];
        unpk2(acc[i][0], vals[0], vals[1]);
        unpk2(acc[i][1], vals[2], vals[3]);
#pragma unroll
        for (int j = 0; j < 4; j++) {
            int n2 = n0 + tx * 4 + j;
            if (n2 >= rectN) continue;
            int yy = n2 / rw, xx = n2 - yy * rw;
            po[(size_t)m * HW + (y0 + yy) * Wd + (x0 + xx)] = vals[j];
        }
    }
}

__global__ void reduce_k(const float* __restrict__ part, float* __restrict__ out,
                         int M, int H, int W, int d, int centerOnly, int ntaps, int kch,
                         int flags, const float* __restrict__ sc,
                         const float* __restrict__ bi, const float* __restrict__ eb) {
    int HW = H * W;
    int idx = blockIdx.x * 256 + threadIdx.x;
    if (idx >= M * HW) return;
    int m = idx / HW;
    int p = idx - m * HW;
    int y = p / W, x = p - y * W;
    float acc = 0.f;
    for (int s = 0; s < ntaps * kch; s++) {
        int ti = s / kch;
        int dy, dx, y0, x0, rh, rw;
        tap_rect(ti, d, centerOnly, H, W, dy, dx, y0, x0, rh, rw);
        if (y >= y0 && y < y0 + rh && x >= x0 && x < x0 + rw)
            acc += part[(size_t)s * M * HW + idx];
    }
    if (flags & 8) acc += eb[m];
    if (flags & 2) acc = sc[m] * acc + bi[m];
    if (flags & 4) acc = fmaxf(acc, 0.f);
    out[idx] = acc;
}

// ============================ small kernels ============================
__global__ void resize_kk(const float* __restrict__ in, float* __restrict__ out,
                          int C, int Hi, int Wi, int Ho, int Wo, int dorelu) {
    int i = blockIdx.x * 256 + threadIdx.x;
    int total = C * Ho * Wo;
    if (i >= total) return;
    int ox = i % Wo;
    int t = i / Wo;
    int oy = t % Ho;
    int c = t / Ho;
    float ry = (Ho > 1) ? (float)(Hi - 1) / (float)(Ho - 1) : 0.f;
    float rx = (Wo > 1) ? (float)(Wi - 1) / (float)(Wo - 1) : 0.f;
    float tyf = oy * ry;
    int yl = (int)floorf(tyf);
    float fy = tyf - yl;
    int yh = min(yl + 1, Hi - 1);
    float txf = ox * rx;
    int xl = (int)floorf(txf);
    float fx = txf - xl;
    int xh = min(xl + 1, Wi - 1);
    const float* p = in + (size_t)c * Hi * Wi;
    float v00 = p[yl * Wi + xl], v01 = p[yl * Wi + xh];
    float v10 = p[yh * Wi + xl], v11 = p[yh * Wi + xh];
    float v = (v00 * (1.f - fy) + v10 * fy) * (1.f - fx) + (v01 * (1.f - fy) + v11 * fy) * fx;
    if (dorelu) v = fmaxf(v, 0.f);
    out[i] = v;
}

__global__ void energy_k(const float* __restrict__ c1r, const float* __restrict__ c2r,
                         float* __restrict__ att) {
    int p = blockIdx.x * 256 + threadIdx.x;
    if (p >= 4096) return;
    int y = p >> 6, x = p & 63;
    float e[9];
    int nidx[9];
    bool val[9];
#pragma unroll
    for (int a = 0; a < 3; a++)
#pragma unroll
        for (int b = 0; b < 3; b++) {
            int k = a * 3 + b;
            int iy = y + 2 * (a - 1), ix = x + 2 * (b - 1);
            val[k] = (unsigned)iy < 64u && (unsigned)ix < 64u;
            nidx[k] = val[k] ? (iy * 64 + ix) : 0;
            e[k] = 0.f;
        }
    for (int c = 0; c < 64; c++) {
        float v = c1r[c * 4096 + p];
        const float* row = c2r + c * 4096;
#pragma unroll
        for (int k = 0; k < 9; k++)
            if (val[k]) e[k] = fmaf(v, row[nidx[k]], e[k]);
    }
    float mx = e[0];
#pragma unroll
    for (int k = 1; k < 9; k++) mx = fmaxf(mx, e[k]);
    float sum = 0.f, ex[9];
#pragma unroll
    for (int k = 0; k < 9; k++) { ex[k] = expf(e[k] - mx); sum += ex[k]; }
    float inv = 1.f / sum;
#pragma unroll
    for (int k = 0; k < 9; k++) att[k * 4096 + p] = ex[k] * inv;
}

__global__ void gap_k(const float* __restrict__ x, float* __restrict__ gap) {
    int c = blockIdx.x * 8 + (threadIdx.x >> 5);
    int lane = threadIdx.x & 31;
    const float* p = x + (size_t)c * 1024;
    float s = 0.f;
    for (int i = lane; i < 1024; i += 32) s += p[i];
#pragma unroll
    for (int o = 16; o; o >>= 1) s += __shfl_xor_sync(0xffffffffu, s, o);
    if (!lane) gap[c] = s * (1.f / 1024.f);
}

__global__ void f4_k(const float* __restrict__ w, const float* __restrict__ s,
                     const float* __restrict__ b, const float* __restrict__ gap,
                     float* __restrict__ f4) {
    int o = blockIdx.x * 8 + (threadIdx.x >> 5);
    int lane = threadIdx.x & 31;
    const float* row = w + (size_t)o * 4096;
    float acc = 0.f;
    for (int i = lane; i < 4096; i += 32) acc = fmaf(row[i], gap[i], acc);
#pragma unroll
    for (int off = 16; off; off >>= 1) acc += __shfl_xor_sync(0xffffffffu, acc, off);
    if (!lane) f4[o] = fmaxf(s[o] * acc + b[o], 0.f);
}

__global__ void bias4_k(const float* __restrict__ apw, const float* __restrict__ f4,
                        float* __restrict__ b4) {
    int o = blockIdx.x * 8 + (threadIdx.x >> 5);
    int lane = threadIdx.x & 31;
    const float* row = apw + (size_t)o * 2560 + 2048;
    float acc = 0.f;
    for (int i = lane; i < 512; i += 32) acc = fmaf(row[i], f4[i], acc);
#pragma unroll
    for (int off = 16; off; off >>= 1) acc += __shfl_xor_sync(0xffffffffu, acc, off);
    if (!lane) b4[o] = acc;
}

__global__ void agg_k(const float* __restrict__ att, const float* __restrict__ zup,
                      const float* __restrict__ c6b, float* __restrict__ out) {
    int p = blockIdx.x * 256 + threadIdx.x;
    if (p >= 4096) return;
    int y = p >> 6, x = p & 63;
    float acc[19];
#pragma unroll
    for (int o = 0; o < 19; o++) acc[o] = c6b[o];
#pragma unroll
    for (int a = 0; a < 3; a++)
#pragma unroll
        for (int b = 0; b < 3; b++) {
            int k = a * 3 + b;
            int iy = y + 2 * (a - 1), ix = x + 2 * (b - 1);
            if ((unsigned)iy < 64u && (unsigned)ix < 64u) {
                float w = att[k * 4096 + p];
                int n = iy * 64 + ix;
#pragma unroll
                for (int o = 0; o < 19; o++) acc[o] = fmaf(w, zup[o * 4096 + n], acc[o]);
            }
        }
#pragma unroll
    for (int o = 0; o < 19; o++) out[o * 4096 + p] = acc[o];
}

// ============================ host driver ============================
static float* g_part_p;

static void run_conv(int mt, const float* Wt, int Arow, int wstride, int wofs0, int centerOnly,
                     const float* X, float* Cout,
                     int M, int K, int H, int Wd, int d, int kch,
                     const float* sc, const float* bi, const float* eb, int flags) {
    int ntaps = (d > 0 && !centerOnly) ? 9 : 1;
    int HW = H * Wd;
    int Kc = K / kch;
    dim3 grid((HW + 63) / 64, (M + mt - 1) / mt, ntaps * kch);
    if (mt == 128)
        gemm2<128><<<grid, 256>>>(Wt, Arow, wstride, wofs0, centerOnly, X, g_part_p,
                                  M, Kc, kch, H, Wd, d);
    else
        gemm2<64><<<grid, 256>>>(Wt, Arow, wstride, wofs0, centerOnly, X, g_part_p,
                                 M, Kc, kch, H, Wd, d);
    int tot = M * HW;
    reduce_k<<<(tot + 255) / 256, 256>>>(g_part_p, Cout, M, H, Wd, d, centerOnly,
                                         ntaps, kch, flags, sc, bi, eb);
}

extern "C" void kernel_launch(void* const* d_in, const int* in_sizes, int n_in,
                              void* d_out, int out_size) {
    const float* c1 = (const float*)d_in[0];
    const float* c2 = (const float*)d_in[1];
    const float* x = (const float*)d_in[2];
    const float* rf1_w = (const float*)d_in[3];
    const float* rf1_s = (const float*)d_in[4];
    const float* rf1_b = (const float*)d_in[5];
    const float* rf2_w = (const float*)d_in[6];
    const float* rf2_s = (const float*)d_in[7];
    const float* rf2_b = (const float*)d_in[8];
    const float* r2_w = (const float*)d_in[9];
    const float* r2_s = (const float*)d_in[10];
    const float* r2_b = (const float*)d_in[11];
    const float* a0_w = (const float*)d_in[12];
    const float* a0_s = (const float*)d_in[13];
    const float* a0_b = (const float*)d_in[14];
    const float* a1_w = (const float*)d_in[15];
    const float* a1_s = (const float*)d_in[16];
    const float* a1_b = (const float*)d_in[17];
    const float* a2_w = (const float*)d_in[18];
    const float* a2_s = (const float*)d_in[19];
    const float* a2_b = (const float*)d_in[20];
    const float* a3_w = (const float*)d_in[21];
    const float* a3_s = (const float*)d_in[22];
    const float* a3_b = (const float*)d_in[23];
    const float* a4_w = (const float*)d_in[24];
    const float* a4_s = (const float*)d_in[25];
    const float* a4_b = (const float*)d_in[26];
    const float* ap_w = (const float*)d_in[27];
    const float* ap_s = (const float*)d_in[28];
    const float* ap_b = (const float*)d_in[29];
    const float* c6_w = (const float*)d_in[30];
    const float* c6_b = (const float*)d_in[31];

    float *t2, *c1r, *c2r, *att, *gap, *f4, *b4, *outb, *z, *zup;
    __half *whi, *xthi, *xtlo, *fhi, *flo, *c1thi, *c1tlo, *t1thi, *t1tlo;
    cudaGetSymbolAddress((void**)&g_part_p, g_part);
    cudaGetSymbolAddress((void**)&t2, g_t2);
    cudaGetSymbolAddress((void**)&c1r, g_c1r);
    cudaGetSymbolAddress((void**)&c2r, g_c2r);
    cudaGetSymbolAddress((void**)&att, g_att);
    cudaGetSymbolAddress((void**)&gap, g_gap);
    cudaGetSymbolAddress((void**)&f4, g_f4);
    cudaGetSymbolAddress((void**)&b4, g_b4);
    cudaGetSymbolAddress((void**)&outb, g_outb);
    cudaGetSymbolAddress((void**)&z, g_z);
    cudaGetSymbolAddress((void**)&zup, g_zup);
    cudaGetSymbolAddress((void**)&whi, g_whi);
    cudaGetSymbolAddress((void**)&xthi, g_xthi);
    cudaGetSymbolAddress((void**)&xtlo, g_xtlo);
    cudaGetSymbolAddress((void**)&fhi, g_fhi);
    cudaGetSymbolAddress((void**)&flo, g_flo);
    cudaGetSymbolAddress((void**)&c1thi, g_c1thi);
    cudaGetSymbolAddress((void**)&c1tlo, g_c1tlo);
    cudaGetSymbolAddress((void**)&t1thi, g_t1thi);
    cudaGetSymbolAddress((void**)&t1tlo, g_t1tlo);

    const int SMEM_H1 = 2 * 9216 * 2;   // 36864 B (single-pass)
    const int SMEM_H2 = 3 * 9216 * 2;   // 55296 B (2-pass)
    cudaFuncSetAttribute(hgemm<0>, cudaFuncAttributeMaxDynamicSharedMemorySize, SMEM_H1);
    cudaFuncSetAttribute(hgemm<1>, cudaFuncAttributeMaxDynamicSharedMemorySize, SMEM_H2);

    // --- conversions (launch #6 = a1 hgemm for ncu -s 5 -c 1) ---
    xtrans_g<<<dim3(32, 128), 256>>>(x, xthi, xtlo, 1024, 4096);                       // 1
    wconv3x3<<<dim3(512, 8), 256>>>(a1_w, whi + S_A1);                                 // 2
    wconv3x3<<<dim3(512, 8), 256>>>(a2_w, whi + S_A2);                                 // 3
    wconv1x1<<<(512 * 4096 / 4 + 255) / 256, 256>>>(a0_w, 4096, 4096, whi + S_A0, 512 * 1024); // 4
    wcenter<<<(512 * 2048 + 255) / 256, 256>>>(a3_w, whi + S_A3);                      // 5
    // --- ASPP big convs: single-pass fp16 HMMA ---
    hgemm<0><<<dim3(8, 4, 9), 256, SMEM_H1>>>(whi + S_A1, xthi, nullptr, g_part_p,
                                              4096, 4096, 4096, 1, 12, 5, 1024, 1);    // 6 <- profiled
    reduce_ht<<<dim3(32, 16), 256>>>(g_part_p, 9, 512, 1024, a1_s, a1_b, fhi, flo, 2048, 512, 12, 5);
    hgemm<0><<<dim3(8, 4, 9), 256, SMEM_H1>>>(whi + S_A2, xthi, nullptr, g_part_p,
                                              4096, 4096, 4096, 1, 24, 5, 1024, 1);
    reduce_ht<<<dim3(32, 16), 256>>>(g_part_p, 9, 512, 1024, a2_s, a2_b, fhi, flo, 2048, 1024, 24, 5);
    hgemm<0><<<dim3(8, 4, 8), 256, SMEM_H1>>>(whi + S_A0, xthi, nullptr, g_part_p,
                                              4096, 512, 4096, 0, 0, 5, 1024, 0);
    reduce_ht<<<dim3(32, 16), 256>>>(g_part_p, 8, 512, 1024, a0_s, a0_b, fhi, flo, 2048, 0, 0, 5);
    hgemm<0><<<dim3(8, 4, 8), 256, SMEM_H1>>>(whi + S_A3, xthi, nullptr, g_part_p,
                                              4096, 512, 4096, 0, 0, 5, 1024, 0);
    reduce_ht<<<dim3(32, 16), 256>>>(g_part_p, 8, 512, 1024, a3_s, a3_b, fhi, flo, 2048, 1536, 0, 5);

    // --- attention branch: refine convs on HMMA (2-pass for accuracy) ---
    xtrans_g<<<dim3(128, 8), 256>>>(c1, c1thi, c1tlo, 4096, 256);
    wrf_k<<<(64 * 256 * 9 + 255) / 256, 256>>>(rf1_w, whi + S_RF1, 64, 256);
    wrf_k<<<(64 * 64 * 9 + 255) / 256, 256>>>(rf2_w, whi + S_RF2, 64, 64);
    hgemm<1><<<dim3(32, 1, 9), 256, SMEM_H2>>>(whi + S_RF1, c1thi, c1tlo, g_part_p,
                                               256, 256, 256, 1, 2, 6, 4096, 1);
    reduce_ht<<<dim3(128, 2), 256>>>(g_part_p, 9, 128, 4096, rf1_s, rf1_b, t1thi, t1tlo, 64, 0, 2, 6);
    hgemm<1><<<dim3(32, 1, 9), 256, SMEM_H2>>>(whi + S_RF2, t1thi, t1tlo, g_part_p,
                                               64, 64, 64, 1, 2, 6, 4096, 1);
    reduce_pl<<<(64 * 4096 + 255) / 256, 256>>>(g_part_p, c1r, 9, 128, 4096, 64, 6,
                                                rf2_s, rf2_b, nullptr, 2, 6);
    run_conv(64, r2_w, 512, 1, 0, 1, c2, t2, 64, 512, 32, 32, 0, 4, r2_s, r2_b, nullptr, 2);
    resize_kk<<<(64 * 4096 + 255) / 256, 256>>>(t2, c2r, 64, 32, 32, 64, 64, 1);
    energy_k<<<16, 256>>>(c1r, c2r, att);

    // --- GAP branch + ap (2-pass: exact fcat via hi/lo) ---
    gap_k<<<512, 256>>>(x, gap);
    f4_k<<<64, 256>>>(a4_w, a4_s, a4_b, gap, f4);
    bias4_k<<<64, 256>>>(ap_w, f4, b4);
    wconv1x1<<<(512 * 2048 / 4 + 255) / 256, 256>>>(ap_w, 2560, 2048, whi + S_AP, 512 * 512);
    hgemm<1><<<dim3(8, 4, 8), 256, SMEM_H2>>>(whi + S_AP, fhi, flo, g_part_p,
                                              2048, 256, 2048, 0, 0, 5, 1024, 0);
    reduce_pl<<<2048, 256>>>(g_part_p, outb, 8, 512, 1024, 512, 2 | 4 | 8,
                             ap_s, ap_b, b4, 0, 5);

    // --- final head ---
    run_conv(64, c6_w, 512, 1, 0, 1, outb, z, 19, 512, 32, 32, 0, 4, nullptr, nullptr, nullptr, 0);
    resize_kk<<<(19 * 4096 + 255) / 256, 256>>>(z, zup, 19, 32, 32, 64, 64, 0);
    agg_k<<<16, 256>>>(att, zup, c6_b, (float*)d_out);
}

// round 11
// speedup vs baseline: 1.5685x; 1.5685x over previous
#include <cuda_runtime.h>
#include <cuda_fp16.h>
#include <math.h>
#include <stdint.h>

#define DEV_INLINE __device__ __forceinline__

DEV_INLINE unsigned long long pk2(float lo, float hi) {
    unsigned long long r;
    asm("mov.b64 %0, {%1, %2};" : "=l"(r) : "f"(lo), "f"(hi));
    return r;
}
DEV_INLINE void unpk2(unsigned long long v, float& lo, float& hi) {
    asm("mov.b64 {%0, %1}, %2;" : "=f"(lo), "=f"(hi) : "l"(v));
}
#define FFMA2(d, a, b) asm("fma.rn.f32x2 %0, %1, %2, %0;" : "+l"(d) : "l"(a), "l"(b))

DEV_INLINE void mma_f16(float* c, const uint32_t* a, const uint32_t* b) {
    asm volatile(
        "mma.sync.aligned.m16n8k16.row.col.f32.f16.f16.f32 "
        "{%0,%1,%2,%3}, {%4,%5,%6,%7}, {%8,%9}, {%0,%1,%2,%3};"
        : "+f"(c[0]), "+f"(c[1]), "+f"(c[2]), "+f"(c[3])
        : "r"(a[0]), "r"(a[1]), "r"(a[2]), "r"(a[3]), "r"(b[0]), "r"(b[1]));
}
DEV_INLINE uint32_t ld32s(const __half* p) { return *(const uint32_t*)p; }

#define CP_ASYNC_CG(dst, src, sz) \
    asm volatile("cp.async.cg.shared.global [%0], [%1], 16, %2;" \
                 :: "r"(dst), "l"(src), "r"(sz) : "memory")
#define CP_COMMIT() asm volatile("cp.async.commit_group;" ::: "memory")
#define CP_WAIT1() asm volatile("cp.async.wait_group 1;" ::: "memory")

// ============================ scratch ============================
__device__ float g_part[5 * 1024 * 1024];
__device__ float g_t2[64 * 1024];
__device__ float g_c1r[64 * 4096];
__device__ float g_c2r[64 * 4096];
__device__ float g_att[9 * 4096];
__device__ float g_gap[4096];
__device__ float g_f4[512];
__device__ float g_b4[512];
__device__ float g_outb[512 * 1024];
__device__ float g_z[19 * 1024];
__device__ float g_zup[19 * 4096];
__device__ __align__(16) __half g_whi[43360256];
__device__ __align__(16) __half g_xthi[1024 * 4096];
__device__ __align__(16) __half g_xtlo[1024 * 4096];
__device__ __align__(16) __half g_fhi[1024 * 2048];
__device__ __align__(16) __half g_flo[1024 * 2048];
__device__ __align__(16) __half g_c1thi[4096 * 256];
__device__ __align__(16) __half g_c1tlo[4096 * 256];
__device__ __align__(16) __half g_t1thi[4096 * 64];
__device__ __align__(16) __half g_t1tlo[4096 * 64];

static const size_t S_A0 = 0;
static const size_t S_A1 = 2097152;
static const size_t S_A2 = 20971520;
static const size_t S_A3 = 39845888;
static const size_t S_AP = 41943040;
static const size_t S_RF1 = 42991616;
static const size_t S_RF2 = 43286528;

// ============================ HMMA GEMM (fp16, cp.async double-buffered) ============================
// part[s][m][pix] = sum_k W[(tap),m][k] * X[pix+shift][k]   (+ optional B-lo pass)
// CTA: 128(m) x 128(pix), 8 warps of 64x32. k-chunks of 64, 2-stage cp.async pipeline.
template <int USE_LO>
__global__ void __launch_bounds__(256, 2)
hgemm(const __half* __restrict__ Wh,
      const __half* __restrict__ Xhi, const __half* __restrict__ Xlo,
      float* __restrict__ part,
      int Ktot, int Kc, int Kx, int tapMode, int dil, int wshift, int HW, int skipEn)
{
    extern __shared__ __half sm[];
    const int STG = USE_LO ? 27648 : 18432;     // halfs per stage
    const uint32_t smB = (uint32_t)__cvta_generic_to_shared(sm);
    const uint32_t STGB = STG * 2;

    const int tid = threadIdx.x;
    const int wid = tid >> 5, lane = tid & 31;
    const int s = blockIdx.z;
    const int m0 = blockIdx.y * 128;
    const int n0 = blockIdx.x * 128;
    const int Mpad = gridDim.y * 128;
    const int Wimg = 1 << wshift;

    int dy = 0, dx = 0, k0s = 0;
    size_t wbase = 0;
    if (tapMode) {
        dy = (s / 3 - 1) * dil;
        dx = (s % 3 - 1) * dil;
        wbase = (size_t)s * Mpad * Ktot;
        if (skipEn) {
            int tileRows = 128 >> wshift;
            int r0 = n0 >> wshift;
            if (r0 + tileRows - 1 + dy < 0 || r0 + dy >= Wimg) return;  // masked in reduce
        }
    } else k0s = s * Kc;

    // per-thread load descriptors (fixed across chunks)
    const __half* gA[4];
    uint32_t sAo[4];
    const __half* gB[4];
    const __half* gBl[4];
    uint32_t sBo[4];
    int bsz[4];
#pragma unroll
    for (int i = 0; i < 4; i++) {
        int v = tid + 256 * i;
        int mr = v >> 3, ko = (v & 7) * 8;
        gA[i] = Wh + wbase + (size_t)(m0 + mr) * Ktot + k0s + ko;
        sAo[i] = (mr * 72 + ko) * 2;
        int nr = mr;
        int q = n0 + nr;
        int iy = (q >> wshift) + dy, ix = (q & (Wimg - 1)) + dx;
        bool ok = (unsigned)iy < (unsigned)Wimg && (unsigned)ix < (unsigned)Wimg;
        size_t gb = ok ? (size_t)((iy << wshift) + ix) * Kx + k0s + ko : 0;
        gB[i] = Xhi + gb;
        gBl[i] = USE_LO ? (Xlo + gb) : Xhi;
        bsz[i] = ok ? 16 : 0;
        sBo[i] = (nr * 72 + ko) * 2;
    }

    const int wm = (wid & 1) * 64;
    const int wn = (wid >> 1) * 32;
    const int r = lane >> 2;
    const int cp = (lane & 3) * 2;

    float acc[4][4][4];
#pragma unroll
    for (int i = 0; i < 4; i++)
#pragma unroll
        for (int j = 0; j < 4; j++)
#pragma unroll
            for (int q = 0; q < 4; q++) acc[i][j][q] = 0.f;

    const int nChunks = Kc / 64;

    // prologue: stage chunk 0 into buf 0
    {
        uint32_t sb = smB;
#pragma unroll
        for (int i = 0; i < 4; i++) { CP_ASYNC_CG(sb + sAo[i], gA[i], 16); gA[i] += 64; }
#pragma unroll
        for (int i = 0; i < 4; i++) {
            CP_ASYNC_CG(sb + 18432 + sBo[i], gB[i], bsz[i]);
            gB[i] += 64;
            if (USE_LO) { CP_ASYNC_CG(sb + 36864 + sBo[i], gBl[i], bsz[i]); gBl[i] += 64; }
        }
        CP_COMMIT();
    }

    for (int c = 0; c < nChunks; c++) {
        if (c + 1 < nChunks) {   // prefetch next chunk into alternate stage
            uint32_t sb = smB + ((c + 1) & 1) * STGB;
#pragma unroll
            for (int i = 0; i < 4; i++) { CP_ASYNC_CG(sb + sAo[i], gA[i], 16); gA[i] += 64; }
#pragma unroll
            for (int i = 0; i < 4; i++) {
                CP_ASYNC_CG(sb + 18432 + sBo[i], gB[i], bsz[i]);
                gB[i] += 64;
                if (USE_LO) { CP_ASYNC_CG(sb + 36864 + sBo[i], gBl[i], bsz[i]); gBl[i] += 64; }
            }
        }
        CP_COMMIT();
        CP_WAIT1();           // chunk c resident
        __syncthreads();

        const __half* sAh = sm + (c & 1) * STG;
        const __half* sBh = sAh + 9216;
        const __half* sBl = sAh + 18432;

#pragma unroll
        for (int kk = 0; kk < 64; kk += 16) {
            uint32_t af[4][4], bh[4][2];
#pragma unroll
            for (int im = 0; im < 4; im++) {
                const __half* p = sAh + (wm + im * 16 + r) * 72 + kk + cp;
                af[im][0] = ld32s(p);
                af[im][1] = ld32s(p + 8 * 72);
                af[im][2] = ld32s(p + 8);
                af[im][3] = ld32s(p + 8 * 72 + 8);
            }
#pragma unroll
            for (int in_ = 0; in_ < 4; in_++) {
                const __half* ph = sBh + (wn + in_ * 8 + r) * 72 + kk + cp;
                bh[in_][0] = ld32s(ph);
                bh[in_][1] = ld32s(ph + 8);
            }
#pragma unroll
            for (int im = 0; im < 4; im++)
#pragma unroll
                for (int in_ = 0; in_ < 4; in_++) mma_f16(acc[im][in_], af[im], bh[in_]);
            if (USE_LO) {
                uint32_t bl[4][2];
#pragma unroll
                for (int in_ = 0; in_ < 4; in_++) {
                    const __half* pl = sBl + (wn + in_ * 8 + r) * 72 + kk + cp;
                    bl[in_][0] = ld32s(pl);
                    bl[in_][1] = ld32s(pl + 8);
                }
#pragma unroll
                for (int im = 0; im < 4; im++)
#pragma unroll
                    for (int in_ = 0; in_ < 4; in_++) mma_f16(acc[im][in_], af[im], bl[in_]);
            }
        }
        __syncthreads();   // stage reusable for prefetch issued next iteration
    }

    float* po = part + (size_t)s * Mpad * HW;
    const int rbase = m0 + wm + r;
    const int cbase = n0 + wn + cp;
#pragma unroll
    for (int im = 0; im < 4; im++)
#pragma unroll
        for (int in_ = 0; in_ < 4; in_++) {
            int m = rbase + im * 16, n = cbase + in_ * 8;
            float2 v0 = make_float2(acc[im][in_][0], acc[im][in_][1]);
            float2 v1 = make_float2(acc[im][in_][2], acc[im][in_][3]);
            *(float2*)&po[(size_t)m * HW + n] = v0;
            *(float2*)&po[(size_t)(m + 8) * HW + n] = v1;
        }
}

// reduce slices + bn_relu, write TRANSPOSED fp16 hi/lo (tap-masked by row)
__global__ void reduce_ht(const float* __restrict__ part, int S, int Mpad, int HW,
                          const float* __restrict__ sc, const float* __restrict__ bi,
                          __half* __restrict__ ohi, __half* __restrict__ olo,
                          int ostride, int colOff, int tapDil, int wshift)
{
    __shared__ float t[32][33];
    int tx = threadIdx.x & 31, ty = threadIdx.x >> 5;
    int q0 = blockIdx.x * 32, m0 = blockIdx.y * 32;
    int y = q0 >> wshift;
    int Wimg = 1 << wshift;
#pragma unroll
    for (int r = 0; r < 4; r++) {
        int ml = ty + 8 * r;
        int m = m0 + ml;
        float a = 0.f;
        for (int s = 0; s < S; s++) {
            if (tapDil) {
                int dy = (s / 3 - 1) * tapDil;
                if ((unsigned)(y + dy) >= (unsigned)Wimg) continue;
            }
            a += part[(size_t)s * Mpad * HW + (size_t)m * HW + q0 + tx];
        }
        t[ml][tx] = fmaxf(sc[m] * a + bi[m], 0.f);
    }
    __syncthreads();
#pragma unroll
    for (int r = 0; r < 4; r++) {
        int ql = ty + 8 * r;
        float v = t[tx][ql];
        __half h = __float2half_rn(v);
        size_t o = (size_t)(q0 + ql) * ostride + colOff + m0 + tx;
        ohi[o] = h;
        olo[o] = __float2half_rn(v - __half2float(h));
    }
}

// reduce slices + epilogue to plain fp32
__global__ void reduce_pl(const float* __restrict__ part, float* __restrict__ out,
                          int S, int Mpad, int HW, int Mtot, int flags,
                          const float* __restrict__ sc, const float* __restrict__ bi,
                          const float* __restrict__ eb, int tapDil, int wshift)
{
    int idx = blockIdx.x * 256 + threadIdx.x;
    if (idx >= Mtot * HW) return;
    int m = idx / HW;
    int p = idx - m * HW;
    int y = p >> wshift;
    int Wimg = 1 << wshift;
    float a = 0.f;
    for (int s = 0; s < S; s++) {
        if (tapDil) {
            int dy = (s / 3 - 1) * tapDil;
            if ((unsigned)(y + dy) >= (unsigned)Wimg) continue;
        }
        a += part[(size_t)s * Mpad * HW + idx];
    }
    if (flags & 8) a += eb[m];
    if (flags & 2) a = sc[m] * a + bi[m];
    if (flags & 4) a = fmaxf(a, 0.f);
    out[idx] = a;
}

// ============================ conversion pre-passes ============================
__global__ void xtrans_g(const float* __restrict__ in,
                         __half* __restrict__ ohi, __half* __restrict__ olo,
                         int HW, int K) {
    __shared__ float t[32][33];
    int tx = threadIdx.x & 31, ty = threadIdx.x >> 5;
    int q0 = blockIdx.x * 32, k0 = blockIdx.y * 32;
#pragma unroll
    for (int r = 0; r < 4; r++)
        t[ty + 8 * r][tx] = in[(size_t)(k0 + ty + 8 * r) * HW + q0 + tx];
    __syncthreads();
#pragma unroll
    for (int r = 0; r < 4; r++) {
        int ql = ty + 8 * r;
        float v = t[tx][ql];
        __half h = __float2half_rn(v);
        size_t o = (size_t)(q0 + ql) * K + k0 + tx;
        ohi[o] = h;
        olo[o] = __float2half_rn(v - __half2float(h));
    }
}

__global__ void wconv1x1(const float* __restrict__ in, int rowStride, int K,
                         __half* __restrict__ whi, int total4) {
    int i = blockIdx.x * 256 + threadIdx.x;
    if (i >= total4) return;
    int e = i * 4, m = e / K, k = e - m * K;
    float4 v = *(const float4*)(in + (size_t)m * rowStride + k);
    size_t o = (size_t)m * K + k;
    *(__half2*)(whi + o) = __floats2half2_rn(v.x, v.y);
    *(__half2*)(whi + o + 2) = __floats2half2_rn(v.z, v.w);
}

__global__ void wconv3x3(const float* __restrict__ in, __half* __restrict__ whi) {
    __shared__ float st[4608];
    int m = blockIdx.x, kb = blockIdx.y;
    const float* src = in + (size_t)m * 36864 + (size_t)kb * 4608;
    for (int i = threadIdx.x; i < 1152; i += 256)
        *(float4*)(st + 4 * i) = *(const float4*)(src + 4 * i);
    __syncthreads();
    for (int j = threadIdx.x; j < 2304; j += 256) {
        int t = j / 256, k = (j & 255) * 2;
        size_t o = ((size_t)t * 512 + m) * 4096 + kb * 512 + k;
        *(__half2*)(whi + o) = __floats2half2_rn(st[k * 9 + t], st[(k + 1) * 9 + t]);
    }
}

__global__ void wcenter(const float* __restrict__ in, __half* __restrict__ whi) {
    int i = blockIdx.x * 256 + threadIdx.x;
    if (i >= 512 * 2048) return;
    int e = i * 2, m = e >> 12, k = e & 4095;
    const float* p = in + (size_t)m * 36864 + k * 9 + 4;
    *(__half2*)(whi + e) = __floats2half2_rn(p[0], p[9]);
}

__global__ void wrf_k(const float* __restrict__ in, __half* __restrict__ out, int M, int K) {
    int i = blockIdx.x * 256 + threadIdx.x;
    if (i >= M * K * 9) return;
    int m = i / (K * 9);
    int rem = i - m * K * 9;
    int k = rem / 9, t = rem - k * 9;
    out[((size_t)t * 128 + m) * K + k] = __float2half_rn(in[i]);
}

// ============================ FFMA2 path (r2, c6) ============================
DEV_INLINE void tap_rect(int ti, int d, int centerOnly, int H, int W,
                         int& dy, int& dx, int& y0, int& x0, int& rh, int& rw) {
    if (centerOnly || d == 0) { dy = dx = 0; y0 = x0 = 0; rh = H; rw = W; return; }
    dy = (ti / 3 - 1) * d;
    dx = (ti % 3 - 1) * d;
    y0 = dy < 0 ? -dy : 0;
    x0 = dx < 0 ? -dx : 0;
    rh = H - (dy < 0 ? -dy : dy);
    rw = W - (dx < 0 ? -dx : dx);
}

template <int MT>
__global__ void __launch_bounds__(256, 2)
gemm2(const float* __restrict__ W, int Arow, int wstride, int wofs0, int centerOnly,
      const float* __restrict__ X, float* __restrict__ part,
      int M, int Kc, int kch, int H, int Wd, int d)
{
    constexpr int NT = 64, KT = 16;
    constexpr int ROWS = MT / 16;
    __shared__ float sA[KT][MT + 4];
    __shared__ float sB[KT][NT + 4];

    const int tid = threadIdx.x;
    const int s = blockIdx.z;
    const int ti = s / kch;
    const int kc = s - ti * kch;
    int dy, dx, y0, x0, rh, rw;
    tap_rect(ti, d, centerOnly, H, Wd, dy, dx, y0, x0, rh, rw);
    const int rectN = rh * rw;
    const int HW = H * Wd;
    const int n0 = blockIdx.x * NT;
    if (n0 >= rectN) return;
    const int m0 = blockIdx.y * MT;
    const int wofs = centerOnly ? wofs0 : ti;
    const int kcS = kc * Kc;

    const int nB = tid & 63, kB = tid >> 6;
    bool bval = false;
    const float* pB[4];
    {
        int pofs = 0;
        int nn = n0 + nB;
        if (nn < rectN) {
            int yy = nn / rw, xx = nn - yy * rw;
            bval = true;
            pofs = (y0 + yy + dy) * Wd + (x0 + xx + dx);
        }
#pragma unroll
        for (int t = 0; t < 4; t++) pB[t] = X + (size_t)(kcS + kB + 4 * t) * HW + pofs;
    }
    const int kA = tid & 15, mA = tid >> 4;
    const float* pA[ROWS];
    bool aval[ROWS];
#pragma unroll
    for (int t = 0; t < ROWS; t++) {
        int mg = m0 + mA + 16 * t;
        aval[t] = (mg < M);
        pA[t] = W + (aval[t] ? ((size_t)mg * Arow + wofs + (size_t)(kcS + kA) * wstride) : 0);
    }

    unsigned long long acc[ROWS][2];
#pragma unroll
    for (int i = 0; i < ROWS; i++) { acc[i][0] = 0ull; acc[i][1] = 0ull; }

    float rA[ROWS], rB[4];
#pragma unroll
    for (int t = 0; t < ROWS; t++) { rA[t] = aval[t] ? __ldg(pA[t]) : 0.f; pA[t] += (size_t)KT * wstride; }
#pragma unroll
    for (int t = 0; t < 4; t++) { rB[t] = bval ? __ldg(pB[t]) : 0.f; pB[t] += (size_t)KT * HW; }

    const int tx = tid & 15, ty = tid >> 4;

    for (int k0 = 0; k0 < Kc; k0 += KT) {
#pragma unroll
        for (int t = 0; t < ROWS; t++) sA[kA][mA + 16 * t] = rA[t];
#pragma unroll
        for (int t = 0; t < 4; t++) sB[kB + 4 * t][nB] = rB[t];
        __syncthreads();
        if (k0 + KT < Kc) {
#pragma unroll
            for (int t = 0; t < ROWS; t++) { rA[t] = aval[t] ? __ldg(pA[t]) : 0.f; pA[t] += (size_t)KT * wstride; }
#pragma unroll
            for (int t = 0; t < 4; t++) { rB[t] = bval ? __ldg(pB[t]) : 0.f; pB[t] += (size_t)KT * HW; }
        }
#pragma unroll
        for (int kk = 0; kk < KT; kk++) {
            const unsigned long long* bp =
                reinterpret_cast<const unsigned long long*>(&sB[kk][tx * 4]);
            unsigned long long b0 = bp[0], b1 = bp[1];
            const float* ar = &sA[kk][ty * ROWS];
#pragma unroll
            for (int i = 0; i < ROWS; i++) {
                float a = ar[i];
                unsigned long long ap = pk2(a, a);
                FFMA2(acc[i][0], ap, b0);
                FFMA2(acc[i][1], ap, b1);
            }
        }
        __syncthreads();
    }

    float* po = part + (size_t)s * M * HW;
#pragma unroll
    for (int i = 0; i < ROWS; i++) {
        int m = m0 + ty * ROWS + i;
        if (m >= M) continue;
        float vals[4];
        unpk2(acc[i][0], vals[0], vals[1]);
        unpk2(acc[i][1], vals[2], vals[3]);
#pragma unroll
        for (int j = 0; j < 4; j++) {
            int n2 = n0 + tx * 4 + j;
            if (n2 >= rectN) continue;
            int yy = n2 / rw, xx = n2 - yy * rw;
            po[(size_t)m * HW + (y0 + yy) * Wd + (x0 + xx)] = vals[j];
        }
    }
}

__global__ void reduce_k(const float* __restrict__ part, float* __restrict__ out,
                         int M, int H, int W, int d, int centerOnly, int ntaps, int kch,
                         int flags, const float* __restrict__ sc,
                         const float* __restrict__ bi, const float* __restrict__ eb) {
    int HW = H * W;
    int idx = blockIdx.x * 256 + threadIdx.x;
    if (idx >= M * HW) return;
    int m = idx / HW;
    int p = idx - m * HW;
    int y = p / W, x = p - y * W;
    float acc = 0.f;
    for (int s = 0; s < ntaps * kch; s++) {
        int ti = s / kch;
        int dy, dx, y0, x0, rh, rw;
        tap_rect(ti, d, centerOnly, H, W, dy, dx, y0, x0, rh, rw);
        if (y >= y0 && y < y0 + rh && x >= x0 && x < x0 + rw)
            acc += part[(size_t)s * M * HW + idx];
    }
    if (flags & 8) acc += eb[m];
    if (flags & 2) acc = sc[m] * acc + bi[m];
    if (flags & 4) acc = fmaxf(acc, 0.f);
    out[idx] = acc;
}

// ============================ small kernels ============================
__global__ void resize_kk(const float* __restrict__ in, float* __restrict__ out,
                          int C, int Hi, int Wi, int Ho, int Wo, int dorelu) {
    int i = blockIdx.x * 256 + threadIdx.x;
    int total = C * Ho * Wo;
    if (i >= total) return;
    int ox = i % Wo;
    int t = i / Wo;
    int oy = t % Ho;
    int c = t / Ho;
    float ry = (Ho > 1) ? (float)(Hi - 1) / (float)(Ho - 1) : 0.f;
    float rx = (Wo > 1) ? (float)(Wi - 1) / (float)(Wo - 1) : 0.f;
    float tyf = oy * ry;
    int yl = (int)floorf(tyf);
    float fy = tyf - yl;
    int yh = min(yl + 1, Hi - 1);
    float txf = ox * rx;
    int xl = (int)floorf(txf);
    float fx = txf - xl;
    int xh = min(xl + 1, Wi - 1);
    const float* p = in + (size_t)c * Hi * Wi;
    float v00 = p[yl * Wi + xl], v01 = p[yl * Wi + xh];
    float v10 = p[yh * Wi + xl], v11 = p[yh * Wi + xh];
    float v = (v00 * (1.f - fy) + v10 * fy) * (1.f - fx) + (v01 * (1.f - fy) + v11 * fy) * fx;
    if (dorelu) v = fmaxf(v, 0.f);
    out[i] = v;
}

__global__ void energy_k(const float* __restrict__ c1r, const float* __restrict__ c2r,
                         float* __restrict__ att) {
    int p = blockIdx.x * 256 + threadIdx.x;
    if (p >= 4096) return;
    int y = p >> 6, x = p & 63;
    float e[9];
    int nidx[9];
    bool val[9];
#pragma unroll
    for (int a = 0; a < 3; a++)
#pragma unroll
        for (int b = 0; b < 3; b++) {
            int k = a * 3 + b;
            int iy = y + 2 * (a - 1), ix = x + 2 * (b - 1);
            val[k] = (unsigned)iy < 64u && (unsigned)ix < 64u;
            nidx[k] = val[k] ? (iy * 64 + ix) : 0;
            e[k] = 0.f;
        }
    for (int c = 0; c < 64; c++) {
        float v = c1r[c * 4096 + p];
        const float* row = c2r + c * 4096;
#pragma unroll
        for (int k = 0; k < 9; k++)
            if (val[k]) e[k] = fmaf(v, row[nidx[k]], e[k]);
    }
    float mx = e[0];
#pragma unroll
    for (int k = 1; k < 9; k++) mx = fmaxf(mx, e[k]);
    float sum = 0.f, ex[9];
#pragma unroll
    for (int k = 0; k < 9; k++) { ex[k] = expf(e[k] - mx); sum += ex[k]; }
    float inv = 1.f / sum;
#pragma unroll
    for (int k = 0; k < 9; k++) att[k * 4096 + p] = ex[k] * inv;
}

__global__ void gap_k(const float* __restrict__ x, float* __restrict__ gap) {
    int c = blockIdx.x * 8 + (threadIdx.x >> 5);
    int lane = threadIdx.x & 31;
    const float* p = x + (size_t)c * 1024;
    float s = 0.f;
    for (int i = lane; i < 1024; i += 32) s += p[i];
#pragma unroll
    for (int o = 16; o; o >>= 1) s += __shfl_xor_sync(0xffffffffu, s, o);
    if (!lane) gap[c] = s * (1.f / 1024.f);
}

__global__ void f4_k(const float* __restrict__ w, const float* __restrict__ s,
                     const float* __restrict__ b, const float* __restrict__ gap,
                     float* __restrict__ f4) {
    int o = blockIdx.x * 8 + (threadIdx.x >> 5);
    int lane = threadIdx.x & 31;
    const float* row = w + (size_t)o * 4096;
    float acc = 0.f;
    for (int i = lane; i < 4096; i += 32) acc = fmaf(row[i], gap[i], acc);
#pragma unroll
    for (int off = 16; off; off >>= 1) acc += __shfl_xor_sync(0xffffffffu, acc, off);
    if (!lane) f4[o] = fmaxf(s[o] * acc + b[o], 0.f);
}

__global__ void bias4_k(const float* __restrict__ apw, const float* __restrict__ f4,
                        float* __restrict__ b4) {
    int o = blockIdx.x * 8 + (threadIdx.x >> 5);
    int lane = threadIdx.x & 31;
    const float* row = apw + (size_t)o * 2560 + 2048;
    float acc = 0.f;
    for (int i = lane; i < 512; i += 32) acc = fmaf(row[i], f4[i], acc);
#pragma unroll
    for (int off = 16; off; off >>= 1) acc += __shfl_xor_sync(0xffffffffu, acc, off);
    if (!lane) b4[o] = acc;
}

__global__ void agg_k(const float* __restrict__ att, const float* __restrict__ zup,
                      const float* __restrict__ c6b, float* __restrict__ out) {
    int p = blockIdx.x * 256 + threadIdx.x;
    if (p >= 4096) return;
    int y = p >> 6, x = p & 63;
    float acc[19];
#pragma unroll
    for (int o = 0; o < 19; o++) acc[o] = c6b[o];
#pragma unroll
    for (int a = 0; a < 3; a++)
#pragma unroll
        for (int b = 0; b < 3; b++) {
            int k = a * 3 + b;
            int iy = y + 2 * (a - 1), ix = x + 2 * (b - 1);
            if ((unsigned)iy < 64u && (unsigned)ix < 64u) {
                float w = att[k * 4096 + p];
                int n = iy * 64 + ix;
#pragma unroll
                for (int o = 0; o < 19; o++) acc[o] = fmaf(w, zup[o * 4096 + n], acc[o]);
            }
        }
#pragma unroll
    for (int o = 0; o < 19; o++) out[o * 4096 + p] = acc[o];
}

// ============================ host driver ============================
static float* g_part_p;

static void run_conv(int mt, const float* Wt, int Arow, int wstride, int wofs0, int centerOnly,
                     const float* X, float* Cout,
                     int M, int K, int H, int Wd, int d, int kch,
                     const float* sc, const float* bi, const float* eb, int flags) {
    int ntaps = (d > 0 && !centerOnly) ? 9 : 1;
    int HW = H * Wd;
    int Kc = K / kch;
    dim3 grid((HW + 63) / 64, (M + mt - 1) / mt, ntaps * kch);
    if (mt == 128)
        gemm2<128><<<grid, 256>>>(Wt, Arow, wstride, wofs0, centerOnly, X, g_part_p,
                                  M, Kc, kch, H, Wd, d);
    else
        gemm2<64><<<grid, 256>>>(Wt, Arow, wstride, wofs0, centerOnly, X, g_part_p,
                                 M, Kc, kch, H, Wd, d);
    int tot = M * HW;
    reduce_k<<<(tot + 255) / 256, 256>>>(g_part_p, Cout, M, H, Wd, d, centerOnly,
                                         ntaps, kch, flags, sc, bi, eb);
}

extern "C" void kernel_launch(void* const* d_in, const int* in_sizes, int n_in,
                              void* d_out, int out_size) {
    const float* c1 = (const float*)d_in[0];
    const float* c2 = (const float*)d_in[1];
    const float* x = (const float*)d_in[2];
    const float* rf1_w = (const float*)d_in[3];
    const float* rf1_s = (const float*)d_in[4];
    const float* rf1_b = (const float*)d_in[5];
    const float* rf2_w = (const float*)d_in[6];
    const float* rf2_s = (const float*)d_in[7];
    const float* rf2_b = (const float*)d_in[8];
    const float* r2_w = (const float*)d_in[9];
    const float* r2_s = (const float*)d_in[10];
    const float* r2_b = (const float*)d_in[11];
    const float* a0_w = (const float*)d_in[12];
    const float* a0_s = (const float*)d_in[13];
    const float* a0_b = (const float*)d_in[14];
    const float* a1_w = (const float*)d_in[15];
    const float* a1_s = (const float*)d_in[16];
    const float* a1_b = (const float*)d_in[17];
    const float* a2_w = (const float*)d_in[18];
    const float* a2_s = (const float*)d_in[19];
    const float* a2_b = (const float*)d_in[20];
    const float* a3_w = (const float*)d_in[21];
    const float* a3_s = (const float*)d_in[22];
    const float* a3_b = (const float*)d_in[23];
    const float* a4_w = (const float*)d_in[24];
    const float* a4_s = (const float*)d_in[25];
    const float* a4_b = (const float*)d_in[26];
    const float* ap_w = (const float*)d_in[27];
    const float* ap_s = (const float*)d_in[28];
    const float* ap_b = (const float*)d_in[29];
    const float* c6_w = (const float*)d_in[30];
    const float* c6_b = (const float*)d_in[31];

    float *t2, *c1r, *c2r, *att, *gap, *f4, *b4, *outb, *z, *zup;
    __half *whi, *xthi, *xtlo, *fhi, *flo, *c1thi, *c1tlo, *t1thi, *t1tlo;
    cudaGetSymbolAddress((void**)&g_part_p, g_part);
    cudaGetSymbolAddress((void**)&t2, g_t2);
    cudaGetSymbolAddress((void**)&c1r, g_c1r);
    cudaGetSymbolAddress((void**)&c2r, g_c2r);
    cudaGetSymbolAddress((void**)&att, g_att);
    cudaGetSymbolAddress((void**)&gap, g_gap);
    cudaGetSymbolAddress((void**)&f4, g_f4);
    cudaGetSymbolAddress((void**)&b4, g_b4);
    cudaGetSymbolAddress((void**)&outb, g_outb);
    cudaGetSymbolAddress((void**)&z, g_z);
    cudaGetSymbolAddress((void**)&zup, g_zup);
    cudaGetSymbolAddress((void**)&whi, g_whi);
    cudaGetSymbolAddress((void**)&xthi, g_xthi);
    cudaGetSymbolAddress((void**)&xtlo, g_xtlo);
    cudaGetSymbolAddress((void**)&fhi, g_fhi);
    cudaGetSymbolAddress((void**)&flo, g_flo);
    cudaGetSymbolAddress((void**)&c1thi, g_c1thi);
    cudaGetSymbolAddress((void**)&c1tlo, g_c1tlo);
    cudaGetSymbolAddress((void**)&t1thi, g_t1thi);
    cudaGetSymbolAddress((void**)&t1tlo, g_t1tlo);

    const int SMEM_H1 = 2 * 18432 * 2;   // 73728 B (single-pass, 2 stages)
    const int SMEM_H2 = 2 * 27648 * 2;   // 110592 B (2-pass, 2 stages)
    cudaFuncSetAttribute(hgemm<0>, cudaFuncAttributeMaxDynamicSharedMemorySize, SMEM_H1);
    cudaFuncSetAttribute(hgemm<1>, cudaFuncAttributeMaxDynamicSharedMemorySize, SMEM_H2);

    // --- conversions; launch #4 = a1 hgemm (ncu captures the 4th launch) ---
    xtrans_g<<<dim3(32, 128), 256>>>(x, xthi, xtlo, 1024, 4096);                       // 1
    wconv3x3<<<dim3(512, 8), 256>>>(a1_w, whi + S_A1);                                 // 2
    wconv3x3<<<dim3(512, 8), 256>>>(a2_w, whi + S_A2);                                 // 3
    hgemm<0><<<dim3(8, 4, 9), 256, SMEM_H1>>>(whi + S_A1, xthi, nullptr, g_part_p,
                                              4096, 4096, 4096, 1, 12, 5, 1024, 1);    // 4 <- profiled
    reduce_ht<<<dim3(32, 16), 256>>>(g_part_p, 9, 512, 1024, a1_s, a1_b, fhi, flo, 2048, 512, 12, 5);
    hgemm<0><<<dim3(8, 4, 9), 256, SMEM_H1>>>(whi + S_A2, xthi, nullptr, g_part_p,
                                              4096, 4096, 4096, 1, 24, 5, 1024, 1);
    reduce_ht<<<dim3(32, 16), 256>>>(g_part_p, 9, 512, 1024, a2_s, a2_b, fhi, flo, 2048, 1024, 24, 5);
    wconv1x1<<<(512 * 4096 / 4 + 255) / 256, 256>>>(a0_w, 4096, 4096, whi + S_A0, 512 * 1024);
    hgemm<0><<<dim3(8, 4, 8), 256, SMEM_H1>>>(whi + S_A0, xthi, nullptr, g_part_p,
                                              4096, 512, 4096, 0, 0, 5, 1024, 0);
    reduce_ht<<<dim3(32, 16), 256>>>(g_part_p, 8, 512, 1024, a0_s, a0_b, fhi, flo, 2048, 0, 0, 5);
    wcenter<<<(512 * 2048 + 255) / 256, 256>>>(a3_w, whi + S_A3);
    hgemm<0><<<dim3(8, 4, 8), 256, SMEM_H1>>>(whi + S_A3, xthi, nullptr, g_part_p,
                                              4096, 512, 4096, 0, 0, 5, 1024, 0);
    reduce_ht<<<dim3(32, 16), 256>>>(g_part_p, 8, 512, 1024, a3_s, a3_b, fhi, flo, 2048, 1536, 0, 5);

    // --- attention branch: refine convs on HMMA (2-pass for accuracy) ---
    xtrans_g<<<dim3(128, 8), 256>>>(c1, c1thi, c1tlo, 4096, 256);
    wrf_k<<<(64 * 256 * 9 + 255) / 256, 256>>>(rf1_w, whi + S_RF1, 64, 256);
    wrf_k<<<(64 * 64 * 9 + 255) / 256, 256>>>(rf2_w, whi + S_RF2, 64, 64);
    hgemm<1><<<dim3(32, 1, 9), 256, SMEM_H2>>>(whi + S_RF1, c1thi, c1tlo, g_part_p,
                                               256, 256, 256, 1, 2, 6, 4096, 1);
    reduce_ht<<<dim3(128, 2), 256>>>(g_part_p, 9, 128, 4096, rf1_s, rf1_b, t1thi, t1tlo, 64, 0, 2, 6);
    hgemm<1><<<dim3(32, 1, 9), 256, SMEM_H2>>>(whi + S_RF2, t1thi, t1tlo, g_part_p,
                                               64, 64, 64, 1, 2, 6, 4096, 1);
    reduce_pl<<<(64 * 4096 + 255) / 256, 256>>>(g_part_p, c1r, 9, 128, 4096, 64, 6,
                                                rf2_s, rf2_b, nullptr, 2, 6);
    run_conv(64, r2_w, 512, 1, 0, 1, c2, t2, 64, 512, 32, 32, 0, 4, r2_s, r2_b, nullptr, 2);
    resize_kk<<<(64 * 4096 + 255) / 256, 256>>>(t2, c2r, 64, 32, 32, 64, 64, 1);
    energy_k<<<16, 256>>>(c1r, c2r, att);

    // --- GAP branch + ap (2-pass: exact fcat via hi/lo) ---
    gap_k<<<512, 256>>>(x, gap);
    f4_k<<<64, 256>>>(a4_w, a4_s, a4_b, gap, f4);
    bias4_k<<<64, 256>>>(ap_w, f4, b4);
    wconv1x1<<<(512 * 2048 / 4 + 255) / 256, 256>>>(ap_w, 2560, 2048, whi + S_AP, 512 * 512);
    hgemm<1><<<dim3(8, 4, 8), 256, SMEM_H2>>>(whi + S_AP, fhi, flo, g_part_p,
                                              2048, 256, 2048, 0, 0, 5, 1024, 0);
    reduce_pl<<<2048, 256>>>(g_part_p, outb, 8, 512, 1024, 512, 2 | 4 | 8,
                             ap_s, ap_b, b4, 0, 5);

    // --- final head ---
    run_conv(64, c6_w, 512, 1, 0, 1, outb, z, 19, 512, 32, 32, 0, 4, nullptr, nullptr, nullptr, 0);
    resize_kk<<<(19 * 4096 + 255) / 256, 256>>>(z, zup, 19, 32, 32, 64, 64, 0);
    agg_k<<<16, 256>>>(att, zup, c6_b, (float*)d_out);
}

// round 12
// speedup vs baseline: 1.6324x; 1.0408x over previous
#include <cuda_runtime.h>
#include <cuda_fp16.h>
#include <math.h>
#include <stdint.h>

#define DEV_INLINE __device__ __forceinline__

DEV_INLINE unsigned long long pk2(float lo, float hi) {
    unsigned long long r;
    asm("mov.b64 %0, {%1, %2};" : "=l"(r) : "f"(lo), "f"(hi));
    return r;
}
DEV_INLINE void unpk2(unsigned long long v, float& lo, float& hi) {
    asm("mov.b64 {%0, %1}, %2;" : "=f"(lo), "=f"(hi) : "l"(v));
}
#define FFMA2(d, a, b) asm("fma.rn.f32x2 %0, %1, %2, %0;" : "+l"(d) : "l"(a), "l"(b))

DEV_INLINE void mma_f16(float* c, const uint32_t* a, const uint32_t* b) {
    asm volatile(
        "mma.sync.aligned.m16n8k16.row.col.f32.f16.f16.f32 "
        "{%0,%1,%2,%3}, {%4,%5,%6,%7}, {%8,%9}, {%0,%1,%2,%3};"
        : "+f"(c[0]), "+f"(c[1]), "+f"(c[2]), "+f"(c[3])
        : "r"(a[0]), "r"(a[1]), "r"(a[2]), "r"(a[3]), "r"(b[0]), "r"(b[1]));
}
DEV_INLINE void ldsm_x4(uint32_t& r0, uint32_t& r1, uint32_t& r2, uint32_t& r3, uint32_t a) {
    asm volatile("ldmatrix.sync.aligned.m8n8.x4.shared.b16 {%0,%1,%2,%3}, [%4];"
                 : "=r"(r0), "=r"(r1), "=r"(r2), "=r"(r3) : "r"(a));
}

#define CP_ASYNC_CG(dst, src, sz) \
    asm volatile("cp.async.cg.shared.global [%0], [%1], 16, %2;" \
                 :: "r"(dst), "l"(src), "r"(sz) : "memory")
#define CP_COMMIT() asm volatile("cp.async.commit_group;" ::: "memory")
#define CP_WAIT1() asm volatile("cp.async.wait_group 1;" ::: "memory")

// ============================ scratch ============================
__device__ float g_part[5 * 1024 * 1024];
__device__ float g_t2[64 * 1024];
__device__ float g_c1r[64 * 4096];
__device__ float g_c2r[64 * 4096];
__device__ float g_att[9 * 4096];
__device__ float g_gap[4096];
__device__ float g_f4[512];
__device__ float g_b4[512];
__device__ float g_outb[512 * 1024];
__device__ float g_z[19 * 1024];
__device__ float g_zup[19 * 4096];
__device__ __align__(16) __half g_whi[43360256];
__device__ __align__(16) __half g_xthi[1024 * 4096];
__device__ __align__(16) __half g_xtlo[1024 * 4096];
__device__ __align__(16) __half g_fhi[1024 * 2048];
__device__ __align__(16) __half g_flo[1024 * 2048];
__device__ __align__(16) __half g_c1thi[4096 * 256];
__device__ __align__(16) __half g_c1tlo[4096 * 256];
__device__ __align__(16) __half g_t1thi[4096 * 64];
__device__ __align__(16) __half g_t1tlo[4096 * 64];

static const size_t S_A0 = 0;
static const size_t S_A1 = 2097152;
static const size_t S_A2 = 20971520;
static const size_t S_A3 = 39845888;
static const size_t S_AP = 41943040;
static const size_t S_RF1 = 42991616;
static const size_t S_RF2 = 43286528;

// ============================ HMMA GEMM (fp16, cp.async + ldmatrix) ============================
// part[s][m][pix] = sum_k W[(tap),m][k] * X[pix+shift][k]   (+ optional B-lo pass)
// CTA: 128(m) x 128(pix), 8 warps of 64x32. k-chunks of 64, 2-stage cp.async pipeline.
template <int USE_LO>
__global__ void __launch_bounds__(256, 2)
hgemm(const __half* __restrict__ Wh,
      const __half* __restrict__ Xhi, const __half* __restrict__ Xlo,
      float* __restrict__ part,
      int Ktot, int Kc, int Kx, int tapMode, int dil, int wshift, int HW, int skipEn)
{
    extern __shared__ __half sm[];
    const int STG = USE_LO ? 27648 : 18432;     // halfs per stage
    const uint32_t smB = (uint32_t)__cvta_generic_to_shared(sm);
    const uint32_t STGB = STG * 2;

    const int tid = threadIdx.x;
    const int wid = tid >> 5, lane = tid & 31;
    const int s = blockIdx.z;
    const int m0 = blockIdx.y * 128;
    const int n0 = blockIdx.x * 128;
    const int Mpad = gridDim.y * 128;
    const int Wimg = 1 << wshift;

    int dy = 0, dx = 0, k0s = 0;
    size_t wbase = 0;
    if (tapMode) {
        dy = (s / 3 - 1) * dil;
        dx = (s % 3 - 1) * dil;
        wbase = (size_t)s * Mpad * Ktot;
        if (skipEn) {
            int tileRows = 128 >> wshift;
            int r0 = n0 >> wshift;
            if (r0 + tileRows - 1 + dy < 0 || r0 + dy >= Wimg) return;  // masked in reduce
        }
    } else k0s = s * Kc;

    // per-thread load descriptors (fixed across chunks)
    const __half* gA[4];
    uint32_t sAo[4];
    const __half* gB[4];
    const __half* gBl[4];
    uint32_t sBo[4];
    int bsz[4];
#pragma unroll
    for (int i = 0; i < 4; i++) {
        int v = tid + 256 * i;
        int mr = v >> 3, ko = (v & 7) * 8;
        gA[i] = Wh + wbase + (size_t)(m0 + mr) * Ktot + k0s + ko;
        sAo[i] = (mr * 72 + ko) * 2;
        int nr = mr;
        int q = n0 + nr;
        int iy = (q >> wshift) + dy, ix = (q & (Wimg - 1)) + dx;
        bool ok = (unsigned)iy < (unsigned)Wimg && (unsigned)ix < (unsigned)Wimg;
        size_t gb = ok ? (size_t)((iy << wshift) + ix) * Kx + k0s + ko : 0;
        gB[i] = Xhi + gb;
        gBl[i] = USE_LO ? (Xlo + gb) : Xhi;
        bsz[i] = ok ? 16 : 0;
        sBo[i] = (nr * 72 + ko) * 2;
    }

    const int wm = (wid & 1) * 64;
    const int wn = (wid >> 1) * 32;

    // ldmatrix address offsets (bytes, within stage)
    uint32_t aOff[4], bOff[2];
#pragma unroll
    for (int im = 0; im < 4; im++)
        aOff[im] = ((wm + im * 16 + (lane & 15)) * 72 + (lane >> 4) * 8) * 2;
#pragma unroll
    for (int pi = 0; pi < 2; pi++)
        bOff[pi] = ((wn + pi * 16 + ((lane >> 4) & 1) * 8 + (lane & 7)) * 72 +
                    ((lane >> 3) & 1) * 8) * 2 + 18432;

    float acc[4][4][4];
#pragma unroll
    for (int i = 0; i < 4; i++)
#pragma unroll
        for (int j = 0; j < 4; j++)
#pragma unroll
            for (int q = 0; q < 4; q++) acc[i][j][q] = 0.f;

    const int nChunks = Kc / 64;

    // prologue: stage chunk 0 into buf 0
    {
        uint32_t sb = smB;
#pragma unroll
        for (int i = 0; i < 4; i++) { CP_ASYNC_CG(sb + sAo[i], gA[i], 16); gA[i] += 64; }
#pragma unroll
        for (int i = 0; i < 4; i++) {
            CP_ASYNC_CG(sb + 18432 + sBo[i], gB[i], bsz[i]);
            gB[i] += 64;
            if (USE_LO) { CP_ASYNC_CG(sb + 36864 + sBo[i], gBl[i], bsz[i]); gBl[i] += 64; }
        }
        CP_COMMIT();
    }

    for (int c = 0; c < nChunks; c++) {
        if (c + 1 < nChunks) {   // prefetch next chunk into alternate stage
            uint32_t sb = smB + ((c + 1) & 1) * STGB;
#pragma unroll
            for (int i = 0; i < 4; i++) { CP_ASYNC_CG(sb + sAo[i], gA[i], 16); gA[i] += 64; }
#pragma unroll
            for (int i = 0; i < 4; i++) {
                CP_ASYNC_CG(sb + 18432 + sBo[i], gB[i], bsz[i]);
                gB[i] += 64;
                if (USE_LO) { CP_ASYNC_CG(sb + 36864 + sBo[i], gBl[i], bsz[i]); gBl[i] += 64; }
            }
        }
        CP_COMMIT();
        CP_WAIT1();           // chunk c resident
        __syncthreads();

        const uint32_t sbase = smB + (c & 1) * STGB;

#pragma unroll
        for (int kk = 0; kk < 64; kk += 16) {
            uint32_t af[4][4], bh[4][2];
#pragma unroll
            for (int im = 0; im < 4; im++)
                ldsm_x4(af[im][0], af[im][1], af[im][2], af[im][3],
                        sbase + aOff[im] + kk * 2);
#pragma unroll
            for (int pi = 0; pi < 2; pi++)
                ldsm_x4(bh[2 * pi][0], bh[2 * pi][1], bh[2 * pi + 1][0], bh[2 * pi + 1][1],
                        sbase + bOff[pi] + kk * 2);
#pragma unroll
            for (int im = 0; im < 4; im++)
#pragma unroll
                for (int in_ = 0; in_ < 4; in_++) mma_f16(acc[im][in_], af[im], bh[in_]);
            if (USE_LO) {
                uint32_t bl[4][2];
#pragma unroll
                for (int pi = 0; pi < 2; pi++)
                    ldsm_x4(bl[2 * pi][0], bl[2 * pi][1], bl[2 * pi + 1][0], bl[2 * pi + 1][1],
                            sbase + bOff[pi] + 18432 + kk * 2);
#pragma unroll
                for (int im = 0; im < 4; im++)
#pragma unroll
                    for (int in_ = 0; in_ < 4; in_++) mma_f16(acc[im][in_], af[im], bl[in_]);
            }
        }
        __syncthreads();   // stage reusable for prefetch issued next iteration
    }

    float* po = part + (size_t)s * Mpad * HW;
    const int r = lane >> 2;
    const int cp = (lane & 3) * 2;
    const int rbase = m0 + wm + r;
    const int cbase = n0 + wn + cp;
#pragma unroll
    for (int im = 0; im < 4; im++)
#pragma unroll
        for (int in_ = 0; in_ < 4; in_++) {
            int m = rbase + im * 16, n = cbase + in_ * 8;
            float2 v0 = make_float2(acc[im][in_][0], acc[im][in_][1]);
            float2 v1 = make_float2(acc[im][in_][2], acc[im][in_][3]);
            *(float2*)&po[(size_t)m * HW + n] = v0;
            *(float2*)&po[(size_t)(m + 8) * HW + n] = v1;
        }
}

// reduce slices + bn_relu, write TRANSPOSED fp16 hi/lo (tap-masked by row)
__global__ void reduce_ht(const float* __restrict__ part, int S, int Mpad, int HW,
                          const float* __restrict__ sc, const float* __restrict__ bi,
                          __half* __restrict__ ohi, __half* __restrict__ olo,
                          int ostride, int colOff, int tapDil, int wshift)
{
    __shared__ float t[32][33];
    int tx = threadIdx.x & 31, ty = threadIdx.x >> 5;
    int q0 = blockIdx.x * 32, m0 = blockIdx.y * 32;
    int y = q0 >> wshift;
    int Wimg = 1 << wshift;
#pragma unroll
    for (int r = 0; r < 4; r++) {
        int ml = ty + 8 * r;
        int m = m0 + ml;
        float a = 0.f;
        for (int s = 0; s < S; s++) {
            if (tapDil) {
                int dy = (s / 3 - 1) * tapDil;
                if ((unsigned)(y + dy) >= (unsigned)Wimg) continue;
            }
            a += part[(size_t)s * Mpad * HW + (size_t)m * HW + q0 + tx];
        }
        t[ml][tx] = fmaxf(sc[m] * a + bi[m], 0.f);
    }
    __syncthreads();
#pragma unroll
    for (int r = 0; r < 4; r++) {
        int ql = ty + 8 * r;
        float v = t[tx][ql];
        __half h = __float2half_rn(v);
        size_t o = (size_t)(q0 + ql) * ostride + colOff + m0 + tx;
        ohi[o] = h;
        olo[o] = __float2half_rn(v - __half2float(h));
    }
}

// reduce slices + epilogue to plain fp32
__global__ void reduce_pl(const float* __restrict__ part, float* __restrict__ out,
                          int S, int Mpad, int HW, int Mtot, int flags,
                          const float* __restrict__ sc, const float* __restrict__ bi,
                          const float* __restrict__ eb, int tapDil, int wshift)
{
    int idx = blockIdx.x * 256 + threadIdx.x;
    if (idx >= Mtot * HW) return;
    int m = idx / HW;
    int p = idx - m * HW;
    int y = p >> wshift;
    int Wimg = 1 << wshift;
    float a = 0.f;
    for (int s = 0; s < S; s++) {
        if (tapDil) {
            int dy = (s / 3 - 1) * tapDil;
            if ((unsigned)(y + dy) >= (unsigned)Wimg) continue;
        }
        a += part[(size_t)s * Mpad * HW + idx];
    }
    if (flags & 8) a += eb[m];
    if (flags & 2) a = sc[m] * a + bi[m];
    if (flags & 4) a = fmaxf(a, 0.f);
    out[idx] = a;
}

// ============================ conversion pre-passes ============================
__global__ void xtrans_g(const float* __restrict__ in,
                         __half* __restrict__ ohi, __half* __restrict__ olo,
                         int HW, int K) {
    __shared__ float t[32][33];
    int tx = threadIdx.x & 31, ty = threadIdx.x >> 5;
    int q0 = blockIdx.x * 32, k0 = blockIdx.y * 32;
#pragma unroll
    for (int r = 0; r < 4; r++)
        t[ty + 8 * r][tx] = in[(size_t)(k0 + ty + 8 * r) * HW + q0 + tx];
    __syncthreads();
#pragma unroll
    for (int r = 0; r < 4; r++) {
        int ql = ty + 8 * r;
        float v = t[tx][ql];
        __half h = __float2half_rn(v);
        size_t o = (size_t)(q0 + ql) * K + k0 + tx;
        ohi[o] = h;
        olo[o] = __float2half_rn(v - __half2float(h));
    }
}

__global__ void wconv1x1(const float* __restrict__ in, int rowStride, int K,
                         __half* __restrict__ whi, int total4) {
    int i = blockIdx.x * 256 + threadIdx.x;
    if (i >= total4) return;
    int e = i * 4, m = e / K, k = e - m * K;
    float4 v = *(const float4*)(in + (size_t)m * rowStride + k);
    size_t o = (size_t)m * K + k;
    *(__half2*)(whi + o) = __floats2half2_rn(v.x, v.y);
    *(__half2*)(whi + o + 2) = __floats2half2_rn(v.z, v.w);
}

__global__ void wconv3x3(const float* __restrict__ in, __half* __restrict__ whi) {
    __shared__ float st[4608];
    int m = blockIdx.x, kb = blockIdx.y;
    const float* src = in + (size_t)m * 36864 + (size_t)kb * 4608;
    for (int i = threadIdx.x; i < 1152; i += 256)
        *(float4*)(st + 4 * i) = *(const float4*)(src + 4 * i);
    __syncthreads();
    for (int j = threadIdx.x; j < 2304; j += 256) {
        int t = j / 256, k = (j & 255) * 2;
        size_t o = ((size_t)t * 512 + m) * 4096 + kb * 512 + k;
        *(__half2*)(whi + o) = __floats2half2_rn(st[k * 9 + t], st[(k + 1) * 9 + t]);
    }
}

__global__ void wcenter(const float* __restrict__ in, __half* __restrict__ whi) {
    int i = blockIdx.x * 256 + threadIdx.x;
    if (i >= 512 * 2048) return;
    int e = i * 2, m = e >> 12, k = e & 4095;
    const float* p = in + (size_t)m * 36864 + k * 9 + 4;
    *(__half2*)(whi + e) = __floats2half2_rn(p[0], p[9]);
}

__global__ void wrf_k(const float* __restrict__ in, __half* __restrict__ out, int M, int K) {
    int i = blockIdx.x * 256 + threadIdx.x;
    if (i >= M * K * 9) return;
    int m = i / (K * 9);
    int rem = i - m * K * 9;
    int k = rem / 9, t = rem - k * 9;
    out[((size_t)t * 128 + m) * K + k] = __float2half_rn(in[i]);
}

// ============================ FFMA2 path (r2, c6) ============================
DEV_INLINE void tap_rect(int ti, int d, int centerOnly, int H, int W,
                         int& dy, int& dx, int& y0, int& x0, int& rh, int& rw) {
    if (centerOnly || d == 0) { dy = dx = 0; y0 = x0 = 0; rh = H; rw = W; return; }
    dy = (ti / 3 - 1) * d;
    dx = (ti % 3 - 1) * d;
    y0 = dy < 0 ? -dy : 0;
    x0 = dx < 0 ? -dx : 0;
    rh = H - (dy < 0 ? -dy : dy);
    rw = W - (dx < 0 ? -dx : dx);
}

template <int MT>
__global__ void __launch_bounds__(256, 2)
gemm2(const float* __restrict__ W, int Arow, int wstride, int wofs0, int centerOnly,
      const float* __restrict__ X, float* __restrict__ part,
      int M, int Kc, int kch, int H, int Wd, int d)
{
    constexpr int NT = 64, KT = 16;
    constexpr int ROWS = MT / 16;
    __shared__ float sA[KT][MT + 4];
    __shared__ float sB[KT][NT + 4];

    const int tid = threadIdx.x;
    const int s = blockIdx.z;
    const int ti = s / kch;
    const int kc = s - ti * kch;
    int dy, dx, y0, x0, rh, rw;
    tap_rect(ti, d, centerOnly, H, Wd, dy, dx, y0, x0, rh, rw);
    const int rectN = rh * rw;
    const int HW = H * Wd;
    const int n0 = blockIdx.x * NT;
    if (n0 >= rectN) return;
    const int m0 = blockIdx.y * MT;
    const int wofs = centerOnly ? wofs0 : ti;
    const int kcS = kc * Kc;

    const int nB = tid & 63, kB = tid >> 6;
    bool bval = false;
    const float* pB[4];
    {
        int pofs = 0;
        int nn = n0 + nB;
        if (nn < rectN) {
            int yy = nn / rw, xx = nn - yy * rw;
            bval = true;
            pofs = (y0 + yy + dy) * Wd + (x0 + xx + dx);
        }
#pragma unroll
        for (int t = 0; t < 4; t++) pB[t] = X + (size_t)(kcS + kB + 4 * t) * HW + pofs;
    }
    const int kA = tid & 15, mA = tid >> 4;
    const float* pA[ROWS];
    bool aval[ROWS];
#pragma unroll
    for (int t = 0; t < ROWS; t++) {
        int mg = m0 + mA + 16 * t;
        aval[t] = (mg < M);
        pA[t] = W + (aval[t] ? ((size_t)mg * Arow + wofs + (size_t)(kcS + kA) * wstride) : 0);
    }

    unsigned long long acc[ROWS][2];
#pragma unroll
    for (int i = 0; i < ROWS; i++) { acc[i][0] = 0ull; acc[i][1] = 0ull; }

    float rA[ROWS], rB[4];
#pragma unroll
    for (int t = 0; t < ROWS; t++) { rA[t] = aval[t] ? __ldg(pA[t]) : 0.f; pA[t] += (size_t)KT * wstride; }
#pragma unroll
    for (int t = 0; t < 4; t++) { rB[t] = bval ? __ldg(pB[t]) : 0.f; pB[t] += (size_t)KT * HW; }

    const int tx = tid & 15, ty = tid >> 4;

    for (int k0 = 0; k0 < Kc; k0 += KT) {
#pragma unroll
        for (int t = 0; t < ROWS; t++) sA[kA][mA + 16 * t] = rA[t];
#pragma unroll
        for (int t = 0; t < 4; t++) sB[kB + 4 * t][nB] = rB[t];
        __syncthreads();
        if (k0 + KT < Kc) {
#pragma unroll
            for (int t = 0; t < ROWS; t++) { rA[t] = aval[t] ? __ldg(pA[t]) : 0.f; pA[t] += (size_t)KT * wstride; }
#pragma unroll
            for (int t = 0; t < 4; t++) { rB[t] = bval ? __ldg(pB[t]) : 0.f; pB[t] += (size_t)KT * HW; }
        }
#pragma unroll
        for (int kk = 0; kk < KT; kk++) {
            const unsigned long long* bp =
                reinterpret_cast<const unsigned long long*>(&sB[kk][tx * 4]);
            unsigned long long b0 = bp[0], b1 = bp[1];
            const float* ar = &sA[kk][ty * ROWS];
#pragma unroll
            for (int i = 0; i < ROWS; i++) {
                float a = ar[i];
                unsigned long long ap = pk2(a, a);
                FFMA2(acc[i][0], ap, b0);
                FFMA2(acc[i][1], ap, b1);
            }
        }
        __syncthreads();
    }

    float* po = part + (size_t)s * M * HW;
#pragma unroll
    for (int i = 0; i < ROWS; i++) {
        int m = m0 + ty * ROWS + i;
        if (m >= M) continue;
        float vals[4];
        unpk2(acc[i][0], vals[0], vals[1]);
        unpk2(acc[i][1], vals[2], vals[3]);
#pragma unroll
        for (int j = 0; j < 4; j++) {
            int n2 = n0 + tx * 4 + j;
            if (n2 >= rectN) continue;
            int yy = n2 / rw, xx = n2 - yy * rw;
            po[(size_t)m * HW + (y0 + yy) * Wd + (x0 + xx)] = vals[j];
        }
    }
}

__global__ void reduce_k(const float* __restrict__ part, float* __restrict__ out,
                         int M, int H, int W, int d, int centerOnly, int ntaps, int kch,
                         int flags, const float* __restrict__ sc,
                         const float* __restrict__ bi, const float* __restrict__ eb) {
    int HW = H * W;
    int idx = blockIdx.x * 256 + threadIdx.x;
    if (idx >= M * HW) return;
    int m = idx / HW;
    int p = idx - m * HW;
    int y = p / W, x = p - y * W;
    float acc = 0.f;
    for (int s = 0; s < ntaps * kch; s++) {
        int ti = s / kch;
        int dy, dx, y0, x0, rh, rw;
        tap_rect(ti, d, centerOnly, H, W, dy, dx, y0, x0, rh, rw);
        if (y >= y0 && y < y0 + rh && x >= x0 && x < x0 + rw)
            acc += part[(size_t)s * M * HW + idx];
    }
    if (flags & 8) acc += eb[m];
    if (flags & 2) acc = sc[m] * acc + bi[m];
    if (flags & 4) acc = fmaxf(acc, 0.f);
    out[idx] = acc;
}

// ============================ small kernels ============================
__global__ void resize_kk(const float* __restrict__ in, float* __restrict__ out,
                          int C, int Hi, int Wi, int Ho, int Wo, int dorelu) {
    int i = blockIdx.x * 256 + threadIdx.x;
    int total = C * Ho * Wo;
    if (i >= total) return;
    int ox = i % Wo;
    int t = i / Wo;
    int oy = t % Ho;
    int c = t / Ho;
    float ry = (Ho > 1) ? (float)(Hi - 1) / (float)(Ho - 1) : 0.f;
    float rx = (Wo > 1) ? (float)(Wi - 1) / (float)(Wo - 1) : 0.f;
    float tyf = oy * ry;
    int yl = (int)floorf(tyf);
    float fy = tyf - yl;
    int yh = min(yl + 1, Hi - 1);
    float txf = ox * rx;
    int xl = (int)floorf(txf);
    float fx = txf - xl;
    int xh = min(xl + 1, Wi - 1);
    const float* p = in + (size_t)c * Hi * Wi;
    float v00 = p[yl * Wi + xl], v01 = p[yl * Wi + xh];
    float v10 = p[yh * Wi + xl], v11 = p[yh * Wi + xh];
    float v = (v00 * (1.f - fy) + v10 * fy) * (1.f - fx) + (v01 * (1.f - fy) + v11 * fy) * fx;
    if (dorelu) v = fmaxf(v, 0.f);
    out[i] = v;
}

__global__ void energy_k(const float* __restrict__ c1r, const float* __restrict__ c2r,
                         float* __restrict__ att) {
    int p = blockIdx.x * 256 + threadIdx.x;
    if (p >= 4096) return;
    int y = p >> 6, x = p & 63;
    float e[9];
    int nidx[9];
    bool val[9];
#pragma unroll
    for (int a = 0; a < 3; a++)
#pragma unroll
        for (int b = 0; b < 3; b++) {
            int k = a * 3 + b;
            int iy = y + 2 * (a - 1), ix = x + 2 * (b - 1);
            val[k] = (unsigned)iy < 64u && (unsigned)ix < 64u;
            nidx[k] = val[k] ? (iy * 64 + ix) : 0;
            e[k] = 0.f;
        }
    for (int c = 0; c < 64; c++) {
        float v = c1r[c * 4096 + p];
        const float* row = c2r + c * 4096;
#pragma unroll
        for (int k = 0; k < 9; k++)
            if (val[k]) e[k] = fmaf(v, row[nidx[k]], e[k]);
    }
    float mx = e[0];
#pragma unroll
    for (int k = 1; k < 9; k++) mx = fmaxf(mx, e[k]);
    float sum = 0.f, ex[9];
#pragma unroll
    for (int k = 0; k < 9; k++) { ex[k] = expf(e[k] - mx); sum += ex[k]; }
    float inv = 1.f / sum;
#pragma unroll
    for (int k = 0; k < 9; k++) att[k * 4096 + p] = ex[k] * inv;
}

__global__ void gap_k(const float* __restrict__ x, float* __restrict__ gap) {
    int c = blockIdx.x * 8 + (threadIdx.x >> 5);
    int lane = threadIdx.x & 31;
    const float* p = x + (size_t)c * 1024;
    float s = 0.f;
    for (int i = lane; i < 1024; i += 32) s += p[i];
#pragma unroll
    for (int o = 16; o; o >>= 1) s += __shfl_xor_sync(0xffffffffu, s, o);
    if (!lane) gap[c] = s * (1.f / 1024.f);
}

__global__ void f4_k(const float* __restrict__ w, const float* __restrict__ s,
                     const float* __restrict__ b, const float* __restrict__ gap,
                     float* __restrict__ f4) {
    int o = blockIdx.x * 8 + (threadIdx.x >> 5);
    int lane = threadIdx.x & 31;
    const float* row = w + (size_t)o * 4096;
    float acc = 0.f;
    for (int i = lane; i < 4096; i += 32) acc = fmaf(row[i], gap[i], acc);
#pragma unroll
    for (int off = 16; off; off >>= 1) acc += __shfl_xor_sync(0xffffffffu, acc, off);
    if (!lane) f4[o] = fmaxf(s[o] * acc + b[o], 0.f);
}

__global__ void bias4_k(const float* __restrict__ apw, const float* __restrict__ f4,
                        float* __restrict__ b4) {
    int o = blockIdx.x * 8 + (threadIdx.x >> 5);
    int lane = threadIdx.x & 31;
    const float* row = apw + (size_t)o * 2560 + 2048;
    float acc = 0.f;
    for (int i = lane; i < 512; i += 32) acc = fmaf(row[i], f4[i], acc);
#pragma unroll
    for (int off = 16; off; off >>= 1) acc += __shfl_xor_sync(0xffffffffu, acc, off);
    if (!lane) b4[o] = acc;
}

__global__ void agg_k(const float* __restrict__ att, const float* __restrict__ zup,
                      const float* __restrict__ c6b, float* __restrict__ out) {
    int p = blockIdx.x * 256 + threadIdx.x;
    if (p >= 4096) return;
    int y = p >> 6, x = p & 63;
    float acc[19];
#pragma unroll
    for (int o = 0; o < 19; o++) acc[o] = c6b[o];
#pragma unroll
    for (int a = 0; a < 3; a++)
#pragma unroll
        for (int b = 0; b < 3; b++) {
            int k = a * 3 + b;
            int iy = y + 2 * (a - 1), ix = x + 2 * (b - 1);
            if ((unsigned)iy < 64u && (unsigned)ix < 64u) {
                float w = att[k * 4096 + p];
                int n = iy * 64 + ix;
#pragma unroll
                for (int o = 0; o < 19; o++) acc[o] = fmaf(w, zup[o * 4096 + n], acc[o]);
            }
        }
#pragma unroll
    for (int o = 0; o < 19; o++) out[o * 4096 + p] = acc[o];
}

// ============================ host driver ============================
static float* g_part_p;

static void run_conv(int mt, const float* Wt, int Arow, int wstride, int wofs0, int centerOnly,
                     const float* X, float* Cout,
                     int M, int K, int H, int Wd, int d, int kch,
                     const float* sc, const float* bi, const float* eb, int flags) {
    int ntaps = (d > 0 && !centerOnly) ? 9 : 1;
    int HW = H * Wd;
    int Kc = K / kch;
    dim3 grid((HW + 63) / 64, (M + mt - 1) / mt, ntaps * kch);
    if (mt == 128)
        gemm2<128><<<grid, 256>>>(Wt, Arow, wstride, wofs0, centerOnly, X, g_part_p,
                                  M, Kc, kch, H, Wd, d);
    else
        gemm2<64><<<grid, 256>>>(Wt, Arow, wstride, wofs0, centerOnly, X, g_part_p,
                                 M, Kc, kch, H, Wd, d);
    int tot = M * HW;
    reduce_k<<<(tot + 255) / 256, 256>>>(g_part_p, Cout, M, H, Wd, d, centerOnly,
                                         ntaps, kch, flags, sc, bi, eb);
}

extern "C" void kernel_launch(void* const* d_in, const int* in_sizes, int n_in,
                              void* d_out, int out_size) {
    const float* c1 = (const float*)d_in[0];
    const float* c2 = (const float*)d_in[1];
    const float* x = (const float*)d_in[2];
    const float* rf1_w = (const float*)d_in[3];
    const float* rf1_s = (const float*)d_in[4];
    const float* rf1_b = (const float*)d_in[5];
    const float* rf2_w = (const float*)d_in[6];
    const float* rf2_s = (const float*)d_in[7];
    const float* rf2_b = (const float*)d_in[8];
    const float* r2_w = (const float*)d_in[9];
    const float* r2_s = (const float*)d_in[10];
    const float* r2_b = (const float*)d_in[11];
    const float* a0_w = (const float*)d_in[12];
    const float* a0_s = (const float*)d_in[13];
    const float* a0_b = (const float*)d_in[14];
    const float* a1_w = (const float*)d_in[15];
    const float* a1_s = (const float*)d_in[16];
    const float* a1_b = (const float*)d_in[17];
    const float* a2_w = (const float*)d_in[18];
    const float* a2_s = (const float*)d_in[19];
    const float* a2_b = (const float*)d_in[20];
    const float* a3_w = (const float*)d_in[21];
    const float* a3_s = (const float*)d_in[22];
    const float* a3_b = (const float*)d_in[23];
    const float* a4_w = (const float*)d_in[24];
    const float* a4_s = (const float*)d_in[25];
    const float* a4_b = (const float*)d_in[26];
    const float* ap_w = (const float*)d_in[27];
    const float* ap_s = (const float*)d_in[28];
    const float* ap_b = (const float*)d_in[29];
    const float* c6_w = (const float*)d_in[30];
    const float* c6_b = (const float*)d_in[31];

    float *t2, *c1r, *c2r, *att, *gap, *f4, *b4, *outb, *z, *zup;
    __half *whi, *xthi, *xtlo, *fhi, *flo, *c1thi, *c1tlo, *t1thi, *t1tlo;
    cudaGetSymbolAddress((void**)&g_part_p, g_part);
    cudaGetSymbolAddress((void**)&t2, g_t2);
    cudaGetSymbolAddress((void**)&c1r, g_c1r);
    cudaGetSymbolAddress((void**)&c2r, g_c2r);
    cudaGetSymbolAddress((void**)&att, g_att);
    cudaGetSymbolAddress((void**)&gap, g_gap);
    cudaGetSymbolAddress((void**)&f4, g_f4);
    cudaGetSymbolAddress((void**)&b4, g_b4);
    cudaGetSymbolAddress((void**)&outb, g_outb);
    cudaGetSymbolAddress((void**)&z, g_z);
    cudaGetSymbolAddress((void**)&zup, g_zup);
    cudaGetSymbolAddress((void**)&whi, g_whi);
    cudaGetSymbolAddress((void**)&xthi, g_xthi);
    cudaGetSymbolAddress((void**)&xtlo, g_xtlo);
    cudaGetSymbolAddress((void**)&fhi, g_fhi);
    cudaGetSymbolAddress((void**)&flo, g_flo);
    cudaGetSymbolAddress((void**)&c1thi, g_c1thi);
    cudaGetSymbolAddress((void**)&c1tlo, g_c1tlo);
    cudaGetSymbolAddress((void**)&t1thi, g_t1thi);
    cudaGetSymbolAddress((void**)&t1tlo, g_t1tlo);

    const int SMEM_H1 = 2 * 18432 * 2;   // 73728 B (single-pass, 2 stages)
    const int SMEM_H2 = 2 * 27648 * 2;   // 110592 B (2-pass, 2 stages)
    cudaFuncSetAttribute(hgemm<0>, cudaFuncAttributeMaxDynamicSharedMemorySize, SMEM_H1);
    cudaFuncSetAttribute(hgemm<1>, cudaFuncAttributeMaxDynamicSharedMemorySize, SMEM_H2);

    // --- conversions; launch #4 = a1 hgemm (ncu captures the 4th launch) ---
    xtrans_g<<<dim3(32, 128), 256>>>(x, xthi, xtlo, 1024, 4096);                       // 1
    wconv3x3<<<dim3(512, 8), 256>>>(a1_w, whi + S_A1);                                 // 2
    wconv3x3<<<dim3(512, 8), 256>>>(a2_w, whi + S_A2);                                 // 3
    hgemm<0><<<dim3(8, 4, 9), 256, SMEM_H1>>>(whi + S_A1, xthi, nullptr, g_part_p,
                                              4096, 4096, 4096, 1, 12, 5, 1024, 1);    // 4 <- profiled
    reduce_ht<<<dim3(32, 16), 256>>>(g_part_p, 9, 512, 1024, a1_s, a1_b, fhi, flo, 2048, 512, 12, 5);
    hgemm<0><<<dim3(8, 4, 9), 256, SMEM_H1>>>(whi + S_A2, xthi, nullptr, g_part_p,
                                              4096, 4096, 4096, 1, 24, 5, 1024, 1);
    reduce_ht<<<dim3(32, 16), 256>>>(g_part_p, 9, 512, 1024, a2_s, a2_b, fhi, flo, 2048, 1024, 24, 5);
    wconv1x1<<<(512 * 4096 / 4 + 255) / 256, 256>>>(a0_w, 4096, 4096, whi + S_A0, 512 * 1024);
    hgemm<0><<<dim3(8, 4, 8), 256, SMEM_H1>>>(whi + S_A0, xthi, nullptr, g_part_p,
                                              4096, 512, 4096, 0, 0, 5, 1024, 0);
    reduce_ht<<<dim3(32, 16), 256>>>(g_part_p, 8, 512, 1024, a0_s, a0_b, fhi, flo, 2048, 0, 0, 5);
    wcenter<<<(512 * 2048 + 255) / 256, 256>>>(a3_w, whi + S_A3);
    hgemm<0><<<dim3(8, 4, 8), 256, SMEM_H1>>>(whi + S_A3, xthi, nullptr, g_part_p,
                                              4096, 512, 4096, 0, 0, 5, 1024, 0);
    reduce_ht<<<dim3(32, 16), 256>>>(g_part_p, 8, 512, 1024, a3_s, a3_b, fhi, flo, 2048, 1536, 0, 5);

    // --- attention branch: refine convs on HMMA (2-pass for accuracy) ---
    xtrans_g<<<dim3(128, 8), 256>>>(c1, c1thi, c1tlo, 4096, 256);
    wrf_k<<<(64 * 256 * 9 + 255) / 256, 256>>>(rf1_w, whi + S_RF1, 64, 256);
    wrf_k<<<(64 * 64 * 9 + 255) / 256, 256>>>(rf2_w, whi + S_RF2, 64, 64);
    hgemm<1><<<dim3(32, 1, 9), 256, SMEM_H2>>>(whi + S_RF1, c1thi, c1tlo, g_part_p,
                                               256, 256, 256, 1, 2, 6, 4096, 1);
    reduce_ht<<<dim3(128, 2), 256>>>(g_part_p, 9, 128, 4096, rf1_s, rf1_b, t1thi, t1tlo, 64, 0, 2, 6);
    hgemm<1><<<dim3(32, 1, 9), 256, SMEM_H2>>>(whi + S_RF2, t1thi, t1tlo, g_part_p,
                                               64, 64, 64, 1, 2, 6, 4096, 1);
    reduce_pl<<<(64 * 4096 + 255) / 256, 256>>>(g_part_p, c1r, 9, 128, 4096, 64, 6,
                                                rf2_s, rf2_b, nullptr, 2, 6);
    run_conv(64, r2_w, 512, 1, 0, 1, c2, t2, 64, 512, 32, 32, 0, 4, r2_s, r2_b, nullptr, 2);
    resize_kk<<<(64 * 4096 + 255) / 256, 256>>>(t2, c2r, 64, 32, 32, 64, 64, 1);
    energy_k<<<16, 256>>>(c1r, c2r, att);

    // --- GAP branch + ap (2-pass: exact fcat via hi/lo) ---
    gap_k<<<512, 256>>>(x, gap);
    f4_k<<<64, 256>>>(a4_w, a4_s, a4_b, gap, f4);
    bias4_k<<<64, 256>>>(ap_w, f4, b4);
    wconv1x1<<<(512 * 2048 / 4 + 255) / 256, 256>>>(ap_w, 2560, 2048, whi + S_AP, 512 * 512);
    hgemm<1><<<dim3(8, 4, 8), 256, SMEM_H2>>>(whi + S_AP, fhi, flo, g_part_p,
                                              2048, 256, 2048, 0, 0, 5, 1024, 0);
    reduce_pl<<<2048, 256>>>(g_part_p, outb, 8, 512, 1024, 512, 2 | 4 | 8,
                             ap_s, ap_b, b4, 0, 5);

    // --- final head ---
    run_conv(64, c6_w, 512, 1, 0, 1, outb, z, 19, 512, 32, 32, 0, 4, nullptr, nullptr, nullptr, 0);
    resize_kk<<<(19 * 4096 + 255) / 256, 256>>>(z, zup, 19, 32, 32, 64, 64, 0);
    agg_k<<<16, 256>>>(att, zup, c6_b, (float*)d_out);
}

// round 13
// speedup vs baseline: 1.6454x; 1.0079x over previous
#include <cuda_runtime.h>
#include <cuda_fp16.h>
#include <math.h>
#include <stdint.h>

#define DEV_INLINE __device__ __forceinline__

DEV_INLINE unsigned long long pk2(float lo, float hi) {
    unsigned long long r;
    asm("mov.b64 %0, {%1, %2};" : "=l"(r) : "f"(lo), "f"(hi));
    return r;
}
DEV_INLINE void unpk2(unsigned long long v, float& lo, float& hi) {
    asm("mov.b64 {%0, %1}, %2;" : "=f"(lo), "=f"(hi) : "l"(v));
}
#define FFMA2(d, a, b) asm("fma.rn.f32x2 %0, %1, %2, %0;" : "+l"(d) : "l"(a), "l"(b))

DEV_INLINE void mma_f16(float* c, const uint32_t* a, const uint32_t* b) {
    asm volatile(
        "mma.sync.aligned.m16n8k16.row.col.f32.f16.f16.f32 "
        "{%0,%1,%2,%3}, {%4,%5,%6,%7}, {%8,%9}, {%0,%1,%2,%3};"
        : "+f"(c[0]), "+f"(c[1]), "+f"(c[2]), "+f"(c[3])
        : "r"(a[0]), "r"(a[1]), "r"(a[2]), "r"(a[3]), "r"(b[0]), "r"(b[1]));
}
DEV_INLINE void ldsm_x4(uint32_t& r0, uint32_t& r1, uint32_t& r2, uint32_t& r3, uint32_t a) {
    asm volatile("ldmatrix.sync.aligned.m8n8.x4.shared.b16 {%0,%1,%2,%3}, [%4];"
                 : "=r"(r0), "=r"(r1), "=r"(r2), "=r"(r3) : "r"(a));
}

#define CP_ASYNC_CG(dst, src, sz) \
    asm volatile("cp.async.cg.shared.global [%0], [%1], 16, %2;" \
                 :: "r"(dst), "l"(src), "r"(sz) : "memory")
#define CP_COMMIT() asm volatile("cp.async.commit_group;" ::: "memory")
#define CP_WAIT_N1() asm volatile("cp.async.wait_group 1;" ::: "memory")
#define CP_WAIT_N2() asm volatile("cp.async.wait_group 2;" ::: "memory")

// ============================ scratch ============================
__device__ float g_part[5 * 1024 * 1024];
__device__ float g_t2[64 * 1024];
__device__ float g_c1r[64 * 4096];
__device__ float g_c2r[64 * 4096];
__device__ float g_att[9 * 4096];
__device__ float g_gap[4096];
__device__ float g_f4[512];
__device__ float g_b4[512];
__device__ float g_outb[512 * 1024];
__device__ float g_z[19 * 1024];
__device__ float g_zup[19 * 4096];
__device__ __align__(16) __half g_whi[43360256];
__device__ __align__(16) __half g_xthi[1024 * 4096];
__device__ __align__(16) __half g_xtlo[1024 * 4096];
__device__ __align__(16) __half g_fhi[1024 * 2048];
__device__ __align__(16) __half g_flo[1024 * 2048];
__device__ __align__(16) __half g_c1thi[4096 * 256];
__device__ __align__(16) __half g_c1tlo[4096 * 256];
__device__ __align__(16) __half g_t1thi[4096 * 64];
__device__ __align__(16) __half g_t1tlo[4096 * 64];

static const size_t S_A0 = 0;
static const size_t S_A1 = 2097152;
static const size_t S_A2 = 20971520;
static const size_t S_A3 = 39845888;
static const size_t S_AP = 41943040;
static const size_t S_RF1 = 42991616;
static const size_t S_RF2 = 43286528;

// ============================ HMMA GEMM (fp16, multi-stage cp.async + ldmatrix) ============================
// part[s][m][pix] = sum_k W[(tap),m][k] * X[pix+shift][k]   (+ optional B-lo pass)
// CTA: 128(m) x 128(pix), 8 warps of 64x32. k-chunks of 64.
// Pipeline: 3 stages (single-pass) / 2 stages (2-pass; smem limit).
template <int USE_LO>
__global__ void __launch_bounds__(256, 2)
hgemm(const __half* __restrict__ Wh,
      const __half* __restrict__ Xhi, const __half* __restrict__ Xlo,
      float* __restrict__ part,
      int Ktot, int Kc, int Kx, int tapMode, int dil, int wshift, int HW, int skipEn)
{
    extern __shared__ __half sm[];
    constexpr int NSTAGE = USE_LO ? 2 : 3;
    const int STG = USE_LO ? 27648 : 18432;     // halfs per stage
    const uint32_t smB = (uint32_t)__cvta_generic_to_shared(sm);
    const uint32_t STGB = STG * 2;

    const int tid = threadIdx.x;
    const int wid = tid >> 5, lane = tid & 31;
    const int s = blockIdx.z;
    const int m0 = blockIdx.y * 128;
    const int n0 = blockIdx.x * 128;
    const int Mpad = gridDim.y * 128;
    const int Wimg = 1 << wshift;

    int dy = 0, dx = 0, k0s = 0;
    size_t wbase = 0;
    if (tapMode) {
        dy = (s / 3 - 1) * dil;
        dx = (s % 3 - 1) * dil;
        wbase = (size_t)s * Mpad * Ktot;
        if (skipEn) {
            int tileRows = 128 >> wshift;
            int r0 = n0 >> wshift;
            if (r0 + tileRows - 1 + dy < 0 || r0 + dy >= Wimg) return;  // masked in reduce
        }
    } else k0s = s * Kc;

    // per-thread load descriptors (fixed across chunks)
    const __half* gA[4];
    uint32_t sAo[4];
    const __half* gB[4];
    const __half* gBl[4];
    uint32_t sBo[4];
    int bsz[4];
#pragma unroll
    for (int i = 0; i < 4; i++) {
        int v = tid + 256 * i;
        int mr = v >> 3, ko = (v & 7) * 8;
        gA[i] = Wh + wbase + (size_t)(m0 + mr) * Ktot + k0s + ko;
        sAo[i] = (mr * 72 + ko) * 2;
        int nr = mr;
        int q = n0 + nr;
        int iy = (q >> wshift) + dy, ix = (q & (Wimg - 1)) + dx;
        bool ok = (unsigned)iy < (unsigned)Wimg && (unsigned)ix < (unsigned)Wimg;
        size_t gb = ok ? (size_t)((iy << wshift) + ix) * Kx + k0s + ko : 0;
        gB[i] = Xhi + gb;
        gBl[i] = USE_LO ? (Xlo + gb) : Xhi;
        bsz[i] = ok ? 16 : 0;
        sBo[i] = (nr * 72 + ko) * 2;
    }

    const int wm = (wid & 1) * 64;
    const int wn = (wid >> 1) * 32;

    // ldmatrix address offsets (bytes, within stage)
    uint32_t aOff[4], bOff[2];
#pragma unroll
    for (int im = 0; im < 4; im++)
        aOff[im] = ((wm + im * 16 + (lane & 15)) * 72 + (lane >> 4) * 8) * 2;
#pragma unroll
    for (int pi = 0; pi < 2; pi++)
        bOff[pi] = ((wn + pi * 16 + ((lane >> 4) & 1) * 8 + (lane & 7)) * 72 +
                    ((lane >> 3) & 1) * 8) * 2 + 18432;

    float acc[4][4][4];
#pragma unroll
    for (int i = 0; i < 4; i++)
#pragma unroll
        for (int j = 0; j < 4; j++)
#pragma unroll
            for (int q = 0; q < 4; q++) acc[i][j][q] = 0.f;

    const int nChunks = Kc / 64;

#define LOADCHUNK(sb)                                                            \
    do {                                                                         \
        _Pragma("unroll")                                                        \
        for (int i = 0; i < 4; i++) { CP_ASYNC_CG((sb) + sAo[i], gA[i], 16); gA[i] += 64; } \
        _Pragma("unroll")                                                        \
        for (int i = 0; i < 4; i++) {                                            \
            CP_ASYNC_CG((sb) + 18432 + sBo[i], gB[i], bsz[i]);                   \
            gB[i] += 64;                                                         \
            if (USE_LO) { CP_ASYNC_CG((sb) + 36864 + sBo[i], gBl[i], bsz[i]); gBl[i] += 64; } \
        }                                                                        \
    } while (0)

    // prologue: stage chunks 0..NSTAGE-2
    {
        int npro = (NSTAGE - 1 < nChunks) ? NSTAGE - 1 : nChunks;
        for (int p = 0; p < npro; p++) {
            LOADCHUNK(smB + p * STGB);
            CP_COMMIT();
        }
        for (int p = npro; p < NSTAGE - 1; p++) CP_COMMIT();
    }

    for (int c = 0; c < nChunks; c++) {
        int pf = c + NSTAGE - 1;
        if (pf < nChunks) LOADCHUNK(smB + (pf % NSTAGE) * STGB);
        CP_COMMIT();
        if (USE_LO) CP_WAIT_N1(); else CP_WAIT_N2();   // chunk c resident
        __syncthreads();

        const uint32_t sbase = smB + (c % NSTAGE) * STGB;

#pragma unroll
        for (int kk = 0; kk < 64; kk += 16) {
            uint32_t af[4][4], bh[4][2];
#pragma unroll
            for (int im = 0; im < 4; im++)
                ldsm_x4(af[im][0], af[im][1], af[im][2], af[im][3],
                        sbase + aOff[im] + kk * 2);
#pragma unroll
            for (int pi = 0; pi < 2; pi++)
                ldsm_x4(bh[2 * pi][0], bh[2 * pi][1], bh[2 * pi + 1][0], bh[2 * pi + 1][1],
                        sbase + bOff[pi] + kk * 2);
#pragma unroll
            for (int im = 0; im < 4; im++)
#pragma unroll
                for (int in_ = 0; in_ < 4; in_++) mma_f16(acc[im][in_], af[im], bh[in_]);
            if (USE_LO) {
                uint32_t bl[4][2];
#pragma unroll
                for (int pi = 0; pi < 2; pi++)
                    ldsm_x4(bl[2 * pi][0], bl[2 * pi][1], bl[2 * pi + 1][0], bl[2 * pi + 1][1],
                            sbase + bOff[pi] + 18432 + kk * 2);
#pragma unroll
                for (int im = 0; im < 4; im++)
#pragma unroll
                    for (int in_ = 0; in_ < 4; in_++) mma_f16(acc[im][in_], af[im], bl[in_]);
            }
        }
        __syncthreads();   // stage reusable for the prefetch issued next iteration
    }
#undef LOADCHUNK

    float* po = part + (size_t)s * Mpad * HW;
    const int r = lane >> 2;
    const int cp = (lane & 3) * 2;
    const int rbase = m0 + wm + r;
    const int cbase = n0 + wn + cp;
#pragma unroll
    for (int im = 0; im < 4; im++)
#pragma unroll
        for (int in_ = 0; in_ < 4; in_++) {
            int m = rbase + im * 16, n = cbase + in_ * 8;
            float2 v0 = make_float2(acc[im][in_][0], acc[im][in_][1]);
            float2 v1 = make_float2(acc[im][in_][2], acc[im][in_][3]);
            *(float2*)&po[(size_t)m * HW + n] = v0;
            *(float2*)&po[(size_t)(m + 8) * HW + n] = v1;
        }
}

// reduce slices + bn_relu, write TRANSPOSED fp16 hi/lo (tap-masked by row)
__global__ void reduce_ht(const float* __restrict__ part, int S, int Mpad, int HW,
                          const float* __restrict__ sc, const float* __restrict__ bi,
                          __half* __restrict__ ohi, __half* __restrict__ olo,
                          int ostride, int colOff, int tapDil, int wshift)
{
    __shared__ float t[32][33];
    int tx = threadIdx.x & 31, ty = threadIdx.x >> 5;
    int q0 = blockIdx.x * 32, m0 = blockIdx.y * 32;
    int y = q0 >> wshift;
    int Wimg = 1 << wshift;
#pragma unroll
    for (int r = 0; r < 4; r++) {
        int ml = ty + 8 * r;
        int m = m0 + ml;
        float a = 0.f;
        for (int s = 0; s < S; s++) {
            if (tapDil) {
                int dy = (s / 3 - 1) * tapDil;
                if ((unsigned)(y + dy) >= (unsigned)Wimg) continue;
            }
            a += part[(size_t)s * Mpad * HW + (size_t)m * HW + q0 + tx];
        }
        t[ml][tx] = fmaxf(sc[m] * a + bi[m], 0.f);
    }
    __syncthreads();
#pragma unroll
    for (int r = 0; r < 4; r++) {
        int ql = ty + 8 * r;
        float v = t[tx][ql];
        __half h = __float2half_rn(v);
        size_t o = (size_t)(q0 + ql) * ostride + colOff + m0 + tx;
        ohi[o] = h;
        olo[o] = __float2half_rn(v - __half2float(h));
    }
}

// reduce slices + epilogue to plain fp32
__global__ void reduce_pl(const float* __restrict__ part, float* __restrict__ out,
                          int S, int Mpad, int HW, int Mtot, int flags,
                          const float* __restrict__ sc, const float* __restrict__ bi,
                          const float* __restrict__ eb, int tapDil, int wshift)
{
    int idx = blockIdx.x * 256 + threadIdx.x;
    if (idx >= Mtot * HW) return;
    int m = idx / HW;
    int p = idx - m * HW;
    int y = p >> wshift;
    int Wimg = 1 << wshift;
    float a = 0.f;
    for (int s = 0; s < S; s++) {
        if (tapDil) {
            int dy = (s / 3 - 1) * tapDil;
            if ((unsigned)(y + dy) >= (unsigned)Wimg) continue;
        }
        a += part[(size_t)s * Mpad * HW + idx];
    }
    if (flags & 8) a += eb[m];
    if (flags & 2) a = sc[m] * a + bi[m];
    if (flags & 4) a = fmaxf(a, 0.f);
    out[idx] = a;
}

// ============================ conversion pre-passes ============================
__global__ void xtrans_g(const float* __restrict__ in,
                         __half* __restrict__ ohi, __half* __restrict__ olo,
                         int HW, int K) {
    __shared__ float t[32][33];
    int tx = threadIdx.x & 31, ty = threadIdx.x >> 5;
    int q0 = blockIdx.x * 32, k0 = blockIdx.y * 32;
#pragma unroll
    for (int r = 0; r < 4; r++)
        t[ty + 8 * r][tx] = in[(size_t)(k0 + ty + 8 * r) * HW + q0 + tx];
    __syncthreads();
#pragma unroll
    for (int r = 0; r < 4; r++) {
        int ql = ty + 8 * r;
        float v = t[tx][ql];
        __half h = __float2half_rn(v);
        size_t o = (size_t)(q0 + ql) * K + k0 + tx;
        ohi[o] = h;
        olo[o] = __float2half_rn(v - __half2float(h));
    }
}

__global__ void wconv1x1(const float* __restrict__ in, int rowStride, int K,
                         __half* __restrict__ whi, int total4) {
    int i = blockIdx.x * 256 + threadIdx.x;
    if (i >= total4) return;
    int e = i * 4, m = e / K, k = e - m * K;
    float4 v = *(const float4*)(in + (size_t)m * rowStride + k);
    size_t o = (size_t)m * K + k;
    *(__half2*)(whi + o) = __floats2half2_rn(v.x, v.y);
    *(__half2*)(whi + o + 2) = __floats2half2_rn(v.z, v.w);
}

__global__ void wconv3x3(const float* __restrict__ in, __half* __restrict__ whi) {
    __shared__ float st[4608];
    int m = blockIdx.x, kb = blockIdx.y;
    const float* src = in + (size_t)m * 36864 + (size_t)kb * 4608;
    for (int i = threadIdx.x; i < 1152; i += 256)
        *(float4*)(st + 4 * i) = *(const float4*)(src + 4 * i);
    __syncthreads();
    for (int j = threadIdx.x; j < 2304; j += 256) {
        int t = j / 256, k = (j & 255) * 2;
        size_t o = ((size_t)t * 512 + m) * 4096 + kb * 512 + k;
        *(__half2*)(whi + o) = __floats2half2_rn(st[k * 9 + t], st[(k + 1) * 9 + t]);
    }
}

__global__ void wcenter(const float* __restrict__ in, __half* __restrict__ whi) {
    int i = blockIdx.x * 256 + threadIdx.x;
    if (i >= 512 * 2048) return;
    int e = i * 2, m = e >> 12, k = e & 4095;
    const float* p = in + (size_t)m * 36864 + k * 9 + 4;
    *(__half2*)(whi + e) = __floats2half2_rn(p[0], p[9]);
}

__global__ void wrf_k(const float* __restrict__ in, __half* __restrict__ out, int M, int K) {
    int i = blockIdx.x * 256 + threadIdx.x;
    if (i >= M * K * 9) return;
    int m = i / (K * 9);
    int rem = i - m * K * 9;
    int k = rem / 9, t = rem - k * 9;
    out[((size_t)t * 128 + m) * K + k] = __float2half_rn(in[i]);
}

// ============================ FFMA2 path (r2, c6) ============================
DEV_INLINE void tap_rect(int ti, int d, int centerOnly, int H, int W,
                         int& dy, int& dx, int& y0, int& x0, int& rh, int& rw) {
    if (centerOnly || d == 0) { dy = dx = 0; y0 = x0 = 0; rh = H; rw = W; return; }
    dy = (ti / 3 - 1) * d;
    dx = (ti % 3 - 1) * d;
    y0 = dy < 0 ? -dy : 0;
    x0 = dx < 0 ? -dx : 0;
    rh = H - (dy < 0 ? -dy : dy);
    rw = W - (dx < 0 ? -dx : dx);
}

template <int MT>
__global__ void __launch_bounds__(256, 2)
gemm2(const float* __restrict__ W, int Arow, int wstride, int wofs0, int centerOnly,
      const float* __restrict__ X, float* __restrict__ part,
      int M, int Kc, int kch, int H, int Wd, int d)
{
    constexpr int NT = 64, KT = 16;
    constexpr int ROWS = MT / 16;
    __shared__ float sA[KT][MT + 4];
    __shared__ float sB[KT][NT + 4];

    const int tid = threadIdx.x;
    const int s = blockIdx.z;
    const int ti = s / kch;
    const int kc = s - ti * kch;
    int dy, dx, y0, x0, rh, rw;
    tap_rect(ti, d, centerOnly, H, Wd, dy, dx, y0, x0, rh, rw);
    const int rectN = rh * rw;
    const int HW = H * Wd;
    const int n0 = blockIdx.x * NT;
    if (n0 >= rectN) return;
    const int m0 = blockIdx.y * MT;
    const int wofs = centerOnly ? wofs0 : ti;
    const int kcS = kc * Kc;

    const int nB = tid & 63, kB = tid >> 6;
    bool bval = false;
    const float* pB[4];
    {
        int pofs = 0;
        int nn = n0 + nB;
        if (nn < rectN) {
            int yy = nn / rw, xx = nn - yy * rw;
            bval = true;
            pofs = (y0 + yy + dy) * Wd + (x0 + xx + dx);
        }
#pragma unroll
        for (int t = 0; t < 4; t++) pB[t] = X + (size_t)(kcS + kB + 4 * t) * HW + pofs;
    }
    const int kA = tid & 15, mA = tid >> 4;
    const float* pA[ROWS];
    bool aval[ROWS];
#pragma unroll
    for (int t = 0; t < ROWS; t++) {
        int mg = m0 + mA + 16 * t;
        aval[t] = (mg < M);
        pA[t] = W + (aval[t] ? ((size_t)mg * Arow + wofs + (size_t)(kcS + kA) * wstride) : 0);
    }

    unsigned long long acc[ROWS][2];
#pragma unroll
    for (int i = 0; i < ROWS; i++) { acc[i][0] = 0ull; acc[i][1] = 0ull; }

    float rA[ROWS], rB[4];
#pragma unroll
    for (int t = 0; t < ROWS; t++) { rA[t] = aval[t] ? __ldg(pA[t]) : 0.f; pA[t] += (size_t)KT * wstride; }
#pragma unroll
    for (int t = 0; t < 4; t++) { rB[t] = bval ? __ldg(pB[t]) : 0.f; pB[t] += (size_t)KT * HW; }

    const int tx = tid & 15, ty = tid >> 4;

    for (int k0 = 0; k0 < Kc; k0 += KT) {
#pragma unroll
        for (int t = 0; t < ROWS; t++) sA[kA][mA + 16 * t] = rA[t];
#pragma unroll
        for (int t = 0; t < 4; t++) sB[kB + 4 * t][nB] = rB[t];
        __syncthreads();
        if (k0 + KT < Kc) {
#pragma unroll
            for (int t = 0; t < ROWS; t++) { rA[t] = aval[t] ? __ldg(pA[t]) : 0.f; pA[t] += (size_t)KT * wstride; }
#pragma unroll
            for (int t = 0; t < 4; t++) { rB[t] = bval ? __ldg(pB[t]) : 0.f; pB[t] += (size_t)KT * HW; }
        }
#pragma unroll
        for (int kk = 0; kk < KT; kk++) {
            const unsigned long long* bp =
                reinterpret_cast<const unsigned long long*>(&sB[kk][tx * 4]);
            unsigned long long b0 = bp[0], b1 = bp[1];
            const float* ar = &sA[kk][ty * ROWS];
#pragma unroll
            for (int i = 0; i < ROWS; i++) {
                float a = ar[i];
                unsigned long long ap = pk2(a, a);
                FFMA2(acc[i][0], ap, b0);
                FFMA2(acc[i][1], ap, b1);
            }
        }
        __syncthreads();
    }

    float* po = part + (size_t)s * M * HW;
#pragma unroll
    for (int i = 0; i < ROWS; i++) {
        int m = m0 + ty * ROWS + i;
        if (m >= M) continue;
        float vals[4];
        unpk2(acc[i][0], vals[0], vals[1]);
        unpk2(acc[i][1], vals[2], vals[3]);
#pragma unroll
        for (int j = 0; j < 4; j++) {
            int n2 = n0 + tx * 4 + j;
            if (n2 >= rectN) continue;
            int yy = n2 / rw, xx = n2 - yy * rw;
            po[(size_t)m * HW + (y0 + yy) * Wd + (x0 + xx)] = vals[j];
        }
    }
}

__global__ void reduce_k(const float* __restrict__ part, float* __restrict__ out,
                         int M, int H, int W, int d, int centerOnly, int ntaps, int kch,
                         int flags, const float* __restrict__ sc,
                         const float* __restrict__ bi, const float* __restrict__ eb) {
    int HW = H * W;
    int idx = blockIdx.x * 256 + threadIdx.x;
    if (idx >= M * HW) return;
    int m = idx / HW;
    int p = idx - m * HW;
    int y = p / W, x = p - y * W;
    float acc = 0.f;
    for (int s = 0; s < ntaps * kch; s++) {
        int ti = s / kch;
        int dy, dx, y0, x0, rh, rw;
        tap_rect(ti, d, centerOnly, H, W, dy, dx, y0, x0, rh, rw);
        if (y >= y0 && y < y0 + rh && x >= x0 && x < x0 + rw)
            acc += part[(size_t)s * M * HW + idx];
    }
    if (flags & 8) acc += eb[m];
    if (flags & 2) acc = sc[m] * acc + bi[m];
    if (flags & 4) acc = fmaxf(acc, 0.f);
    out[idx] = acc;
}

// ============================ small kernels ============================
__global__ void resize_kk(const float* __restrict__ in, float* __restrict__ out,
                          int C, int Hi, int Wi, int Ho, int Wo, int dorelu) {
    int i = blockIdx.x * 256 + threadIdx.x;
    int total = C * Ho * Wo;
    if (i >= total) return;
    int ox = i % Wo;
    int t = i / Wo;
    int oy = t % Ho;
    int c = t / Ho;
    float ry = (Ho > 1) ? (float)(Hi - 1) / (float)(Ho - 1) : 0.f;
    float rx = (Wo > 1) ? (float)(Wi - 1) / (float)(Wo - 1) : 0.f;
    float tyf = oy * ry;
    int yl = (int)floorf(tyf);
    float fy = tyf - yl;
    int yh = min(yl + 1, Hi - 1);
    float txf = ox * rx;
    int xl = (int)floorf(txf);
    float fx = txf - xl;
    int xh = min(xl + 1, Wi - 1);
    const float* p = in + (size_t)c * Hi * Wi;
    float v00 = p[yl * Wi + xl], v01 = p[yl * Wi + xh];
    float v10 = p[yh * Wi + xl], v11 = p[yh * Wi + xh];
    float v = (v00 * (1.f - fy) + v10 * fy) * (1.f - fx) + (v01 * (1.f - fy) + v11 * fy) * fx;
    if (dorelu) v = fmaxf(v, 0.f);
    out[i] = v;
}

__global__ void energy_k(const float* __restrict__ c1r, const float* __restrict__ c2r,
                         float* __restrict__ att) {
    int p = blockIdx.x * 256 + threadIdx.x;
    if (p >= 4096) return;
    int y = p >> 6, x = p & 63;
    float e[9];
    int nidx[9];
    bool val[9];
#pragma unroll
    for (int a = 0; a < 3; a++)
#pragma unroll
        for (int b = 0; b < 3; b++) {
            int k = a * 3 + b;
            int iy = y + 2 * (a - 1), ix = x + 2 * (b - 1);
            val[k] = (unsigned)iy < 64u && (unsigned)ix < 64u;
            nidx[k] = val[k] ? (iy * 64 + ix) : 0;
            e[k] = 0.f;
        }
    for (int c = 0; c < 64; c++) {
        float v = c1r[c * 4096 + p];
        const float* row = c2r + c * 4096;
#pragma unroll
        for (int k = 0; k < 9; k++)
            if (val[k]) e[k] = fmaf(v, row[nidx[k]], e[k]);
    }
    float mx = e[0];
#pragma unroll
    for (int k = 1; k < 9; k++) mx = fmaxf(mx, e[k]);
    float sum = 0.f, ex[9];
#pragma unroll
    for (int k = 0; k < 9; k++) { ex[k] = expf(e[k] - mx); sum += ex[k]; }
    float inv = 1.f / sum;
#pragma unroll
    for (int k = 0; k < 9; k++) att[k * 4096 + p] = ex[k] * inv;
}

__global__ void gap_k(const float* __restrict__ x, float* __restrict__ gap) {
    int c = blockIdx.x * 8 + (threadIdx.x >> 5);
    int lane = threadIdx.x & 31;
    const float* p = x + (size_t)c * 1024;
    float s = 0.f;
    for (int i = lane; i < 1024; i += 32) s += p[i];
#pragma unroll
    for (int o = 16; o; o >>= 1) s += __shfl_xor_sync(0xffffffffu, s, o);
    if (!lane) gap[c] = s * (1.f / 1024.f);
}

__global__ void f4_k(const float* __restrict__ w, const float* __restrict__ s,
                     const float* __restrict__ b, const float* __restrict__ gap,
                     float* __restrict__ f4) {
    int o = blockIdx.x * 8 + (threadIdx.x >> 5);
    int lane = threadIdx.x & 31;
    const float* row = w + (size_t)o * 4096;
    float acc = 0.f;
    for (int i = lane; i < 4096; i += 32) acc = fmaf(row[i], gap[i], acc);
#pragma unroll
    for (int off = 16; off; off >>= 1) acc += __shfl_xor_sync(0xffffffffu, acc, off);
    if (!lane) f4[o] = fmaxf(s[o] * acc + b[o], 0.f);
}

__global__ void bias4_k(const float* __restrict__ apw, const float* __restrict__ f4,
                        float* __restrict__ b4) {
    int o = blockIdx.x * 8 + (threadIdx.x >> 5);
    int lane = threadIdx.x & 31;
    const float* row = apw + (size_t)o * 2560 + 2048;
    float acc = 0.f;
    for (int i = lane; i < 512; i += 32) acc = fmaf(row[i], f4[i], acc);
#pragma unroll
    for (int off = 16; off; off >>= 1) acc += __shfl_xor_sync(0xffffffffu, acc, off);
    if (!lane) b4[o] = acc;
}

__global__ void agg_k(const float* __restrict__ att, const float* __restrict__ zup,
                      const float* __restrict__ c6b, float* __restrict__ out) {
    int p = blockIdx.x * 256 + threadIdx.x;
    if (p >= 4096) return;
    int y = p >> 6, x = p & 63;
    float acc[19];
#pragma unroll
    for (int o = 0; o < 19; o++) acc[o] = c6b[o];
#pragma unroll
    for (int a = 0; a < 3; a++)
#pragma unroll
        for (int b = 0; b < 3; b++) {
            int k = a * 3 + b;
            int iy = y + 2 * (a - 1), ix = x + 2 * (b - 1);
            if ((unsigned)iy < 64u && (unsigned)ix < 64u) {
                float w = att[k * 4096 + p];
                int n = iy * 64 + ix;
#pragma unroll
                for (int o = 0; o < 19; o++) acc[o] = fmaf(w, zup[o * 4096 + n], acc[o]);
            }
        }
#pragma unroll
    for (int o = 0; o < 19; o++) out[o * 4096 + p] = acc[o];
}

// ============================ host driver ============================
static float* g_part_p;

static void run_conv(int mt, const float* Wt, int Arow, int wstride, int wofs0, int centerOnly,
                     const float* X, float* Cout,
                     int M, int K, int H, int Wd, int d, int kch,
                     const float* sc, const float* bi, const float* eb, int flags) {
    int ntaps = (d > 0 && !centerOnly) ? 9 : 1;
    int HW = H * Wd;
    int Kc = K / kch;
    dim3 grid((HW + 63) / 64, (M + mt - 1) / mt, ntaps * kch);
    if (mt == 128)
        gemm2<128><<<grid, 256>>>(Wt, Arow, wstride, wofs0, centerOnly, X, g_part_p,
                                  M, Kc, kch, H, Wd, d);
    else
        gemm2<64><<<grid, 256>>>(Wt, Arow, wstride, wofs0, centerOnly, X, g_part_p,
                                 M, Kc, kch, H, Wd, d);
    int tot = M * HW;
    reduce_k<<<(tot + 255) / 256, 256>>>(g_part_p, Cout, M, H, Wd, d, centerOnly,
                                         ntaps, kch, flags, sc, bi, eb);
}

extern "C" void kernel_launch(void* const* d_in, const int* in_sizes, int n_in,
                              void* d_out, int out_size) {
    const float* c1 = (const float*)d_in[0];
    const float* c2 = (const float*)d_in[1];
    const float* x = (const float*)d_in[2];
    const float* rf1_w = (const float*)d_in[3];
    const float* rf1_s = (const float*)d_in[4];
    const float* rf1_b = (const float*)d_in[5];
    const float* rf2_w = (const float*)d_in[6];
    const float* rf2_s = (const float*)d_in[7];
    const float* rf2_b = (const float*)d_in[8];
    const float* r2_w = (const float*)d_in[9];
    const float* r2_s = (const float*)d_in[10];
    const float* r2_b = (const float*)d_in[11];
    const float* a0_w = (const float*)d_in[12];
    const float* a0_s = (const float*)d_in[13];
    const float* a0_b = (const float*)d_in[14];
    const float* a1_w = (const float*)d_in[15];
    const float* a1_s = (const float*)d_in[16];
    const float* a1_b = (const float*)d_in[17];
    const float* a2_w = (const float*)d_in[18];
    const float* a2_s = (const float*)d_in[19];
    const float* a2_b = (const float*)d_in[20];
    const float* a3_w = (const float*)d_in[21];
    const float* a3_s = (const float*)d_in[22];
    const float* a3_b = (const float*)d_in[23];
    const float* a4_w = (const float*)d_in[24];
    const float* a4_s = (const float*)d_in[25];
    const float* a4_b = (const float*)d_in[26];
    const float* ap_w = (const float*)d_in[27];
    const float* ap_s = (const float*)d_in[28];
    const float* ap_b = (const float*)d_in[29];
    const float* c6_w = (const float*)d_in[30];
    const float* c6_b = (const float*)d_in[31];

    float *t2, *c1r, *c2r, *att, *gap, *f4, *b4, *outb, *z, *zup;
    __half *whi, *xthi, *xtlo, *fhi, *flo, *c1thi, *c1tlo, *t1thi, *t1tlo;
    cudaGetSymbolAddress((void**)&g_part_p, g_part);
    cudaGetSymbolAddress((void**)&t2, g_t2);
    cudaGetSymbolAddress((void**)&c1r, g_c1r);
    cudaGetSymbolAddress((void**)&c2r, g_c2r);
    cudaGetSymbolAddress((void**)&att, g_att);
    cudaGetSymbolAddress((void**)&gap, g_gap);
    cudaGetSymbolAddress((void**)&f4, g_f4);
    cudaGetSymbolAddress((void**)&b4, g_b4);
    cudaGetSymbolAddress((void**)&outb, g_outb);
    cudaGetSymbolAddress((void**)&z, g_z);
    cudaGetSymbolAddress((void**)&zup, g_zup);
    cudaGetSymbolAddress((void**)&whi, g_whi);
    cudaGetSymbolAddress((void**)&xthi, g_xthi);
    cudaGetSymbolAddress((void**)&xtlo, g_xtlo);
    cudaGetSymbolAddress((void**)&fhi, g_fhi);
    cudaGetSymbolAddress((void**)&flo, g_flo);
    cudaGetSymbolAddress((void**)&c1thi, g_c1thi);
    cudaGetSymbolAddress((void**)&c1tlo, g_c1tlo);
    cudaGetSymbolAddress((void**)&t1thi, g_t1thi);
    cudaGetSymbolAddress((void**)&t1tlo, g_t1tlo);

    const int SMEM_H1 = 3 * 18432 * 2;   // 110592 B (single-pass, 3 stages)
    const int SMEM_H2 = 2 * 27648 * 2;   // 110592 B (2-pass, 2 stages)
    cudaFuncSetAttribute(hgemm<0>, cudaFuncAttributeMaxDynamicSharedMemorySize, SMEM_H1);
    cudaFuncSetAttribute(hgemm<1>, cudaFuncAttributeMaxDynamicSharedMemorySize, SMEM_H2);

    // --- conversions; launch #4 = a1 hgemm (ncu captures the 4th launch) ---
    xtrans_g<<<dim3(32, 128), 256>>>(x, xthi, xtlo, 1024, 4096);                       // 1
    wconv3x3<<<dim3(512, 8), 256>>>(a1_w, whi + S_A1);                                 // 2
    wconv3x3<<<dim3(512, 8), 256>>>(a2_w, whi + S_A2);                                 // 3
    hgemm<0><<<dim3(8, 4, 9), 256, SMEM_H1>>>(whi + S_A1, xthi, nullptr, g_part_p,
                                              4096, 4096, 4096, 1, 12, 5, 1024, 1);    // 4 <- profiled
    reduce_ht<<<dim3(32, 16), 256>>>(g_part_p, 9, 512, 1024, a1_s, a1_b, fhi, flo, 2048, 512, 12, 5);
    hgemm<0><<<dim3(8, 4, 9), 256, SMEM_H1>>>(whi + S_A2, xthi, nullptr, g_part_p,
                                              4096, 4096, 4096, 1, 24, 5, 1024, 1);
    reduce_ht<<<dim3(32, 16), 256>>>(g_part_p, 9, 512, 1024, a2_s, a2_b, fhi, flo, 2048, 1024, 24, 5);
    wconv1x1<<<(512 * 4096 / 4 + 255) / 256, 256>>>(a0_w, 4096, 4096, whi + S_A0, 512 * 1024);
    hgemm<0><<<dim3(8, 4, 8), 256, SMEM_H1>>>(whi + S_A0, xthi, nullptr, g_part_p,
                                              4096, 512, 4096, 0, 0, 5, 1024, 0);
    reduce_ht<<<dim3(32, 16), 256>>>(g_part_p, 8, 512, 1024, a0_s, a0_b, fhi, flo, 2048, 0, 0, 5);
    wcenter<<<(512 * 2048 + 255) / 256, 256>>>(a3_w, whi + S_A3);
    hgemm<0><<<dim3(8, 4, 8), 256, SMEM_H1>>>(whi + S_A3, xthi, nullptr, g_part_p,
                                              4096, 512, 4096, 0, 0, 5, 1024, 0);
    reduce_ht<<<dim3(32, 16), 256>>>(g_part_p, 8, 512, 1024, a3_s, a3_b, fhi, flo, 2048, 1536, 0, 5);

    // --- attention branch: refine convs on HMMA (2-pass for accuracy) ---
    xtrans_g<<<dim3(128, 8), 256>>>(c1, c1thi, c1tlo, 4096, 256);
    wrf_k<<<(64 * 256 * 9 + 255) / 256, 256>>>(rf1_w, whi + S_RF1, 64, 256);
    wrf_k<<<(64 * 64 * 9 + 255) / 256, 256>>>(rf2_w, whi + S_RF2, 64, 64);
    hgemm<1><<<dim3(32, 1, 9), 256, SMEM_H2>>>(whi + S_RF1, c1thi, c1tlo, g_part_p,
                                               256, 256, 256, 1, 2, 6, 4096, 1);
    reduce_ht<<<dim3(128, 2), 256>>>(g_part_p, 9, 128, 4096, rf1_s, rf1_b, t1thi, t1tlo, 64, 0, 2, 6);
    hgemm<1><<<dim3(32, 1, 9), 256, SMEM_H2>>>(whi + S_RF2, t1thi, t1tlo, g_part_p,
                                               64, 64, 64, 1, 2, 6, 4096, 1);
    reduce_pl<<<(64 * 4096 + 255) / 256, 256>>>(g_part_p, c1r, 9, 128, 4096, 64, 6,
                                                rf2_s, rf2_b, nullptr, 2, 6);
    run_conv(64, r2_w, 512, 1, 0, 1, c2, t2, 64, 512, 32, 32, 0, 4, r2_s, r2_b, nullptr, 2);
    resize_kk<<<(64 * 4096 + 255) / 256, 256>>>(t2, c2r, 64, 32, 32, 64, 64, 1);
    energy_k<<<16, 256>>>(c1r, c2r, att);

    // --- GAP branch + ap (2-pass: exact fcat via hi/lo) ---
    gap_k<<<512, 256>>>(x, gap);
    f4_k<<<64, 256>>>(a4_w, a4_s, a4_b, gap, f4);
    bias4_k<<<64, 256>>>(ap_w, f4, b4);
    wconv1x1<<<(512 * 2048 / 4 + 255) / 256, 256>>>(ap_w, 2560, 2048, whi + S_AP, 512 * 512);
    hgemm<1><<<dim3(8, 4, 8), 256, SMEM_H2>>>(whi + S_AP, fhi, flo, g_part_p,
                                              2048, 256, 2048, 0, 0, 5, 1024, 0);
    reduce_pl<<<2048, 256>>>(g_part_p, outb, 8, 512, 1024, 512, 2 | 4 | 8,
                             ap_s, ap_b, b4, 0, 5);

    // --- final head ---
    run_conv(64, c6_w, 512, 1, 0, 1, outb, z, 19, 512, 32, 32, 0, 4, nullptr, nullptr, nullptr, 0);
    resize_kk<<<(19 * 4096 + 255) / 256, 256>>>(z, zup, 19, 32, 32, 64, 64, 0);
    agg_k<<<16, 256>>>(att, zup, c6_b, (float*)d_out);
}

// round 14
// speedup vs baseline: 1.7347x; 1.0543x over previous
#include <cuda_runtime.h>
#include <cuda_fp16.h>
#include <math.h>
#include <stdint.h>

#define DEV_INLINE __device__ __forceinline__

DEV_INLINE unsigned long long pk2(float lo, float hi) {
    unsigned long long r;
    asm("mov.b64 %0, {%1, %2};" : "=l"(r) : "f"(lo), "f"(hi));
    return r;
}
DEV_INLINE void unpk2(unsigned long long v, float& lo, float& hi) {
    asm("mov.b64 {%0, %1}, %2;" : "=f"(lo), "=f"(hi) : "l"(v));
}
#define FFMA2(d, a, b) asm("fma.rn.f32x2 %0, %1, %2, %0;" : "+l"(d) : "l"(a), "l"(b))

DEV_INLINE void mma_f16(float* c, const uint32_t* a, const uint32_t* b) {
    asm volatile(
        "mma.sync.aligned.m16n8k16.row.col.f32.f16.f16.f32 "
        "{%0,%1,%2,%3}, {%4,%5,%6,%7}, {%8,%9}, {%0,%1,%2,%3};"
        : "+f"(c[0]), "+f"(c[1]), "+f"(c[2]), "+f"(c[3])
        : "r"(a[0]), "r"(a[1]), "r"(a[2]), "r"(a[3]), "r"(b[0]), "r"(b[1]));
}
DEV_INLINE void ldsm_x4(uint32_t& r0, uint32_t& r1, uint32_t& r2, uint32_t& r3, uint32_t a) {
    asm volatile("ldmatrix.sync.aligned.m8n8.x4.shared.b16 {%0,%1,%2,%3}, [%4];"
                 : "=r"(r0), "=r"(r1), "=r"(r2), "=r"(r3) : "r"(a));
}

#define CP_ASYNC_CG(dst, src, sz) \
    asm volatile("cp.async.cg.shared.global [%0], [%1], 16, %2;" \
                 :: "r"(dst), "l"(src), "r"(sz) : "memory")
#define CP_COMMIT() asm volatile("cp.async.commit_group;" ::: "memory")
#define CP_WAIT_N1() asm volatile("cp.async.wait_group 1;" ::: "memory")
#define CP_WAIT_N2() asm volatile("cp.async.wait_group 2;" ::: "memory")

// ============================ scratch ============================
__device__ float g_part[10 * 1024 * 1024];    // up to 18 slices x 512 x 1024
__device__ float g_t2[64 * 1024];
__device__ float g_c1r[64 * 4096];
__device__ float g_c2r[64 * 4096];
__device__ float g_att[9 * 4096];
__device__ float g_gap[4096];
__device__ float g_f4[512];
__device__ float g_b4[512];
__device__ float g_outb[512 * 1024];
__device__ float g_z[19 * 1024];
__device__ float g_zup[19 * 4096];
__device__ __align__(16) __half g_whi[43360256];
__device__ __align__(16) __half g_xthi[1024 * 4096];
__device__ __align__(16) __half g_xtlo[1024 * 4096];
__device__ __align__(16) __half g_fhi[1024 * 2048];
__device__ __align__(16) __half g_flo[1024 * 2048];
__device__ __align__(16) __half g_c1thi[4096 * 256];
__device__ __align__(16) __half g_c1tlo[4096 * 256];
__device__ __align__(16) __half g_t1thi[4096 * 64];
__device__ __align__(16) __half g_t1tlo[4096 * 64];

static const size_t S_A0 = 0;
static const size_t S_A1 = 2097152;
static const size_t S_A2 = 20971520;
static const size_t S_A3 = 39845888;
static const size_t S_AP = 41943040;
static const size_t S_RF1 = 42991616;
static const size_t S_RF2 = 43286528;

// ============================ HMMA GEMM (fp16, multi-stage cp.async + ldmatrix) ============================
// slice s = (tap, k-chunk): ti = s/kch, kc = s%kch. part[s][m][pix] = partial GEMM.
// CTA: 128(m) x 128(pix), 8 warps of 64x32. k-chunks of 64.
// Pipeline: 3 stages (single-pass) / 2 stages (2-pass; smem limit).
template <int USE_LO>
__global__ void __launch_bounds__(256, 2)
hgemm(const __half* __restrict__ Wh,
      const __half* __restrict__ Xhi, const __half* __restrict__ Xlo,
      float* __restrict__ part,
      int Ktot, int Kc, int Kx, int kch, int tapMode, int dil, int wshift, int HW, int skipEn)
{
    extern __shared__ __half sm[];
    constexpr int NSTAGE = USE_LO ? 2 : 3;
    const int STG = USE_LO ? 27648 : 18432;     // halfs per stage
    const uint32_t smB = (uint32_t)__cvta_generic_to_shared(sm);
    const uint32_t STGB = STG * 2;

    const int tid = threadIdx.x;
    const int wid = tid >> 5, lane = tid & 31;
    const int s = blockIdx.z;
    const int ti = s / kch;
    const int kc = s - ti * kch;
    const int m0 = blockIdx.y * 128;
    const int n0 = blockIdx.x * 128;
    const int Mpad = gridDim.y * 128;
    const int Wimg = 1 << wshift;

    int dy = 0, dx = 0;
    size_t wbase = 0;
    if (tapMode) {
        dy = (ti / 3 - 1) * dil;
        dx = (ti % 3 - 1) * dil;
        wbase = (size_t)ti * Mpad * Ktot;
        if (skipEn) {
            int tileRows = 128 >> wshift;
            int r0 = n0 >> wshift;
            if (r0 + tileRows - 1 + dy < 0 || r0 + dy >= Wimg) return;  // masked in reduce
        }
    }
    const int k0s = kc * Kc;

    // per-thread load descriptors (fixed across chunks)
    const __half* gA[4];
    uint32_t sAo[4];
    const __half* gB[4];
    const __half* gBl[4];
    uint32_t sBo[4];
    int bsz[4];
#pragma unroll
    for (int i = 0; i < 4; i++) {
        int v = tid + 256 * i;
        int mr = v >> 3, ko = (v & 7) * 8;
        gA[i] = Wh + wbase + (size_t)(m0 + mr) * Ktot + k0s + ko;
        sAo[i] = (mr * 72 + ko) * 2;
        int nr = mr;
        int q = n0 + nr;
        int iy = (q >> wshift) + dy, ix = (q & (Wimg - 1)) + dx;
        bool ok = (unsigned)iy < (unsigned)Wimg && (unsigned)ix < (unsigned)Wimg;
        size_t gb = ok ? (size_t)((iy << wshift) + ix) * Kx + k0s + ko : 0;
        gB[i] = Xhi + gb;
        gBl[i] = USE_LO ? (Xlo + gb) : Xhi;
        bsz[i] = ok ? 16 : 0;
        sBo[i] = (nr * 72 + ko) * 2;
    }

    const int wm = (wid & 1) * 64;
    const int wn = (wid >> 1) * 32;

    // ldmatrix address offsets (bytes, within stage)
    uint32_t aOff[4], bOff[2];
#pragma unroll
    for (int im = 0; im < 4; im++)
        aOff[im] = ((wm + im * 16 + (lane & 15)) * 72 + (lane >> 4) * 8) * 2;
#pragma unroll
    for (int pi = 0; pi < 2; pi++)
        bOff[pi] = ((wn + pi * 16 + ((lane >> 4) & 1) * 8 + (lane & 7)) * 72 +
                    ((lane >> 3) & 1) * 8) * 2 + 18432;

    float acc[4][4][4];
#pragma unroll
    for (int i = 0; i < 4; i++)
#pragma unroll
        for (int j = 0; j < 4; j++)
#pragma unroll
            for (int q = 0; q < 4; q++) acc[i][j][q] = 0.f;

    const int nChunks = Kc / 64;

#define LOADCHUNK(sb)                                                            \
    do {                                                                         \
        _Pragma("unroll")                                                        \
        for (int i = 0; i < 4; i++) { CP_ASYNC_CG((sb) + sAo[i], gA[i], 16); gA[i] += 64; } \
        _Pragma("unroll")                                                        \
        for (int i = 0; i < 4; i++) {                                            \
            CP_ASYNC_CG((sb) + 18432 + sBo[i], gB[i], bsz[i]);                   \
            gB[i] += 64;                                                         \
            if (USE_LO) { CP_ASYNC_CG((sb) + 36864 + sBo[i], gBl[i], bsz[i]); gBl[i] += 64; } \
        }                                                                        \
    } while (0)

    // prologue: stage chunks 0..NSTAGE-2
    {
        int npro = (NSTAGE - 1 < nChunks) ? NSTAGE - 1 : nChunks;
        for (int p = 0; p < npro; p++) {
            LOADCHUNK(smB + p * STGB);
            CP_COMMIT();
        }
        for (int p = npro; p < NSTAGE - 1; p++) CP_COMMIT();
    }

    for (int c = 0; c < nChunks; c++) {
        int pf = c + NSTAGE - 1;
        if (pf < nChunks) LOADCHUNK(smB + (pf % NSTAGE) * STGB);
        CP_COMMIT();
        if (USE_LO) CP_WAIT_N1(); else CP_WAIT_N2();   // chunk c resident
        __syncthreads();

        const uint32_t sbase = smB + (c % NSTAGE) * STGB;

#pragma unroll
        for (int kk = 0; kk < 64; kk += 16) {
            uint32_t af[4][4], bh[4][2];
#pragma unroll
            for (int im = 0; im < 4; im++)
                ldsm_x4(af[im][0], af[im][1], af[im][2], af[im][3],
                        sbase + aOff[im] + kk * 2);
#pragma unroll
            for (int pi = 0; pi < 2; pi++)
                ldsm_x4(bh[2 * pi][0], bh[2 * pi][1], bh[2 * pi + 1][0], bh[2 * pi + 1][1],
                        sbase + bOff[pi] + kk * 2);
#pragma unroll
            for (int im = 0; im < 4; im++)
#pragma unroll
                for (int in_ = 0; in_ < 4; in_++) mma_f16(acc[im][in_], af[im], bh[in_]);
            if (USE_LO) {
                uint32_t bl[4][2];
#pragma unroll
                for (int pi = 0; pi < 2; pi++)
                    ldsm_x4(bl[2 * pi][0], bl[2 * pi][1], bl[2 * pi + 1][0], bl[2 * pi + 1][1],
                            sbase + bOff[pi] + 18432 + kk * 2);
#pragma unroll
                for (int im = 0; im < 4; im++)
#pragma unroll
                    for (int in_ = 0; in_ < 4; in_++) mma_f16(acc[im][in_], af[im], bl[in_]);
            }
        }
        __syncthreads();   // stage reusable for the prefetch issued next iteration
    }
#undef LOADCHUNK

    float* po = part + (size_t)s * Mpad * HW;
    const int r = lane >> 2;
    const int cp = (lane & 3) * 2;
    const int rbase = m0 + wm + r;
    const int cbase = n0 + wn + cp;
#pragma unroll
    for (int im = 0; im < 4; im++)
#pragma unroll
        for (int in_ = 0; in_ < 4; in_++) {
            int m = rbase + im * 16, n = cbase + in_ * 8;
            float2 v0 = make_float2(acc[im][in_][0], acc[im][in_][1]);
            float2 v1 = make_float2(acc[im][in_][2], acc[im][in_][3]);
            *(float2*)&po[(size_t)m * HW + n] = v0;
            *(float2*)&po[(size_t)(m + 8) * HW + n] = v1;
        }
}

// reduce slices + bn_relu, write TRANSPOSED fp16 hi/lo (tap-masked by row; tap = s/kch)
__global__ void reduce_ht(const float* __restrict__ part, int S, int kch, int Mpad, int HW,
                          const float* __restrict__ sc, const float* __restrict__ bi,
                          __half* __restrict__ ohi, __half* __restrict__ olo,
                          int ostride, int colOff, int tapDil, int wshift)
{
    __shared__ float t[32][33];
    int tx = threadIdx.x & 31, ty = threadIdx.x >> 5;
    int q0 = blockIdx.x * 32, m0 = blockIdx.y * 32;
    int y = q0 >> wshift;
    int Wimg = 1 << wshift;
#pragma unroll
    for (int r = 0; r < 4; r++) {
        int ml = ty + 8 * r;
        int m = m0 + ml;
        float a = 0.f;
        for (int s = 0; s < S; s++) {
            if (tapDil) {
                int dy = ((s / kch) / 3 - 1) * tapDil;
                if ((unsigned)(y + dy) >= (unsigned)Wimg) continue;
            }
            a += part[(size_t)s * Mpad * HW + (size_t)m * HW + q0 + tx];
        }
        t[ml][tx] = fmaxf(sc[m] * a + bi[m], 0.f);
    }
    __syncthreads();
#pragma unroll
    for (int r = 0; r < 4; r++) {
        int ql = ty + 8 * r;
        float v = t[tx][ql];
        __half h = __float2half_rn(v);
        size_t o = (size_t)(q0 + ql) * ostride + colOff + m0 + tx;
        ohi[o] = h;
        olo[o] = __float2half_rn(v - __half2float(h));
    }
}

// reduce slices + epilogue to plain fp32
__global__ void reduce_pl(const float* __restrict__ part, float* __restrict__ out,
                          int S, int kch, int Mpad, int HW, int Mtot, int flags,
                          const float* __restrict__ sc, const float* __restrict__ bi,
                          const float* __restrict__ eb, int tapDil, int wshift)
{
    int idx = blockIdx.x * 256 + threadIdx.x;
    if (idx >= Mtot * HW) return;
    int m = idx / HW;
    int p = idx - m * HW;
    int y = p >> wshift;
    int Wimg = 1 << wshift;
    float a = 0.f;
    for (int s = 0; s < S; s++) {
        if (tapDil) {
            int dy = ((s / kch) / 3 - 1) * tapDil;
            if ((unsigned)(y + dy) >= (unsigned)Wimg) continue;
        }
        a += part[(size_t)s * Mpad * HW + idx];
    }
    if (flags & 8) a += eb[m];
    if (flags & 2) a = sc[m] * a + bi[m];
    if (flags & 4) a = fmaxf(a, 0.f);
    out[idx] = a;
}

// ============================ conversion pre-passes ============================
__global__ void xtrans_g(const float* __restrict__ in,
                         __half* __restrict__ ohi, __half* __restrict__ olo,
                         int HW, int K) {
    __shared__ float t[32][33];
    int tx = threadIdx.x & 31, ty = threadIdx.x >> 5;
    int q0 = blockIdx.x * 32, k0 = blockIdx.y * 32;
#pragma unroll
    for (int r = 0; r < 4; r++)
        t[ty + 8 * r][tx] = in[(size_t)(k0 + ty + 8 * r) * HW + q0 + tx];
    __syncthreads();
#pragma unroll
    for (int r = 0; r < 4; r++) {
        int ql = ty + 8 * r;
        float v = t[tx][ql];
        __half h = __float2half_rn(v);
        size_t o = (size_t)(q0 + ql) * K + k0 + tx;
        ohi[o] = h;
        olo[o] = __float2half_rn(v - __half2float(h));
    }
}

__global__ void wconv1x1(const float* __restrict__ in, int rowStride, int K,
                         __half* __restrict__ whi, int total4) {
    int i = blockIdx.x * 256 + threadIdx.x;
    if (i >= total4) return;
    int e = i * 4, m = e / K, k = e - m * K;
    float4 v = *(const float4*)(in + (size_t)m * rowStride + k);
    size_t o = (size_t)m * K + k;
    *(__half2*)(whi + o) = __floats2half2_rn(v.x, v.y);
    *(__half2*)(whi + o + 2) = __floats2half2_rn(v.z, v.w);
}

__global__ void wconv3x3(const float* __restrict__ in, __half* __restrict__ whi) {
    __shared__ float st[4608];
    int m = blockIdx.x, kb = blockIdx.y;
    const float* src = in + (size_t)m * 36864 + (size_t)kb * 4608;
    for (int i = threadIdx.x; i < 1152; i += 256)
        *(float4*)(st + 4 * i) = *(const float4*)(src + 4 * i);
    __syncthreads();
    for (int j = threadIdx.x; j < 2304; j += 256) {
        int t = j / 256, k = (j & 255) * 2;
        size_t o = ((size_t)t * 512 + m) * 4096 + kb * 512 + k;
        *(__half2*)(whi + o) = __floats2half2_rn(st[k * 9 + t], st[(k + 1) * 9 + t]);
    }
}

__global__ void wcenter(const float* __restrict__ in, __half* __restrict__ whi) {
    int i = blockIdx.x * 256 + threadIdx.x;
    if (i >= 512 * 2048) return;
    int e = i * 2, m = e >> 12, k = e & 4095;
    const float* p = in + (size_t)m * 36864 + k * 9 + 4;
    *(__half2*)(whi + e) = __floats2half2_rn(p[0], p[9]);
}

__global__ void wrf_k(const float* __restrict__ in, __half* __restrict__ out, int M, int K) {
    int i = blockIdx.x * 256 + threadIdx.x;
    if (i >= M * K * 9) return;
    int m = i / (K * 9);
    int rem = i - m * K * 9;
    int k = rem / 9, t = rem - k * 9;
    out[((size_t)t * 128 + m) * K + k] = __float2half_rn(in[i]);
}

// ============================ FFMA2 path (r2, c6) ============================
DEV_INLINE void tap_rect(int ti, int d, int centerOnly, int H, int W,
                         int& dy, int& dx, int& y0, int& x0, int& rh, int& rw) {
    if (centerOnly || d == 0) { dy = dx = 0; y0 = x0 = 0; rh = H; rw = W; return; }
    dy = (ti / 3 - 1) * d;
    dx = (ti % 3 - 1) * d;
    y0 = dy < 0 ? -dy : 0;
    x0 = dx < 0 ? -dx : 0;
    rh = H - (dy < 0 ? -dy : dy);
    rw = W - (dx < 0 ? -dx : dx);
}

template <int MT>
__global__ void __launch_bounds__(256, 2)
gemm2(const float* __restrict__ W, int Arow, int wstride, int wofs0, int centerOnly,
      const float* __restrict__ X, float* __restrict__ part,
      int M, int Kc, int kch, int H, int Wd, int d)
{
    constexpr int NT = 64, KT = 16;
    constexpr int ROWS = MT / 16;
    __shared__ float sA[KT][MT + 4];
    __shared__ float sB[KT][NT + 4];

    const int tid = threadIdx.x;
    const int s = blockIdx.z;
    const int ti = s / kch;
    const int kc = s - ti * kch;
    int dy, dx, y0, x0, rh, rw;
    tap_rect(ti, d, centerOnly, H, Wd, dy, dx, y0, x0, rh, rw);
    const int rectN = rh * rw;
    const int HW = H * Wd;
    const int n0 = blockIdx.x * NT;
    if (n0 >= rectN) return;
    const int m0 = blockIdx.y * MT;
    const int wofs = centerOnly ? wofs0 : ti;
    const int kcS = kc * Kc;

    const int nB = tid & 63, kB = tid >> 6;
    bool bval = false;
    const float* pB[4];
    {
        int pofs = 0;
        int nn = n0 + nB;
        if (nn < rectN) {
            int yy = nn / rw, xx = nn - yy * rw;
            bval = true;
            pofs = (y0 + yy + dy) * Wd + (x0 + xx + dx);
        }
#pragma unroll
        for (int t = 0; t < 4; t++) pB[t] = X + (size_t)(kcS + kB + 4 * t) * HW + pofs;
    }
    const int kA = tid & 15, mA = tid >> 4;
    const float* pA[ROWS];
    bool aval[ROWS];
#pragma unroll
    for (int t = 0; t < ROWS; t++) {
        int mg = m0 + mA + 16 * t;
        aval[t] = (mg < M);
        pA[t] = W + (aval[t] ? ((size_t)mg * Arow + wofs + (size_t)(kcS + kA) * wstride) : 0);
    }

    unsigned long long acc[ROWS][2];
#pragma unroll
    for (int i = 0; i < ROWS; i++) { acc[i][0] = 0ull; acc[i][1] = 0ull; }

    float rA[ROWS], rB[4];
#pragma unroll
    for (int t = 0; t < ROWS; t++) { rA[t] = aval[t] ? __ldg(pA[t]) : 0.f; pA[t] += (size_t)KT * wstride; }
#pragma unroll
    for (int t = 0; t < 4; t++) { rB[t] = bval ? __ldg(pB[t]) : 0.f; pB[t] += (size_t)KT * HW; }

    const int tx = tid & 15, ty = tid >> 4;

    for (int k0 = 0; k0 < Kc; k0 += KT) {
#pragma unroll
        for (int t = 0; t < ROWS; t++) sA[kA][mA + 16 * t] = rA[t];
#pragma unroll
        for (int t = 0; t < 4; t++) sB[kB + 4 * t][nB] = rB[t];
        __syncthreads();
        if (k0 + KT < Kc) {
#pragma unroll
            for (int t = 0; t < ROWS; t++) { rA[t] = aval[t] ? __ldg(pA[t]) : 0.f; pA[t] += (size_t)KT * wstride; }
#pragma unroll
            for (int t = 0; t < 4; t++) { rB[t] = bval ? __ldg(pB[t]) : 0.f; pB[t] += (size_t)KT * HW; }
        }
#pragma unroll
        for (int kk = 0; kk < KT; kk++) {
            const unsigned long long* bp =
                reinterpret_cast<const unsigned long long*>(&sB[kk][tx * 4]);
            unsigned long long b0 = bp[0], b1 = bp[1];
            const float* ar = &sA[kk][ty * ROWS];
#pragma unroll
            for (int i = 0; i < ROWS; i++) {
                float a = ar[i];
                unsigned long long ap = pk2(a, a);
                FFMA2(acc[i][0], ap, b0);
                FFMA2(acc[i][1], ap, b1);
            }
        }
        __syncthreads();
    }

    float* po = part + (size_t)s * M * HW;
#pragma unroll
    for (int i = 0; i < ROWS; i++) {
        int m = m0 + ty * ROWS + i;
        if (m >= M) continue;
        float vals[4];
        unpk2(acc[i][0], vals[0], vals[1]);
        unpk2(acc[i][1], vals[2], vals[3]);
#pragma unroll
        for (int j = 0; j < 4; j++) {
            int n2 = n0 + tx * 4 + j;
            if (n2 >= rectN) continue;
            int yy = n2 / rw, xx = n2 - yy * rw;
            po[(size_t)m * HW + (y0 + yy) * Wd + (x0 + xx)] = vals[j];
        }
    }
}

__global__ void reduce_k(const float* __restrict__ part, float* __restrict__ out,
                         int M, int H, int W, int d, int centerOnly, int ntaps, int kch,
                         int flags, const float* __restrict__ sc,
                         const float* __restrict__ bi, const float* __restrict__ eb) {
    int HW = H * W;
    int idx = blockIdx.x * 256 + threadIdx.x;
    if (idx >= M * HW) return;
    int m = idx / HW;
    int p = idx - m * HW;
    int y = p / W, x = p - y * W;
    float acc = 0.f;
    for (int s = 0; s < ntaps * kch; s++) {
        int ti = s / kch;
        int dy, dx, y0, x0, rh, rw;
        tap_rect(ti, d, centerOnly, H, W, dy, dx, y0, x0, rh, rw);
        if (y >= y0 && y < y0 + rh && x >= x0 && x < x0 + rw)
            acc += part[(size_t)s * M * HW + idx];
    }
    if (flags & 8) acc += eb[m];
    if (flags & 2) acc = sc[m] * acc + bi[m];
    if (flags & 4) acc = fmaxf(acc, 0.f);
    out[idx] = acc;
}

// ============================ small kernels ============================
__global__ void resize_kk(const float* __restrict__ in, float* __restrict__ out,
                          int C, int Hi, int Wi, int Ho, int Wo, int dorelu) {
    int i = blockIdx.x * 256 + threadIdx.x;
    int total = C * Ho * Wo;
    if (i >= total) return;
    int ox = i % Wo;
    int t = i / Wo;
    int oy = t % Ho;
    int c = t / Ho;
    float ry = (Ho > 1) ? (float)(Hi - 1) / (float)(Ho - 1) : 0.f;
    float rx = (Wo > 1) ? (float)(Wi - 1) / (float)(Wo - 1) : 0.f;
    float tyf = oy * ry;
    int yl = (int)floorf(tyf);
    float fy = tyf - yl;
    int yh = min(yl + 1, Hi - 1);
    float txf = ox * rx;
    int xl = (int)floorf(txf);
    float fx = txf - xl;
    int xh = min(xl + 1, Wi - 1);
    const float* p = in + (size_t)c * Hi * Wi;
    float v00 = p[yl * Wi + xl], v01 = p[yl * Wi + xh];
    float v10 = p[yh * Wi + xl], v11 = p[yh * Wi + xh];
    float v = (v00 * (1.f - fy) + v10 * fy) * (1.f - fx) + (v01 * (1.f - fy) + v11 * fy) * fx;
    if (dorelu) v = fmaxf(v, 0.f);
    out[i] = v;
}

__global__ void energy_k(const float* __restrict__ c1r, const float* __restrict__ c2r,
                         float* __restrict__ att) {
    int p = blockIdx.x * 256 + threadIdx.x;
    if (p >= 4096) return;
    int y = p >> 6, x = p & 63;
    float e[9];
    int nidx[9];
    bool val[9];
#pragma unroll
    for (int a = 0; a < 3; a++)
#pragma unroll
        for (int b = 0; b < 3; b++) {
            int k = a * 3 + b;
            int iy = y + 2 * (a - 1), ix = x + 2 * (b - 1);
            val[k] = (unsigned)iy < 64u && (unsigned)ix < 64u;
            nidx[k] = val[k] ? (iy * 64 + ix) : 0;
            e[k] = 0.f;
        }
    for (int c = 0; c < 64; c++) {
        float v = c1r[c * 4096 + p];
        const float* row = c2r + c * 4096;
#pragma unroll
        for (int k = 0; k < 9; k++)
            if (val[k]) e[k] = fmaf(v, row[nidx[k]], e[k]);
    }
    float mx = e[0];
#pragma unroll
    for (int k = 1; k < 9; k++) mx = fmaxf(mx, e[k]);
    float sum = 0.f, ex[9];
#pragma unroll
    for (int k = 0; k < 9; k++) { ex[k] = expf(e[k] - mx); sum += ex[k]; }
    float inv = 1.f / sum;
#pragma unroll
    for (int k = 0; k < 9; k++) att[k * 4096 + p] = ex[k] * inv;
}

__global__ void gap_k(const float* __restrict__ x, float* __restrict__ gap) {
    int c = blockIdx.x * 8 + (threadIdx.x >> 5);
    int lane = threadIdx.x & 31;
    const float* p = x + (size_t)c * 1024;
    float s = 0.f;
    for (int i = lane; i < 1024; i += 32) s += p[i];
#pragma unroll
    for (int o = 16; o; o >>= 1) s += __shfl_xor_sync(0xffffffffu, s, o);
    if (!lane) gap[c] = s * (1.f / 1024.f);
}

__global__ void f4_k(const float* __restrict__ w, const float* __restrict__ s,
                     const float* __restrict__ b, const float* __restrict__ gap,
                     float* __restrict__ f4) {
    int o = blockIdx.x * 8 + (threadIdx.x >> 5);
    int lane = threadIdx.x & 31;
    const float* row = w + (size_t)o * 4096;
    float acc = 0.f;
    for (int i = lane; i < 4096; i += 32) acc = fmaf(row[i], gap[i], acc);
#pragma unroll
    for (int off = 16; off; off >>= 1) acc += __shfl_xor_sync(0xffffffffu, acc, off);
    if (!lane) f4[o] = fmaxf(s[o] * acc + b[o], 0.f);
}

__global__ void bias4_k(const float* __restrict__ apw, const float* __restrict__ f4,
                        float* __restrict__ b4) {
    int o = blockIdx.x * 8 + (threadIdx.x >> 5);
    int lane = threadIdx.x & 31;
    const float* row = apw + (size_t)o * 2560 + 2048;
    float acc = 0.f;
    for (int i = lane; i < 512; i += 32) acc = fmaf(row[i], f4[i], acc);
#pragma unroll
    for (int off = 16; off; off >>= 1) acc += __shfl_xor_sync(0xffffffffu, acc, off);
    if (!lane) b4[o] = acc;
}

__global__ void agg_k(const float* __restrict__ att, const float* __restrict__ zup,
                      const float* __restrict__ c6b, float* __restrict__ out) {
    int p = blockIdx.x * 256 + threadIdx.x;
    if (p >= 4096) return;
    int y = p >> 6, x = p & 63;
    float acc[19];
#pragma unroll
    for (int o = 0; o < 19; o++) acc[o] = c6b[o];
#pragma unroll
    for (int a = 0; a < 3; a++)
#pragma unroll
        for (int b = 0; b < 3; b++) {
            int k = a * 3 + b;
            int iy = y + 2 * (a - 1), ix = x + 2 * (b - 1);
            if ((unsigned)iy < 64u && (unsigned)ix < 64u) {
                float w = att[k * 4096 + p];
                int n = iy * 64 + ix;
#pragma unroll
                for (int o = 0; o < 19; o++) acc[o] = fmaf(w, zup[o * 4096 + n], acc[o]);
            }
        }
#pragma unroll
    for (int o = 0; o < 19; o++) out[o * 4096 + p] = acc[o];
}

// ============================ host driver ============================
static float* g_part_p;

static void run_conv(int mt, const float* Wt, int Arow, int wstride, int wofs0, int centerOnly,
                     const float* X, float* Cout,
                     int M, int K, int H, int Wd, int d, int kch,
                     const float* sc, const float* bi, const float* eb, int flags) {
    int ntaps = (d > 0 && !centerOnly) ? 9 : 1;
    int HW = H * Wd;
    int Kc = K / kch;
    dim3 grid((HW + 63) / 64, (M + mt - 1) / mt, ntaps * kch);
    if (mt == 128)
        gemm2<128><<<grid, 256>>>(Wt, Arow, wstride, wofs0, centerOnly, X, g_part_p,
                                  M, Kc, kch, H, Wd, d);
    else
        gemm2<64><<<grid, 256>>>(Wt, Arow, wstride, wofs0, centerOnly, X, g_part_p,
                                 M, Kc, kch, H, Wd, d);
    int tot = M * HW;
    reduce_k<<<(tot + 255) / 256, 256>>>(g_part_p, Cout, M, H, Wd, d, centerOnly,
                                         ntaps, kch, flags, sc, bi, eb);
}

extern "C" void kernel_launch(void* const* d_in, const int* in_sizes, int n_in,
                              void* d_out, int out_size) {
    const float* c1 = (const float*)d_in[0];
    const float* c2 = (const float*)d_in[1];
    const float* x = (const float*)d_in[2];
    const float* rf1_w = (const float*)d_in[3];
    const float* rf1_s = (const float*)d_in[4];
    const float* rf1_b = (const float*)d_in[5];
    const float* rf2_w = (const float*)d_in[6];
    const float* rf2_s = (const float*)d_in[7];
    const float* rf2_b = (const float*)d_in[8];
    const float* r2_w = (const float*)d_in[9];
    const float* r2_s = (const float*)d_in[10];
    const float* r2_b = (const float*)d_in[11];
    const float* a0_w = (const float*)d_in[12];
    const float* a0_s = (const float*)d_in[13];
    const float* a0_b = (const float*)d_in[14];
    const float* a1_w = (const float*)d_in[15];
    const float* a1_s = (const float*)d_in[16];
    const float* a1_b = (const float*)d_in[17];
    const float* a2_w = (const float*)d_in[18];
    const float* a2_s = (const float*)d_in[19];
    const float* a2_b = (const float*)d_in[20];
    const float* a3_w = (const float*)d_in[21];
    const float* a3_s = (const float*)d_in[22];
    const float* a3_b = (const float*)d_in[23];
    const float* a4_w = (const float*)d_in[24];
    const float* a4_s = (const float*)d_in[25];
    const float* a4_b = (const float*)d_in[26];
    const float* ap_w = (const float*)d_in[27];
    const float* ap_s = (const float*)d_in[28];
    const float* ap_b = (const float*)d_in[29];
    const float* c6_w = (const float*)d_in[30];
    const float* c6_b = (const float*)d_in[31];

    float *t2, *c1r, *c2r, *att, *gap, *f4, *b4, *outb, *z, *zup;
    __half *whi, *xthi, *xtlo, *fhi, *flo, *c1thi, *c1tlo, *t1thi, *t1tlo;
    cudaGetSymbolAddress((void**)&g_part_p, g_part);
    cudaGetSymbolAddress((void**)&t2, g_t2);
    cudaGetSymbolAddress((void**)&c1r, g_c1r);
    cudaGetSymbolAddress((void**)&c2r, g_c2r);
    cudaGetSymbolAddress((void**)&att, g_att);
    cudaGetSymbolAddress((void**)&gap, g_gap);
    cudaGetSymbolAddress((void**)&f4, g_f4);
    cudaGetSymbolAddress((void**)&b4, g_b4);
    cudaGetSymbolAddress((void**)&outb, g_outb);
    cudaGetSymbolAddress((void**)&z, g_z);
    cudaGetSymbolAddress((void**)&zup, g_zup);
    cudaGetSymbolAddress((void**)&whi, g_whi);
    cudaGetSymbolAddress((void**)&xthi, g_xthi);
    cudaGetSymbolAddress((void**)&xtlo, g_xtlo);
    cudaGetSymbolAddress((void**)&fhi, g_fhi);
    cudaGetSymbolAddress((void**)&flo, g_flo);
    cudaGetSymbolAddress((void**)&c1thi, g_c1thi);
    cudaGetSymbolAddress((void**)&c1tlo, g_c1tlo);
    cudaGetSymbolAddress((void**)&t1thi, g_t1thi);
    cudaGetSymbolAddress((void**)&t1tlo, g_t1tlo);

    const int SMEM_H1 = 3 * 18432 * 2;   // 110592 B (single-pass, 3 stages)
    const int SMEM_H2 = 2 * 27648 * 2;   // 110592 B (2-pass, 2 stages)
    cudaFuncSetAttribute(hgemm<0>, cudaFuncAttributeMaxDynamicSharedMemorySize, SMEM_H1);
    cudaFuncSetAttribute(hgemm<1>, cudaFuncAttributeMaxDynamicSharedMemorySize, SMEM_H2);

    // --- conversions; launch #4 = a1 hgemm (ncu captures the 4th launch; control) ---
    xtrans_g<<<dim3(32, 128), 256>>>(x, xthi, xtlo, 1024, 4096);                       // 1
    wconv3x3<<<dim3(512, 8), 256>>>(a1_w, whi + S_A1);                                 // 2
    wconv3x3<<<dim3(512, 8), 256>>>(a2_w, whi + S_A2);                                 // 3
    hgemm<0><<<dim3(8, 4, 9), 256, SMEM_H1>>>(whi + S_A1, xthi, nullptr, g_part_p,
                                              4096, 4096, 4096, 1, 1, 12, 5, 1024, 1); // 4 <- profiled
    reduce_ht<<<dim3(32, 16), 256>>>(g_part_p, 9, 1, 512, 1024, a1_s, a1_b, fhi, flo, 2048, 512, 12, 5);
    // a2 k-split: 18 slices (9 taps x 2 k-chunks) -> fills the wave with working CTAs
    hgemm<0><<<dim3(8, 4, 18), 256, SMEM_H1>>>(whi + S_A2, xthi, nullptr, g_part_p,
                                               4096, 2048, 4096, 2, 1, 24, 5, 1024, 1);
    reduce_ht<<<dim3(32, 16), 256>>>(g_part_p, 18, 2, 512, 1024, a2_s, a2_b, fhi, flo, 2048, 1024, 24, 5);
    wconv1x1<<<(512 * 4096 / 4 + 255) / 256, 256>>>(a0_w, 4096, 4096, whi + S_A0, 512 * 1024);
    hgemm<0><<<dim3(8, 4, 8), 256, SMEM_H1>>>(whi + S_A0, xthi, nullptr, g_part_p,
                                              4096, 512, 4096, 8, 0, 0, 5, 1024, 0);
    reduce_ht<<<dim3(32, 16), 256>>>(g_part_p, 8, 8, 512, 1024, a0_s, a0_b, fhi, flo, 2048, 0, 0, 5);
    wcenter<<<(512 * 2048 + 255) / 256, 256>>>(a3_w, whi + S_A3);
    hgemm<0><<<dim3(8, 4, 8), 256, SMEM_H1>>>(whi + S_A3, xthi, nullptr, g_part_p,
                                              4096, 512, 4096, 8, 0, 0, 5, 1024, 0);
    reduce_ht<<<dim3(32, 16), 256>>>(g_part_p, 8, 8, 512, 1024, a3_s, a3_b, fhi, flo, 2048, 1536, 0, 5);

    // --- attention branch: refine convs on HMMA (2-pass for accuracy) ---
    xtrans_g<<<dim3(128, 8), 256>>>(c1, c1thi, c1tlo, 4096, 256);
    wrf_k<<<(64 * 256 * 9 + 255) / 256, 256>>>(rf1_w, whi + S_RF1, 64, 256);
    wrf_k<<<(64 * 64 * 9 + 255) / 256, 256>>>(rf2_w, whi + S_RF2, 64, 64);
    hgemm<1><<<dim3(32, 1, 9), 256, SMEM_H2>>>(whi + S_RF1, c1thi, c1tlo, g_part_p,
                                               256, 256, 256, 1, 1, 2, 6, 4096, 1);
    reduce_ht<<<dim3(128, 2), 256>>>(g_part_p, 9, 1, 128, 4096, rf1_s, rf1_b, t1thi, t1tlo, 64, 0, 2, 6);
    hgemm<1><<<dim3(32, 1, 9), 256, SMEM_H2>>>(whi + S_RF2, t1thi, t1tlo, g_part_p,
                                               64, 64, 64, 1, 1, 2, 6, 4096, 1);
    reduce_pl<<<(64 * 4096 + 255) / 256, 256>>>(g_part_p, c1r, 9, 1, 128, 4096, 64, 6,
                                                rf2_s, rf2_b, nullptr, 2, 6);
    run_conv(64, r2_w, 512, 1, 0, 1, c2, t2, 64, 512, 32, 32, 0, 4, r2_s, r2_b, nullptr, 2);
    resize_kk<<<(64 * 4096 + 255) / 256, 256>>>(t2, c2r, 64, 32, 32, 64, 64, 1);
    energy_k<<<16, 256>>>(c1r, c2r, att);

    // --- GAP branch + ap (2-pass: exact fcat via hi/lo) ---
    gap_k<<<512, 256>>>(x, gap);
    f4_k<<<64, 256>>>(a4_w, a4_s, a4_b, gap, f4);
    bias4_k<<<64, 256>>>(ap_w, f4, b4);
    wconv1x1<<<(512 * 2048 / 4 + 255) / 256, 256>>>(ap_w, 2560, 2048, whi + S_AP, 512 * 512);
    hgemm<1><<<dim3(8, 4, 8), 256, SMEM_H2>>>(whi + S_AP, fhi, flo, g_part_p,
                                              2048, 256, 2048, 8, 0, 0, 5, 1024, 0);
    reduce_pl<<<2048, 256>>>(g_part_p, outb, 8, 8, 512, 1024, 512, 2 | 4 | 8,
                             ap_s, ap_b, b4, 0, 5);

    // --- final head ---
    run_conv(64, c6_w, 512, 1, 0, 1, outb, z, 19, 512, 32, 32, 0, 4, nullptr, nullptr, nullptr, 0);
    resize_kk<<<(19 * 4096 + 255) / 256, 256>>>(z, zup, 19, 32, 32, 64, 64, 0);
    agg_k<<<16, 256>>>(att, zup, c6_b, (float*)d_out);
}

// round 15
// speedup vs baseline: 1.7602x; 1.0147x over previous
#include <cuda_runtime.h>
#include <cuda_fp16.h>
#include <math.h>
#include <stdint.h>

#define DEV_INLINE __device__ __forceinline__

DEV_INLINE unsigned long long pk2(float lo, float hi) {
    unsigned long long r;
    asm("mov.b64 %0, {%1, %2};" : "=l"(r) : "f"(lo), "f"(hi));
    return r;
}
DEV_INLINE void unpk2(unsigned long long v, float& lo, float& hi) {
    asm("mov.b64 {%0, %1}, %2;" : "=f"(lo), "=f"(hi) : "l"(v));
}
#define FFMA2(d, a, b) asm("fma.rn.f32x2 %0, %1, %2, %0;" : "+l"(d) : "l"(a), "l"(b))

DEV_INLINE void mma_f16(float* c, const uint32_t* a, const uint32_t* b) {
    asm volatile(
        "mma.sync.aligned.m16n8k16.row.col.f32.f16.f16.f32 "
        "{%0,%1,%2,%3}, {%4,%5,%6,%7}, {%8,%9}, {%0,%1,%2,%3};"
        : "+f"(c[0]), "+f"(c[1]), "+f"(c[2]), "+f"(c[3])
        : "r"(a[0]), "r"(a[1]), "r"(a[2]), "r"(a[3]), "r"(b[0]), "r"(b[1]));
}
DEV_INLINE void ldsm_x4(uint32_t& r0, uint32_t& r1, uint32_t& r2, uint32_t& r3, uint32_t a) {
    asm volatile("ldmatrix.sync.aligned.m8n8.x4.shared.b16 {%0,%1,%2,%3}, [%4];"
                 : "=r"(r0), "=r"(r1), "=r"(r2), "=r"(r3) : "r"(a));
}

#define CP_ASYNC_CG(dst, src, sz) \
    asm volatile("cp.async.cg.shared.global [%0], [%1], 16, %2;" \
                 :: "r"(dst), "l"(src), "r"(sz) : "memory")
#define CP_COMMIT() asm volatile("cp.async.commit_group;" ::: "memory")
#define CP_WAIT_N1() asm volatile("cp.async.wait_group 1;" ::: "memory")
#define CP_WAIT_N2() asm volatile("cp.async.wait_group 2;" ::: "memory")

// ============================ scratch ============================
__device__ float g_part[10 * 1024 * 1024];    // up to 18 slices x 512 x 1024
__device__ float g_t2[64 * 1024];
__device__ float g_c1r[64 * 4096];
__device__ float g_c2r[64 * 4096];
__device__ float g_att[9 * 4096];
__device__ float g_gap[4096];
__device__ float g_f4[512];
__device__ float g_b4[512];
__device__ float g_outb[512 * 1024];
__device__ float g_z[19 * 1024];
__device__ float g_zup[19 * 4096];
__device__ __align__(16) __half g_whi[43360256];
__device__ __align__(16) __half g_xthi[1024 * 4096];
__device__ __align__(16) __half g_fhi[1024 * 2048];
__device__ __align__(16) __half g_c1thi[4096 * 256];
__device__ __align__(16) __half g_c1tlo[4096 * 256];
__device__ __align__(16) __half g_t1thi[4096 * 64];
__device__ __align__(16) __half g_t1tlo[4096 * 64];

static const size_t S_A0 = 0;
static const size_t S_A1 = 2097152;
static const size_t S_A2 = 20971520;
static const size_t S_A3 = 39845888;
static const size_t S_AP = 41943040;
static const size_t S_RF1 = 42991616;
static const size_t S_RF2 = 43286528;

// ============================ HMMA GEMM (fp16, multi-stage cp.async + ldmatrix) ============================
// slice s = (tap, k-chunk): ti = s/kch, kc = s%kch. part[s][m][pix] = partial GEMM.
// CTA: 128(m) x 128(pix), 8 warps of 64x32. k-chunks of 64.
template <int USE_LO>
__global__ void __launch_bounds__(256, 2)
hgemm(const __half* __restrict__ Wh,
      const __half* __restrict__ Xhi, const __half* __restrict__ Xlo,
      float* __restrict__ part,
      int Ktot, int Kc, int Kx, int kch, int tapMode, int dil, int wshift, int HW, int skipEn)
{
    extern __shared__ __half sm[];
    constexpr int NSTAGE = USE_LO ? 2 : 3;
    const int STG = USE_LO ? 27648 : 18432;
    const uint32_t smB = (uint32_t)__cvta_generic_to_shared(sm);
    const uint32_t STGB = STG * 2;

    const int tid = threadIdx.x;
    const int wid = tid >> 5, lane = tid & 31;
    const int s = blockIdx.z;
    const int ti = s / kch;
    const int kc = s - ti * kch;
    const int m0 = blockIdx.y * 128;
    const int n0 = blockIdx.x * 128;
    const int Mpad = gridDim.y * 128;
    const int Wimg = 1 << wshift;

    int dy = 0, dx = 0;
    size_t wbase = 0;
    if (tapMode) {
        dy = (ti / 3 - 1) * dil;
        dx = (ti % 3 - 1) * dil;
        wbase = (size_t)ti * Mpad * Ktot;
        if (skipEn) {
            int tileRows = 128 >> wshift;
            int r0 = n0 >> wshift;
            if (r0 + tileRows - 1 + dy < 0 || r0 + dy >= Wimg) return;  // masked in reduce
        }
    }
    const int k0s = kc * Kc;

    const __half* gA[4];
    uint32_t sAo[4];
    const __half* gB[4];
    const __half* gBl[4];
    uint32_t sBo[4];
    int bsz[4];
#pragma unroll
    for (int i = 0; i < 4; i++) {
        int v = tid + 256 * i;
        int mr = v >> 3, ko = (v & 7) * 8;
        gA[i] = Wh + wbase + (size_t)(m0 + mr) * Ktot + k0s + ko;
        sAo[i] = (mr * 72 + ko) * 2;
        int nr = mr;
        int q = n0 + nr;
        int iy = (q >> wshift) + dy, ix = (q & (Wimg - 1)) + dx;
        bool ok = (unsigned)iy < (unsigned)Wimg && (unsigned)ix < (unsigned)Wimg;
        size_t gb = ok ? (size_t)((iy << wshift) + ix) * Kx + k0s + ko : 0;
        gB[i] = Xhi + gb;
        gBl[i] = USE_LO ? (Xlo + gb) : Xhi;
        bsz[i] = ok ? 16 : 0;
        sBo[i] = (nr * 72 + ko) * 2;
    }

    const int wm = (wid & 1) * 64;
    const int wn = (wid >> 1) * 32;

    uint32_t aOff[4], bOff[2];
#pragma unroll
    for (int im = 0; im < 4; im++)
        aOff[im] = ((wm + im * 16 + (lane & 15)) * 72 + (lane >> 4) * 8) * 2;
#pragma unroll
    for (int pi = 0; pi < 2; pi++)
        bOff[pi] = ((wn + pi * 16 + ((lane >> 4) & 1) * 8 + (lane & 7)) * 72 +
                    ((lane >> 3) & 1) * 8) * 2 + 18432;

    float acc[4][4][4];
#pragma unroll
    for (int i = 0; i < 4; i++)
#pragma unroll
        for (int j = 0; j < 4; j++)
#pragma unroll
            for (int q = 0; q < 4; q++) acc[i][j][q] = 0.f;

    const int nChunks = Kc / 64;

#define LOADCHUNK(sb)                                                            \
    do {                                                                         \
        _Pragma("unroll")                                                        \
        for (int i = 0; i < 4; i++) { CP_ASYNC_CG((sb) + sAo[i], gA[i], 16); gA[i] += 64; } \
        _Pragma("unroll")                                                        \
        for (int i = 0; i < 4; i++) {                                            \
            CP_ASYNC_CG((sb) + 18432 + sBo[i], gB[i], bsz[i]);                   \
            gB[i] += 64;                                                         \
            if (USE_LO) { CP_ASYNC_CG((sb) + 36864 + sBo[i], gBl[i], bsz[i]); gBl[i] += 64; } \
        }                                                                        \
    } while (0)

    {
        int npro = (NSTAGE - 1 < nChunks) ? NSTAGE - 1 : nChunks;
        for (int p = 0; p < npro; p++) {
            LOADCHUNK(smB + p * STGB);
            CP_COMMIT();
        }
        for (int p = npro; p < NSTAGE - 1; p++) CP_COMMIT();
    }

    for (int c = 0; c < nChunks; c++) {
        int pf = c + NSTAGE - 1;
        if (pf < nChunks) LOADCHUNK(smB + (pf % NSTAGE) * STGB);
        CP_COMMIT();
        if (USE_LO) CP_WAIT_N1(); else CP_WAIT_N2();
        __syncthreads();

        const uint32_t sbase = smB + (c % NSTAGE) * STGB;

#pragma unroll
        for (int kk = 0; kk < 64; kk += 16) {
            uint32_t af[4][4], bh[4][2];
#pragma unroll
            for (int im = 0; im < 4; im++)
                ldsm_x4(af[im][0], af[im][1], af[im][2], af[im][3],
                        sbase + aOff[im] + kk * 2);
#pragma unroll
            for (int pi = 0; pi < 2; pi++)
                ldsm_x4(bh[2 * pi][0], bh[2 * pi][1], bh[2 * pi + 1][0], bh[2 * pi + 1][1],
                        sbase + bOff[pi] + kk * 2);
#pragma unroll
            for (int im = 0; im < 4; im++)
#pragma unroll
                for (int in_ = 0; in_ < 4; in_++) mma_f16(acc[im][in_], af[im], bh[in_]);
            if (USE_LO) {
                uint32_t bl[4][2];
#pragma unroll
                for (int pi = 0; pi < 2; pi++)
                    ldsm_x4(bl[2 * pi][0], bl[2 * pi][1], bl[2 * pi + 1][0], bl[2 * pi + 1][1],
                            sbase + bOff[pi] + 18432 + kk * 2);
#pragma unroll
                for (int im = 0; im < 4; im++)
#pragma unroll
                    for (int in_ = 0; in_ < 4; in_++) mma_f16(acc[im][in_], af[im], bl[in_]);
            }
        }
        __syncthreads();
    }
#undef LOADCHUNK

    float* po = part + (size_t)s * Mpad * HW;
    const int r = lane >> 2;
    const int cp = (lane & 3) * 2;
    const int rbase = m0 + wm + r;
    const int cbase = n0 + wn + cp;
#pragma unroll
    for (int im = 0; im < 4; im++)
#pragma unroll
        for (int in_ = 0; in_ < 4; in_++) {
            int m = rbase + im * 16, n = cbase + in_ * 8;
            float2 v0 = make_float2(acc[im][in_][0], acc[im][in_][1]);
            float2 v1 = make_float2(acc[im][in_][2], acc[im][in_][3]);
            *(float2*)&po[(size_t)m * HW + n] = v0;
            *(float2*)&po[(size_t)(m + 8) * HW + n] = v1;
        }
}

// reduce slices + bn_relu, write TRANSPOSED fp16 hi (+ optional lo) (tap = s/kch)
__global__ void reduce_ht(const float* __restrict__ part, int S, int kch, int Mpad, int HW,
                          const float* __restrict__ sc, const float* __restrict__ bi,
                          __half* __restrict__ ohi, __half* __restrict__ olo,
                          int ostride, int colOff, int tapDil, int wshift)
{
    __shared__ float t[32][33];
    int tx = threadIdx.x & 31, ty = threadIdx.x >> 5;
    int q0 = blockIdx.x * 32, m0 = blockIdx.y * 32;
    int y = q0 >> wshift;
    int Wimg = 1 << wshift;
#pragma unroll
    for (int r = 0; r < 4; r++) {
        int ml = ty + 8 * r;
        int m = m0 + ml;
        float a = 0.f;
        for (int s = 0; s < S; s++) {
            if (tapDil) {
                int dy = ((s / kch) / 3 - 1) * tapDil;
                if ((unsigned)(y + dy) >= (unsigned)Wimg) continue;
            }
            a += part[(size_t)s * Mpad * HW + (size_t)m * HW + q0 + tx];
        }
        t[ml][tx] = fmaxf(sc[m] * a + bi[m], 0.f);
    }
    __syncthreads();
#pragma unroll
    for (int r = 0; r < 4; r++) {
        int ql = ty + 8 * r;
        float v = t[tx][ql];
        __half h = __float2half_rn(v);
        size_t o = (size_t)(q0 + ql) * ostride + colOff + m0 + tx;
        ohi[o] = h;
        if (olo) olo[o] = __float2half_rn(v - __half2float(h));
    }
}

// reduce slices + epilogue to plain fp32
__global__ void reduce_pl(const float* __restrict__ part, float* __restrict__ out,
                          int S, int kch, int Mpad, int HW, int Mtot, int flags,
                          const float* __restrict__ sc, const float* __restrict__ bi,
                          const float* __restrict__ eb, int tapDil, int wshift)
{
    int idx = blockIdx.x * 256 + threadIdx.x;
    if (idx >= Mtot * HW) return;
    int m = idx / HW;
    int p = idx - m * HW;
    int y = p >> wshift;
    int Wimg = 1 << wshift;
    float a = 0.f;
    for (int s = 0; s < S; s++) {
        if (tapDil) {
            int dy = ((s / kch) / 3 - 1) * tapDil;
            if ((unsigned)(y + dy) >= (unsigned)Wimg) continue;
        }
        a += part[(size_t)s * Mpad * HW + idx];
    }
    if (flags & 8) a += eb[m];
    if (flags & 2) a = sc[m] * a + bi[m];
    if (flags & 4) a = fmaxf(a, 0.f);
    out[idx] = a;
}

// ============================ conversion pre-passes ============================
__global__ void xtrans_g(const float* __restrict__ in,
                         __half* __restrict__ ohi, __half* __restrict__ olo,
                         int HW, int K) {
    __shared__ float t[32][33];
    int tx = threadIdx.x & 31, ty = threadIdx.x >> 5;
    int q0 = blockIdx.x * 32, k0 = blockIdx.y * 32;
#pragma unroll
    for (int r = 0; r < 4; r++)
        t[ty + 8 * r][tx] = in[(size_t)(k0 + ty + 8 * r) * HW + q0 + tx];
    __syncthreads();
#pragma unroll
    for (int r = 0; r < 4; r++) {
        int ql = ty + 8 * r;
        float v = t[tx][ql];
        __half h = __float2half_rn(v);
        size_t o = (size_t)(q0 + ql) * K + k0 + tx;
        ohi[o] = h;
        if (olo) olo[o] = __float2half_rn(v - __half2float(h));
    }
}

__global__ void wconv1x1(const float* __restrict__ in, int rowStride, int K,
                         __half* __restrict__ whi, int total4) {
    int i = blockIdx.x * 256 + threadIdx.x;
    if (i >= total4) return;
    int e = i * 4, m = e / K, k = e - m * K;
    float4 v = *(const float4*)(in + (size_t)m * rowStride + k);
    size_t o = (size_t)m * K + k;
    *(__half2*)(whi + o) = __floats2half2_rn(v.x, v.y);
    *(__half2*)(whi + o + 2) = __floats2half2_rn(v.z, v.w);
}

// both 3x3 weight tensors in one launch; vectorized 16B stores (8 k per thread)
__global__ void wconv3x3b(const float* __restrict__ inA, const float* __restrict__ inB,
                          __half* __restrict__ outA, __half* __restrict__ outB) {
    __shared__ float st[4608];
    int m = blockIdx.x, kb = blockIdx.y;
    const float* src = (blockIdx.z ? inB : inA) + (size_t)m * 36864 + (size_t)kb * 4608;
    __half* dst = blockIdx.z ? outB : outA;
    for (int i = threadIdx.x; i < 1152; i += 256)
        *(float4*)(st + 4 * i) = *(const float4*)(src + 4 * i);
    __syncthreads();
    for (int j = threadIdx.x; j < 576; j += 256) {
        int t = j / 64, k = (j & 63) * 8;
        __half2 h[4];
#pragma unroll
        for (int q = 0; q < 4; q++)
            h[q] = __floats2half2_rn(st[(k + 2 * q) * 9 + t], st[(k + 2 * q + 1) * 9 + t]);
        size_t o = ((size_t)t * 512 + m) * 4096 + kb * 512 + k;
        *(uint4*)(dst + o) = *(uint4*)h;
    }
}

__global__ void wcenter(const float* __restrict__ in, __half* __restrict__ whi) {
    int i = blockIdx.x * 256 + threadIdx.x;
    if (i >= 512 * 2048) return;
    int e = i * 2, m = e >> 12, k = e & 4095;
    const float* p = in + (size_t)m * 36864 + k * 9 + 4;
    *(__half2*)(whi + e) = __floats2half2_rn(p[0], p[9]);
}

__global__ void wrf_k(const float* __restrict__ in, __half* __restrict__ out, int M, int K) {
    int i = blockIdx.x * 256 + threadIdx.x;
    if (i >= M * K * 9) return;
    int m = i / (K * 9);
    int rem = i - m * K * 9;
    int k = rem / 9, t = rem - k * 9;
    out[((size_t)t * 128 + m) * K + k] = __float2half_rn(in[i]);
}

// ============================ FFMA2 path (r2, c6) ============================
DEV_INLINE void tap_rect(int ti, int d, int centerOnly, int H, int W,
                         int& dy, int& dx, int& y0, int& x0, int& rh, int& rw) {
    if (centerOnly || d == 0) { dy = dx = 0; y0 = x0 = 0; rh = H; rw = W; return; }
    dy = (ti / 3 - 1) * d;
    dx = (ti % 3 - 1) * d;
    y0 = dy < 0 ? -dy : 0;
    x0 = dx < 0 ? -dx : 0;
    rh = H - (dy < 0 ? -dy : dy);
    rw = W - (dx < 0 ? -dx : dx);
}

template <int MT>
__global__ void __launch_bounds__(256, 2)
gemm2(const float* __restrict__ W, int Arow, int wstride, int wofs0, int centerOnly,
      const float* __restrict__ X, float* __restrict__ part,
      int M, int Kc, int kch, int H, int Wd, int d)
{
    constexpr int NT = 64, KT = 16;
    constexpr int ROWS = MT / 16;
    __shared__ float sA[KT][MT + 4];
    __shared__ float sB[KT][NT + 4];

    const int tid = threadIdx.x;
    const int s = blockIdx.z;
    const int ti = s / kch;
    const int kc = s - ti * kch;
    int dy, dx, y0, x0, rh, rw;
    tap_rect(ti, d, centerOnly, H, Wd, dy, dx, y0, x0, rh, rw);
    const int rectN = rh * rw;
    const int HW = H * Wd;
    const int n0 = blockIdx.x * NT;
    if (n0 >= rectN) return;
    const int m0 = blockIdx.y * MT;
    const int wofs = centerOnly ? wofs0 : ti;
    const int kcS = kc * Kc;

    const int nB = tid & 63, kB = tid >> 6;
    bool bval = false;
    const float* pB[4];
    {
        int pofs = 0;
        int nn = n0 + nB;
        if (nn < rectN) {
            int yy = nn / rw, xx = nn - yy * rw;
            bval = true;
            pofs = (y0 + yy + dy) * Wd + (x0 + xx + dx);
        }
#pragma unroll
        for (int t = 0; t < 4; t++) pB[t] = X + (size_t)(kcS + kB + 4 * t) * HW + pofs;
    }
    const int kA = tid & 15, mA = tid >> 4;
    const float* pA[ROWS];
    bool aval[ROWS];
#pragma unroll
    for (int t = 0; t < ROWS; t++) {
        int mg = m0 + mA + 16 * t;
        aval[t] = (mg < M);
        pA[t] = W + (aval[t] ? ((size_t)mg * Arow + wofs + (size_t)(kcS + kA) * wstride) : 0);
    }

    unsigned long long acc[ROWS][2];
#pragma unroll
    for (int i = 0; i < ROWS; i++) { acc[i][0] = 0ull; acc[i][1] = 0ull; }

    float rA[ROWS], rB[4];
#pragma unroll
    for (int t = 0; t < ROWS; t++) { rA[t] = aval[t] ? __ldg(pA[t]) : 0.f; pA[t] += (size_t)KT * wstride; }
#pragma unroll
    for (int t = 0; t < 4; t++) { rB[t] = bval ? __ldg(pB[t]) : 0.f; pB[t] += (size_t)KT * HW; }

    const int tx = tid & 15, ty = tid >> 4;

    for (int k0 = 0; k0 < Kc; k0 += KT) {
#pragma unroll
        for (int t = 0; t < ROWS; t++) sA[kA][mA + 16 * t] = rA[t];
#pragma unroll
        for (int t = 0; t < 4; t++) sB[kB + 4 * t][nB] = rB[t];
        __syncthreads();
        if (k0 + KT < Kc) {
#pragma unroll
            for (int t = 0; t < ROWS; t++) { rA[t] = aval[t] ? __ldg(pA[t]) : 0.f; pA[t] += (size_t)KT * wstride; }
#pragma unroll
            for (int t = 0; t < 4; t++) { rB[t] = bval ? __ldg(pB[t]) : 0.f; pB[t] += (size_t)KT * HW; }
        }
#pragma unroll
        for (int kk = 0; kk < KT; kk++) {
            const unsigned long long* bp =
                reinterpret_cast<const unsigned long long*>(&sB[kk][tx * 4]);
            unsigned long long b0 = bp[0], b1 = bp[1];
            const float* ar = &sA[kk][ty * ROWS];
#pragma unroll
            for (int i = 0; i < ROWS; i++) {
                float a = ar[i];
                unsigned long long ap = pk2(a, a);
                FFMA2(acc[i][0], ap, b0);
                FFMA2(acc[i][1], ap, b1);
            }
        }
        __syncthreads();
    }

    float* po = part + (size_t)s * M * HW;
#pragma unroll
    for (int i = 0; i < ROWS; i++) {
        int m = m0 + ty * ROWS + i;
        if (m >= M) continue;
        float vals[4];
        unpk2(acc[i][0], vals[0], vals[1]);
        unpk2(acc[i][1], vals[2], vals[3]);
#pragma unroll
        for (int j = 0; j < 4; j++) {
            int n2 = n0 + tx * 4 + j;
            if (n2 >= rectN) continue;
            int yy = n2 / rw, xx = n2 - yy * rw;
            po[(size_t)m * HW + (y0 + yy) * Wd + (x0 + xx)] = vals[j];
        }
    }
}

__global__ void reduce_k(const float* __restrict__ part, float* __restrict__ out,
                         int M, int H, int W, int d, int centerOnly, int ntaps, int kch,
                         int flags, const float* __restrict__ sc,
                         const float* __restrict__ bi, const float* __restrict__ eb) {
    int HW = H * W;
    int idx = blockIdx.x * 256 + threadIdx.x;
    if (idx >= M * HW) return;
    int m = idx / HW;
    int p = idx - m * HW;
    int y = p / W, x = p - y * W;
    float acc = 0.f;
    for (int s = 0; s < ntaps * kch; s++) {
        int ti = s / kch;
        int dy, dx, y0, x0, rh, rw;
        tap_rect(ti, d, centerOnly, H, W, dy, dx, y0, x0, rh, rw);
        if (y >= y0 && y < y0 + rh && x >= x0 && x < x0 + rw)
            acc += part[(size_t)s * M * HW + idx];
    }
    if (flags & 8) acc += eb[m];
    if (flags & 2) acc = sc[m] * acc + bi[m];
    if (flags & 4) acc = fmaxf(acc, 0.f);
    out[idx] = acc;
}

// ============================ small kernels ============================
__global__ void resize_kk(const float* __restrict__ in, float* __restrict__ out,
                          int C, int Hi, int Wi, int Ho, int Wo, int dorelu) {
    int i = blockIdx.x * 256 + threadIdx.x;
    int total = C * Ho * Wo;
    if (i >= total) return;
    int ox = i % Wo;
    int t = i / Wo;
    int oy = t % Ho;
    int c = t / Ho;
    float ry = (Ho > 1) ? (float)(Hi - 1) / (float)(Ho - 1) : 0.f;
    float rx = (Wo > 1) ? (float)(Wi - 1) / (float)(Wo - 1) : 0.f;
    float tyf = oy * ry;
    int yl = (int)floorf(tyf);
    float fy = tyf - yl;
    int yh = min(yl + 1, Hi - 1);
    float txf = ox * rx;
    int xl = (int)floorf(txf);
    float fx = txf - xl;
    int xh = min(xl + 1, Wi - 1);
    const float* p = in + (size_t)c * Hi * Wi;
    float v00 = p[yl * Wi + xl], v01 = p[yl * Wi + xh];
    float v10 = p[yh * Wi + xl], v11 = p[yh * Wi + xh];
    float v = (v00 * (1.f - fy) + v10 * fy) * (1.f - fx) + (v01 * (1.f - fy) + v11 * fy) * fx;
    if (dorelu) v = fmaxf(v, 0.f);
    out[i] = v;
}

__global__ void energy_k(const float* __restrict__ c1r, const float* __restrict__ c2r,
                         float* __restrict__ att) {
    int p = blockIdx.x * 256 + threadIdx.x;
    if (p >= 4096) return;
    int y = p >> 6, x = p & 63;
    float e[9];
    int nidx[9];
    bool val[9];
#pragma unroll
    for (int a = 0; a < 3; a++)
#pragma unroll
        for (int b = 0; b < 3; b++) {
            int k = a * 3 + b;
            int iy = y + 2 * (a - 1), ix = x + 2 * (b - 1);
            val[k] = (unsigned)iy < 64u && (unsigned)ix < 64u;
            nidx[k] = val[k] ? (iy * 64 + ix) : 0;
            e[k] = 0.f;
        }
    for (int c = 0; c < 64; c++) {
        float v = c1r[c * 4096 + p];
        const float* row = c2r + c * 4096;
#pragma unroll
        for (int k = 0; k < 9; k++)
            if (val[k]) e[k] = fmaf(v, row[nidx[k]], e[k]);
    }
    float mx = e[0];
#pragma unroll
    for (int k = 1; k < 9; k++) mx = fmaxf(mx, e[k]);
    float sum = 0.f, ex[9];
#pragma unroll
    for (int k = 0; k < 9; k++) { ex[k] = expf(e[k] - mx); sum += ex[k]; }
    float inv = 1.f / sum;
#pragma unroll
    for (int k = 0; k < 9; k++) att[k * 4096 + p] = ex[k] * inv;
}

__global__ void gap_k(const float* __restrict__ x, float* __restrict__ gap) {
    int c = blockIdx.x * 8 + (threadIdx.x >> 5);
    int lane = threadIdx.x & 31;
    const float* p = x + (size_t)c * 1024;
    float s = 0.f;
    for (int i = lane; i < 1024; i += 32) s += p[i];
#pragma unroll
    for (int o = 16; o; o >>= 1) s += __shfl_xor_sync(0xffffffffu, s, o);
    if (!lane) gap[c] = s * (1.f / 1024.f);
}

__global__ void f4_k(const float* __restrict__ w, const float* __restrict__ s,
                     const float* __restrict__ b, const float* __restrict__ gap,
                     float* __restrict__ f4) {
    int o = blockIdx.x * 8 + (threadIdx.x >> 5);
    int lane = threadIdx.x & 31;
    const float* row = w + (size_t)o * 4096;
    float acc = 0.f;
    for (int i = lane; i < 4096; i += 32) acc = fmaf(row[i], gap[i], acc);
#pragma unroll
    for (int off = 16; off; off >>= 1) acc += __shfl_xor_sync(0xffffffffu, acc, off);
    if (!lane) f4[o] = fmaxf(s[o] * acc + b[o], 0.f);
}

__global__ void bias4_k(const float* __restrict__ apw, const float* __restrict__ f4,
                        float* __restrict__ b4) {
    int o = blockIdx.x * 8 + (threadIdx.x >> 5);
    int lane = threadIdx.x & 31;
    const float* row = apw + (size_t)o * 2560 + 2048;
    float acc = 0.f;
    for (int i = lane; i < 512; i += 32) acc = fmaf(row[i], f4[i], acc);
#pragma unroll
    for (int off = 16; off; off >>= 1) acc += __shfl_xor_sync(0xffffffffu, acc, off);
    if (!lane) b4[o] = acc;
}

__global__ void agg_k(const float* __restrict__ att, const float* __restrict__ zup,
                      const float* __restrict__ c6b, float* __restrict__ out) {
    int p = blockIdx.x * 256 + threadIdx.x;
    if (p >= 4096) return;
    int y = p >> 6, x = p & 63;
    float acc[19];
#pragma unroll
    for (int o = 0; o < 19; o++) acc[o] = c6b[o];
#pragma unroll
    for (int a = 0; a < 3; a++)
#pragma unroll
        for (int b = 0; b < 3; b++) {
            int k = a * 3 + b;
            int iy = y + 2 * (a - 1), ix = x + 2 * (b - 1);
            if ((unsigned)iy < 64u && (unsigned)ix < 64u) {
                float w = att[k * 4096 + p];
                int n = iy * 64 + ix;
#pragma unroll
                for (int o = 0; o < 19; o++) acc[o] = fmaf(w, zup[o * 4096 + n], acc[o]);
            }
        }
#pragma unroll
    for (int o = 0; o < 19; o++) out[o * 4096 + p] = acc[o];
}

// ============================ host driver ============================
static float* g_part_p;

static void run_conv(int mt, const float* Wt, int Arow, int wstride, int wofs0, int centerOnly,
                     const float* X, float* Cout,
                     int M, int K, int H, int Wd, int d, int kch,
                     const float* sc, const float* bi, const float* eb, int flags) {
    int ntaps = (d > 0 && !centerOnly) ? 9 : 1;
    int HW = H * Wd;
    int Kc = K / kch;
    dim3 grid((HW + 63) / 64, (M + mt - 1) / mt, ntaps * kch);
    if (mt == 128)
        gemm2<128><<<grid, 256>>>(Wt, Arow, wstride, wofs0, centerOnly, X, g_part_p,
                                  M, Kc, kch, H, Wd, d);
    else
        gemm2<64><<<grid, 256>>>(Wt, Arow, wstride, wofs0, centerOnly, X, g_part_p,
                                 M, Kc, kch, H, Wd, d);
    int tot = M * HW;
    reduce_k<<<(tot + 255) / 256, 256>>>(g_part_p, Cout, M, H, Wd, d, centerOnly,
                                         ntaps, kch, flags, sc, bi, eb);
}

extern "C" void kernel_launch(void* const* d_in, const int* in_sizes, int n_in,
                              void* d_out, int out_size) {
    const float* c1 = (const float*)d_in[0];
    const float* c2 = (const float*)d_in[1];
    const float* x = (const float*)d_in[2];
    const float* rf1_w = (const float*)d_in[3];
    const float* rf1_s = (const float*)d_in[4];
    const float* rf1_b = (const float*)d_in[5];
    const float* rf2_w = (const float*)d_in[6];
    const float* rf2_s = (const float*)d_in[7];
    const float* rf2_b = (const float*)d_in[8];
    const float* r2_w = (const float*)d_in[9];
    const float* r2_s = (const float*)d_in[10];
    const float* r2_b = (const float*)d_in[11];
    const float* a0_w = (const float*)d_in[12];
    const float* a0_s = (const float*)d_in[13];
    const float* a0_b = (const float*)d_in[14];
    const float* a1_w = (const float*)d_in[15];
    const float* a1_s = (const float*)d_in[16];
    const float* a1_b = (const float*)d_in[17];
    const float* a2_w = (const float*)d_in[18];
    const float* a2_s = (const float*)d_in[19];
    const float* a2_b = (const float*)d_in[20];
    const float* a3_w = (const float*)d_in[21];
    const float* a3_s = (const float*)d_in[22];
    const float* a3_b = (const float*)d_in[23];
    const float* a4_w = (const float*)d_in[24];
    const float* a4_s = (const float*)d_in[25];
    const float* a4_b = (const float*)d_in[26];
    const float* ap_w = (const float*)d_in[27];
    const float* ap_s = (const float*)d_in[28];
    const float* ap_b = (const float*)d_in[29];
    const float* c6_w = (const float*)d_in[30];
    const float* c6_b = (const float*)d_in[31];

    float *t2, *c1r, *c2r, *att, *gap, *f4, *b4, *outb, *z, *zup;
    __half *whi, *xthi, *fhi, *c1thi, *c1tlo, *t1thi, *t1tlo;
    cudaGetSymbolAddress((void**)&g_part_p, g_part);
    cudaGetSymbolAddress((void**)&t2, g_t2);
    cudaGetSymbolAddress((void**)&c1r, g_c1r);
    cudaGetSymbolAddress((void**)&c2r, g_c2r);
    cudaGetSymbolAddress((void**)&att, g_att);
    cudaGetSymbolAddress((void**)&gap, g_gap);
    cudaGetSymbolAddress((void**)&f4, g_f4);
    cudaGetSymbolAddress((void**)&b4, g_b4);
    cudaGetSymbolAddress((void**)&outb, g_outb);
    cudaGetSymbolAddress((void**)&z, g_z);
    cudaGetSymbolAddress((void**)&zup, g_zup);
    cudaGetSymbolAddress((void**)&whi, g_whi);
    cudaGetSymbolAddress((void**)&xthi, g_xthi);
    cudaGetSymbolAddress((void**)&fhi, g_fhi);
    cudaGetSymbolAddress((void**)&c1thi, g_c1thi);
    cudaGetSymbolAddress((void**)&c1tlo, g_c1tlo);
    cudaGetSymbolAddress((void**)&t1thi, g_t1thi);
    cudaGetSymbolAddress((void**)&t1tlo, g_t1tlo);

    const int SMEM_H1 = 3 * 18432 * 2;   // 110592 B (single-pass, 3 stages)
    const int SMEM_H2 = 2 * 27648 * 2;   // 110592 B (2-pass, 2 stages)
    cudaFuncSetAttribute(hgemm<0>, cudaFuncAttributeMaxDynamicSharedMemorySize, SMEM_H1);
    cudaFuncSetAttribute(hgemm<1>, cudaFuncAttributeMaxDynamicSharedMemorySize, SMEM_H2);

    // --- conversions; launch #4 = a1 hgemm (profiled) ---
    xtrans_g<<<dim3(32, 128), 256>>>(x, xthi, nullptr, 1024, 4096);                    // 1
    wconv3x3b<<<dim3(512, 8, 2), 256>>>(a1_w, a2_w, whi + S_A1, whi + S_A2);           // 2
    wconv1x1<<<(512 * 4096 / 4 + 255) / 256, 256>>>(a0_w, 4096, 4096, whi + S_A0, 512 * 1024); // 3
    // a1 k-split (work-stealing smoothing past the one-wave quantization)
    hgemm<0><<<dim3(8, 4, 18), 256, SMEM_H1>>>(whi + S_A1, xthi, nullptr, g_part_p,
                                               4096, 2048, 4096, 2, 1, 12, 5, 1024, 1); // 4 <- profiled
    reduce_ht<<<dim3(32, 16), 256>>>(g_part_p, 18, 2, 512, 1024, a1_s, a1_b, fhi, nullptr, 2048, 512, 12, 5);
    hgemm<0><<<dim3(8, 4, 18), 256, SMEM_H1>>>(whi + S_A2, xthi, nullptr, g_part_p,
                                               4096, 2048, 4096, 2, 1, 24, 5, 1024, 1);
    reduce_ht<<<dim3(32, 16), 256>>>(g_part_p, 18, 2, 512, 1024, a2_s, a2_b, fhi, nullptr, 2048, 1024, 24, 5);
    hgemm<0><<<dim3(8, 4, 8), 256, SMEM_H1>>>(whi + S_A0, xthi, nullptr, g_part_p,
                                              4096, 512, 4096, 8, 0, 0, 5, 1024, 0);
    reduce_ht<<<dim3(32, 16), 256>>>(g_part_p, 8, 8, 512, 1024, a0_s, a0_b, fhi, nullptr, 2048, 0, 0, 5);
    wcenter<<<(512 * 2048 + 255) / 256, 256>>>(a3_w, whi + S_A3);
    hgemm<0><<<dim3(8, 4, 8), 256, SMEM_H1>>>(whi + S_A3, xthi, nullptr, g_part_p,
                                              4096, 512, 4096, 8, 0, 0, 5, 1024, 0);
    reduce_ht<<<dim3(32, 16), 256>>>(g_part_p, 8, 8, 512, 1024, a3_s, a3_b, fhi, nullptr, 2048, 1536, 0, 5);

    // --- attention branch: refine convs on HMMA (2-pass for accuracy) ---
    xtrans_g<<<dim3(128, 8), 256>>>(c1, c1thi, c1tlo, 4096, 256);
    wrf_k<<<(64 * 256 * 9 + 255) / 256, 256>>>(rf1_w, whi + S_RF1, 64, 256);
    wrf_k<<<(64 * 64 * 9 + 255) / 256, 256>>>(rf2_w, whi + S_RF2, 64, 64);
    hgemm<1><<<dim3(32, 1, 9), 256, SMEM_H2>>>(whi + S_RF1, c1thi, c1tlo, g_part_p,
                                               256, 256, 256, 1, 1, 2, 6, 4096, 1);
    reduce_ht<<<dim3(128, 2), 256>>>(g_part_p, 9, 1, 128, 4096, rf1_s, rf1_b, t1thi, t1tlo, 64, 0, 2, 6);
    hgemm<1><<<dim3(32, 1, 9), 256, SMEM_H2>>>(whi + S_RF2, t1thi, t1tlo, g_part_p,
                                               64, 64, 64, 1, 1, 2, 6, 4096, 1);
    reduce_pl<<<(64 * 4096 + 255) / 256, 256>>>(g_part_p, c1r, 9, 1, 128, 4096, 64, 6,
                                                rf2_s, rf2_b, nullptr, 2, 6);
    run_conv(64, r2_w, 512, 1, 0, 1, c2, t2, 64, 512, 32, 32, 0, 4, r2_s, r2_b, nullptr, 2);
    resize_kk<<<(64 * 4096 + 255) / 256, 256>>>(t2, c2r, 64, 32, 32, 64, 64, 1);
    energy_k<<<16, 256>>>(c1r, c2r, att);

    // --- GAP branch + ap (single-pass now) ---
    gap_k<<<512, 256>>>(x, gap);
    f4_k<<<64, 256>>>(a4_w, a4_s, a4_b, gap, f4);
    bias4_k<<<64, 256>>>(ap_w, f4, b4);
    wconv1x1<<<(512 * 2048 / 4 + 255) / 256, 256>>>(ap_w, 2560, 2048, whi + S_AP, 512 * 512);
    hgemm<0><<<dim3(8, 4, 8), 256, SMEM_H1>>>(whi + S_AP, fhi, nullptr, g_part_p,
                                              2048, 256, 2048, 8, 0, 0, 5, 1024, 0);
    reduce_pl<<<2048, 256>>>(g_part_p, outb, 8, 8, 512, 1024, 512, 2 | 4 | 8,
                             ap_s, ap_b, b4, 0, 5);

    // --- final head ---
    run_conv(64, c6_w, 512, 1, 0, 1, outb, z, 19, 512, 32, 32, 0, 4, nullptr, nullptr, nullptr, 0);
    resize_kk<<<(19 * 4096 + 255) / 256, 256>>>(z, zup, 19, 32, 32, 64, 64, 0);
    agg_k<<<16, 256>>>(att, zup, c6_b, (float*)d_out);
}

// round 16
// speedup vs baseline: 1.8175x; 1.0326x over previous
#include <cuda_runtime.h>
#include <cuda_fp16.h>
#include <math.h>
#include <stdint.h>

#define DEV_INLINE __device__ __forceinline__

DEV_INLINE unsigned long long pk2(float lo, float hi) {
    unsigned long long r;
    asm("mov.b64 %0, {%1, %2};" : "=l"(r) : "f"(lo), "f"(hi));
    return r;
}
DEV_INLINE void unpk2(unsigned long long v, float& lo, float& hi) {
    asm("mov.b64 {%0, %1}, %2;" : "=f"(lo), "=f"(hi) : "l"(v));
}
#define FFMA2(d, a, b) asm("fma.rn.f32x2 %0, %1, %2, %0;" : "+l"(d) : "l"(a), "l"(b))

DEV_INLINE void mma_f16(float* c, const uint32_t* a, const uint32_t* b) {
    asm volatile(
        "mma.sync.aligned.m16n8k16.row.col.f32.f16.f16.f32 "
        "{%0,%1,%2,%3}, {%4,%5,%6,%7}, {%8,%9}, {%0,%1,%2,%3};"
        : "+f"(c[0]), "+f"(c[1]), "+f"(c[2]), "+f"(c[3])
        : "r"(a[0]), "r"(a[1]), "r"(a[2]), "r"(a[3]), "r"(b[0]), "r"(b[1]));
}
DEV_INLINE void ldsm_x4(uint32_t& r0, uint32_t& r1, uint32_t& r2, uint32_t& r3, uint32_t a) {
    asm volatile("ldmatrix.sync.aligned.m8n8.x4.shared.b16 {%0,%1,%2,%3}, [%4];"
                 : "=r"(r0), "=r"(r1), "=r"(r2), "=r"(r3) : "r"(a));
}

#define CP_ASYNC_CG(dst, src, sz) \
    asm volatile("cp.async.cg.shared.global [%0], [%1], 16, %2;" \
                 :: "r"(dst), "l"(src), "r"(sz) : "memory")
#define CP_COMMIT() asm volatile("cp.async.commit_group;" ::: "memory")
#define CP_WAIT_N1() asm volatile("cp.async.wait_group 1;" ::: "memory")
#define CP_WAIT_N2() asm volatile("cp.async.wait_group 2;" ::: "memory")

// ============================ scratch ============================
__device__ float g_part[2 * 1024 * 1024];     // single accumulation slice (zeroed per layer)
__device__ float g_part2[5 * 1024 * 1024];    // slices for FFMA2 path (r2, c6)
__device__ float g_t2[64 * 1024];
__device__ float g_c1r[64 * 4096];
__device__ float g_c2r[64 * 4096];
__device__ float g_att[9 * 4096];
__device__ float g_gap[4096];
__device__ float g_f4[512];
__device__ float g_b4[512];
__device__ float g_outb[512 * 1024];
__device__ float g_z[19 * 1024];
__device__ float g_zup[19 * 4096];
__device__ __align__(16) __half g_whi[43360256];
__device__ __align__(16) __half g_xthi[1024 * 4096];
__device__ __align__(16) __half g_fhi[1024 * 2048];
__device__ __align__(16) __half g_c1thi[4096 * 256];
__device__ __align__(16) __half g_c1tlo[4096 * 256];
__device__ __align__(16) __half g_t1thi[4096 * 64];
__device__ __align__(16) __half g_t1tlo[4096 * 64];

static const size_t S_A0 = 0;
static const size_t S_A1 = 2097152;
static const size_t S_A2 = 20971520;
static const size_t S_A3 = 39845888;
static const size_t S_AP = 41943040;
static const size_t S_RF1 = 42991616;
static const size_t S_RF2 = 43286528;

// ============================ HMMA GEMM (fp16, cp.async + ldmatrix, RED accumulate) ===========
// slice s = (tap, k-chunk) divides work; ALL slices atomically accumulate into part[0]
// (buffer zeroed before launch). CTA: 128(m) x 128(pix), 8 warps of 64x32, k-chunks of 64.
template <int USE_LO>
__global__ void __launch_bounds__(256, 2)
hgemm(const __half* __restrict__ Wh,
      const __half* __restrict__ Xhi, const __half* __restrict__ Xlo,
      float* __restrict__ part,
      int Ktot, int Kc, int Kx, int kch, int tapMode, int dil, int wshift, int HW, int skipEn)
{
    extern __shared__ __half sm[];
    constexpr int NSTAGE = USE_LO ? 2 : 3;
    const int STG = USE_LO ? 27648 : 18432;
    const uint32_t smB = (uint32_t)__cvta_generic_to_shared(sm);
    const uint32_t STGB = STG * 2;

    const int tid = threadIdx.x;
    const int wid = tid >> 5, lane = tid & 31;
    const int s = blockIdx.z;
    const int ti = s / kch;
    const int kc = s - ti * kch;
    const int m0 = blockIdx.y * 128;
    const int n0 = blockIdx.x * 128;
    const int Mpad = gridDim.y * 128;
    const int Wimg = 1 << wshift;

    int dy = 0, dx = 0;
    size_t wbase = 0;
    if (tapMode) {
        dy = (ti / 3 - 1) * dil;
        dx = (ti % 3 - 1) * dil;
        wbase = (size_t)ti * Mpad * Ktot;
        if (skipEn) {
            int tileRows = 128 >> wshift;
            int r0 = n0 >> wshift;
            if (r0 + tileRows - 1 + dy < 0 || r0 + dy >= Wimg) return;  // zero contribution
        }
    }
    const int k0s = kc * Kc;

    const __half* gA[4];
    uint32_t sAo[4];
    const __half* gB[4];
    const __half* gBl[4];
    uint32_t sBo[4];
    int bsz[4];
#pragma unroll
    for (int i = 0; i < 4; i++) {
        int v = tid + 256 * i;
        int mr = v >> 3, ko = (v & 7) * 8;
        gA[i] = Wh + wbase + (size_t)(m0 + mr) * Ktot + k0s + ko;
        sAo[i] = (mr * 72 + ko) * 2;
        int nr = mr;
        int q = n0 + nr;
        int iy = (q >> wshift) + dy, ix = (q & (Wimg - 1)) + dx;
        bool ok = (unsigned)iy < (unsigned)Wimg && (unsigned)ix < (unsigned)Wimg;
        size_t gb = ok ? (size_t)((iy << wshift) + ix) * Kx + k0s + ko : 0;
        gB[i] = Xhi + gb;
        gBl[i] = USE_LO ? (Xlo + gb) : Xhi;
        bsz[i] = ok ? 16 : 0;
        sBo[i] = (nr * 72 + ko) * 2;
    }

    const int wm = (wid & 1) * 64;
    const int wn = (wid >> 1) * 32;

    uint32_t aOff[4], bOff[2];
#pragma unroll
    for (int im = 0; im < 4; im++)
        aOff[im] = ((wm + im * 16 + (lane & 15)) * 72 + (lane >> 4) * 8) * 2;
#pragma unroll
    for (int pi = 0; pi < 2; pi++)
        bOff[pi] = ((wn + pi * 16 + ((lane >> 4) & 1) * 8 + (lane & 7)) * 72 +
                    ((lane >> 3) & 1) * 8) * 2 + 18432;

    float acc[4][4][4];
#pragma unroll
    for (int i = 0; i < 4; i++)
#pragma unroll
        for (int j = 0; j < 4; j++)
#pragma unroll
            for (int q = 0; q < 4; q++) acc[i][j][q] = 0.f;

    const int nChunks = Kc / 64;

#define LOADCHUNK(sb)                                                            \
    do {                                                                         \
        _Pragma("unroll")                                                        \
        for (int i = 0; i < 4; i++) { CP_ASYNC_CG((sb) + sAo[i], gA[i], 16); gA[i] += 64; } \
        _Pragma("unroll")                                                        \
        for (int i = 0; i < 4; i++) {                                            \
            CP_ASYNC_CG((sb) + 18432 + sBo[i], gB[i], bsz[i]);                   \
            gB[i] += 64;                                                         \
            if (USE_LO) { CP_ASYNC_CG((sb) + 36864 + sBo[i], gBl[i], bsz[i]); gBl[i] += 64; } \
        }                                                                        \
    } while (0)

    {
        int npro = (NSTAGE - 1 < nChunks) ? NSTAGE - 1 : nChunks;
        for (int p = 0; p < npro; p++) {
            LOADCHUNK(smB + p * STGB);
            CP_COMMIT();
        }
        for (int p = npro; p < NSTAGE - 1; p++) CP_COMMIT();
    }

    for (int c = 0; c < nChunks; c++) {
        int pf = c + NSTAGE - 1;
        if (pf < nChunks) LOADCHUNK(smB + (pf % NSTAGE) * STGB);
        CP_COMMIT();
        if (USE_LO) CP_WAIT_N1(); else CP_WAIT_N2();
        __syncthreads();

        const uint32_t sbase = smB + (c % NSTAGE) * STGB;

#pragma unroll
        for (int kk = 0; kk < 64; kk += 16) {
            uint32_t af[4][4], bh[4][2];
#pragma unroll
            for (int im = 0; im < 4; im++)
                ldsm_x4(af[im][0], af[im][1], af[im][2], af[im][3],
                        sbase + aOff[im] + kk * 2);
#pragma unroll
            for (int pi = 0; pi < 2; pi++)
                ldsm_x4(bh[2 * pi][0], bh[2 * pi][1], bh[2 * pi + 1][0], bh[2 * pi + 1][1],
                        sbase + bOff[pi] + kk * 2);
#pragma unroll
            for (int im = 0; im < 4; im++)
#pragma unroll
                for (int in_ = 0; in_ < 4; in_++) mma_f16(acc[im][in_], af[im], bh[in_]);
            if (USE_LO) {
                uint32_t bl[4][2];
#pragma unroll
                for (int pi = 0; pi < 2; pi++)
                    ldsm_x4(bl[2 * pi][0], bl[2 * pi][1], bl[2 * pi + 1][0], bl[2 * pi + 1][1],
                            sbase + bOff[pi] + 18432 + kk * 2);
#pragma unroll
                for (int im = 0; im < 4; im++)
#pragma unroll
                    for (int in_ = 0; in_ < 4; in_++) mma_f16(acc[im][in_], af[im], bl[in_]);
            }
        }
        __syncthreads();
    }
#undef LOADCHUNK

    // epilogue: RED-accumulate into single slice (no return -> REDG)
    const int r = lane >> 2;
    const int cp = (lane & 3) * 2;
    const int rbase = m0 + wm + r;
    const int cbase = n0 + wn + cp;
#pragma unroll
    for (int im = 0; im < 4; im++)
#pragma unroll
        for (int in_ = 0; in_ < 4; in_++) {
            int m = rbase + im * 16, n = cbase + in_ * 8;
            atomicAdd(&part[(size_t)m * HW + n], acc[im][in_][0]);
            atomicAdd(&part[(size_t)m * HW + n + 1], acc[im][in_][1]);
            atomicAdd(&part[(size_t)(m + 8) * HW + n], acc[im][in_][2]);
            atomicAdd(&part[(size_t)(m + 8) * HW + n + 1], acc[im][in_][3]);
        }
}

// bn_relu + TRANSPOSED fp16 hi (+ optional lo) from the single accumulated slice
__global__ void reduce_ht(const float* __restrict__ part, int HW,
                          const float* __restrict__ sc, const float* __restrict__ bi,
                          __half* __restrict__ ohi, __half* __restrict__ olo,
                          int ostride, int colOff)
{
    __shared__ float t[32][33];
    int tx = threadIdx.x & 31, ty = threadIdx.x >> 5;
    int q0 = blockIdx.x * 32, m0 = blockIdx.y * 32;
#pragma unroll
    for (int r = 0; r < 4; r++) {
        int ml = ty + 8 * r;
        int m = m0 + ml;
        float a = part[(size_t)m * HW + q0 + tx];
        t[ml][tx] = fmaxf(sc[m] * a + bi[m], 0.f);
    }
    __syncthreads();
#pragma unroll
    for (int r = 0; r < 4; r++) {
        int ql = ty + 8 * r;
        float v = t[tx][ql];
        __half h = __float2half_rn(v);
        size_t o = (size_t)(q0 + ql) * ostride + colOff + m0 + tx;
        ohi[o] = h;
        if (olo) olo[o] = __float2half_rn(v - __half2float(h));
    }
}

// epilogue to plain fp32 from the single accumulated slice
__global__ void reduce_pl(const float* __restrict__ part, float* __restrict__ out,
                          int HW, int Mtot, int flags,
                          const float* __restrict__ sc, const float* __restrict__ bi,
                          const float* __restrict__ eb)
{
    int idx = blockIdx.x * 256 + threadIdx.x;
    if (idx >= Mtot * HW) return;
    int m = idx / HW;
    float a = part[idx];
    if (flags & 8) a += eb[m];
    if (flags & 2) a = sc[m] * a + bi[m];
    if (flags & 4) a = fmaxf(a, 0.f);
    out[idx] = a;
}

// ============================ conversion pre-passes ============================
__global__ void xtrans_g(const float* __restrict__ in,
                         __half* __restrict__ ohi, __half* __restrict__ olo,
                         int HW, int K) {
    __shared__ float t[32][33];
    int tx = threadIdx.x & 31, ty = threadIdx.x >> 5;
    int q0 = blockIdx.x * 32, k0 = blockIdx.y * 32;
#pragma unroll
    for (int r = 0; r < 4; r++)
        t[ty + 8 * r][tx] = in[(size_t)(k0 + ty + 8 * r) * HW + q0 + tx];
    __syncthreads();
#pragma unroll
    for (int r = 0; r < 4; r++) {
        int ql = ty + 8 * r;
        float v = t[tx][ql];
        __half h = __float2half_rn(v);
        size_t o = (size_t)(q0 + ql) * K + k0 + tx;
        ohi[o] = h;
        if (olo) olo[o] = __float2half_rn(v - __half2float(h));
    }
}

__global__ void wconv1x1(const float* __restrict__ in, int rowStride, int K,
                         __half* __restrict__ whi, int total4) {
    int i = blockIdx.x * 256 + threadIdx.x;
    if (i >= total4) return;
    int e = i * 4, m = e / K, k = e - m * K;
    float4 v = *(const float4*)(in + (size_t)m * rowStride + k);
    size_t o = (size_t)m * K + k;
    *(__half2*)(whi + o) = __floats2half2_rn(v.x, v.y);
    *(__half2*)(whi + o + 2) = __floats2half2_rn(v.z, v.w);
}

__global__ void wconv3x3b(const float* __restrict__ inA, const float* __restrict__ inB,
                          __half* __restrict__ outA, __half* __restrict__ outB) {
    __shared__ float st[4608];
    int m = blockIdx.x, kb = blockIdx.y;
    const float* src = (blockIdx.z ? inB : inA) + (size_t)m * 36864 + (size_t)kb * 4608;
    __half* dst = blockIdx.z ? outB : outA;
    for (int i = threadIdx.x; i < 1152; i += 256)
        *(float4*)(st + 4 * i) = *(const float4*)(src + 4 * i);
    __syncthreads();
    for (int j = threadIdx.x; j < 576; j += 256) {
        int t = j / 64, k = (j & 63) * 8;
        __half2 h[4];
#pragma unroll
        for (int q = 0; q < 4; q++)
            h[q] = __floats2half2_rn(st[(k + 2 * q) * 9 + t], st[(k + 2 * q + 1) * 9 + t]);
        size_t o = ((size_t)t * 512 + m) * 4096 + kb * 512 + k;
        *(uint4*)(dst + o) = *(uint4*)h;
    }
}

__global__ void wcenter(const float* __restrict__ in, __half* __restrict__ whi) {
    int i = blockIdx.x * 256 + threadIdx.x;
    if (i >= 512 * 2048) return;
    int e = i * 2, m = e >> 12, k = e & 4095;
    const float* p = in + (size_t)m * 36864 + k * 9 + 4;
    *(__half2*)(whi + e) = __floats2half2_rn(p[0], p[9]);
}

__global__ void wrf_k(const float* __restrict__ in, __half* __restrict__ out, int M, int K) {
    int i = blockIdx.x * 256 + threadIdx.x;
    if (i >= M * K * 9) return;
    int m = i / (K * 9);
    int rem = i - m * K * 9;
    int k = rem / 9, t = rem - k * 9;
    out[((size_t)t * 128 + m) * K + k] = __float2half_rn(in[i]);
}

// ============================ FFMA2 path (r2, c6) ============================
DEV_INLINE void tap_rect(int ti, int d, int centerOnly, int H, int W,
                         int& dy, int& dx, int& y0, int& x0, int& rh, int& rw) {
    if (centerOnly || d == 0) { dy = dx = 0; y0 = x0 = 0; rh = H; rw = W; return; }
    dy = (ti / 3 - 1) * d;
    dx = (ti % 3 - 1) * d;
    y0 = dy < 0 ? -dy : 0;
    x0 = dx < 0 ? -dx : 0;
    rh = H - (dy < 0 ? -dy : dy);
    rw = W - (dx < 0 ? -dx : dx);
}

template <int MT>
__global__ void __launch_bounds__(256, 2)
gemm2(const float* __restrict__ W, int Arow, int wstride, int wofs0, int centerOnly,
      const float* __restrict__ X, float* __restrict__ part,
      int M, int Kc, int kch, int H, int Wd, int d)
{
    constexpr int NT = 64, KT = 16;
    constexpr int ROWS = MT / 16;
    __shared__ float sA[KT][MT + 4];
    __shared__ float sB[KT][NT + 4];

    const int tid = threadIdx.x;
    const int s = blockIdx.z;
    const int ti = s / kch;
    const int kc = s - ti * kch;
    int dy, dx, y0, x0, rh, rw;
    tap_rect(ti, d, centerOnly, H, Wd, dy, dx, y0, x0, rh, rw);
    const int rectN = rh * rw;
    const int HW = H * Wd;
    const int n0 = blockIdx.x * NT;
    if (n0 >= rectN) return;
    const int m0 = blockIdx.y * MT;
    const int wofs = centerOnly ? wofs0 : ti;
    const int kcS = kc * Kc;

    const int nB = tid & 63, kB = tid >> 6;
    bool bval = false;
    const float* pB[4];
    {
        int pofs = 0;
        int nn = n0 + nB;
        if (nn < rectN) {
            int yy = nn / rw, xx = nn - yy * rw;
            bval = true;
            pofs = (y0 + yy + dy) * Wd + (x0 + xx + dx);
        }
#pragma unroll
        for (int t = 0; t < 4; t++) pB[t] = X + (size_t)(kcS + kB + 4 * t) * HW + pofs;
    }
    const int kA = tid & 15, mA = tid >> 4;
    const float* pA[ROWS];
    bool aval[ROWS];
#pragma unroll
    for (int t = 0; t < ROWS; t++) {
        int mg = m0 + mA + 16 * t;
        aval[t] = (mg < M);
        pA[t] = W + (aval[t] ? ((size_t)mg * Arow + wofs + (size_t)(kcS + kA) * wstride) : 0);
    }

    unsigned long long acc[ROWS][2];
#pragma unroll
    for (int i = 0; i < ROWS; i++) { acc[i][0] = 0ull; acc[i][1] = 0ull; }

    float rA[ROWS], rB[4];
#pragma unroll
    for (int t = 0; t < ROWS; t++) { rA[t] = aval[t] ? __ldg(pA[t]) : 0.f; pA[t] += (size_t)KT * wstride; }
#pragma unroll
    for (int t = 0; t < 4; t++) { rB[t] = bval ? __ldg(pB[t]) : 0.f; pB[t] += (size_t)KT * HW; }

    const int tx = tid & 15, ty = tid >> 4;

    for (int k0 = 0; k0 < Kc; k0 += KT) {
#pragma unroll
        for (int t = 0; t < ROWS; t++) sA[kA][mA + 16 * t] = rA[t];
#pragma unroll
        for (int t = 0; t < 4; t++) sB[kB + 4 * t][nB] = rB[t];
        __syncthreads();
        if (k0 + KT < Kc) {
#pragma unroll
            for (int t = 0; t < ROWS; t++) { rA[t] = aval[t] ? __ldg(pA[t]) : 0.f; pA[t] += (size_t)KT * wstride; }
#pragma unroll
            for (int t = 0; t < 4; t++) { rB[t] = bval ? __ldg(pB[t]) : 0.f; pB[t] += (size_t)KT * HW; }
        }
#pragma unroll
        for (int kk = 0; kk < KT; kk++) {
            const unsigned long long* bp =
                reinterpret_cast<const unsigned long long*>(&sB[kk][tx * 4]);
            unsigned long long b0 = bp[0], b1 = bp[1];
            const float* ar = &sA[kk][ty * ROWS];
#pragma unroll
            for (int i = 0; i < ROWS; i++) {
                float a = ar[i];
                unsigned long long ap = pk2(a, a);
                FFMA2(acc[i][0], ap, b0);
                FFMA2(acc[i][1], ap, b1);
            }
        }
        __syncthreads();
    }

    float* po = part + (size_t)s * M * HW;
#pragma unroll
    for (int i = 0; i < ROWS; i++) {
        int m = m0 + ty * ROWS + i;
        if (m >= M) continue;
        float vals[4];
        unpk2(acc[i][0], vals[0], vals[1]);
        unpk2(acc[i][1], vals[2], vals[3]);
#pragma unroll
        for (int j = 0; j < 4; j++) {
            int n2 = n0 + tx * 4 + j;
            if (n2 >= rectN) continue;
            int yy = n2 / rw, xx = n2 - yy * rw;
            po[(size_t)m * HW + (y0 + yy) * Wd + (x0 + xx)] = vals[j];
        }
    }
}

__global__ void reduce_k(const float* __restrict__ part, float* __restrict__ out,
                         int M, int H, int W, int d, int centerOnly, int ntaps, int kch,
                         int flags, const float* __restrict__ sc,
                         const float* __restrict__ bi, const float* __restrict__ eb) {
    int HW = H * W;
    int idx = blockIdx.x * 256 + threadIdx.x;
    if (idx >= M * HW) return;
    int m = idx / HW;
    int p = idx - m * HW;
    int y = p / W, x = p - y * W;
    float acc = 0.f;
    for (int s = 0; s < ntaps * kch; s++) {
        int ti = s / kch;
        int dy, dx, y0, x0, rh, rw;
        tap_rect(ti, d, centerOnly, H, W, dy, dx, y0, x0, rh, rw);
        if (y >= y0 && y < y0 + rh && x >= x0 && x < x0 + rw)
            acc += part[(size_t)s * M * HW + idx];
    }
    if (flags & 8) acc += eb[m];
    if (flags & 2) acc = sc[m] * acc + bi[m];
    if (flags & 4) acc = fmaxf(acc, 0.f);
    out[idx] = acc;
}

// ============================ small kernels ============================
__global__ void resize_kk(const float* __restrict__ in, float* __restrict__ out,
                          int C, int Hi, int Wi, int Ho, int Wo, int dorelu) {
    int i = blockIdx.x * 256 + threadIdx.x;
    int total = C * Ho * Wo;
    if (i >= total) return;
    int ox = i % Wo;
    int t = i / Wo;
    int oy = t % Ho;
    int c = t / Ho;
    float ry = (Ho > 1) ? (float)(Hi - 1) / (float)(Ho - 1) : 0.f;
    float rx = (Wo > 1) ? (float)(Wi - 1) / (float)(Wo - 1) : 0.f;
    float tyf = oy * ry;
    int yl = (int)floorf(tyf);
    float fy = tyf - yl;
    int yh = min(yl + 1, Hi - 1);
    float txf = ox * rx;
    int xl = (int)floorf(txf);
    float fx = txf - xl;
    int xh = min(xl + 1, Wi - 1);
    const float* p = in + (size_t)c * Hi * Wi;
    float v00 = p[yl * Wi + xl], v01 = p[yl * Wi + xh];
    float v10 = p[yh * Wi + xl], v11 = p[yh * Wi + xh];
    float v = (v00 * (1.f - fy) + v10 * fy) * (1.f - fx) + (v01 * (1.f - fy) + v11 * fy) * fx;
    if (dorelu) v = fmaxf(v, 0.f);
    out[i] = v;
}

__global__ void energy_k(const float* __restrict__ c1r, const float* __restrict__ c2r,
                         float* __restrict__ att) {
    int p = blockIdx.x * 256 + threadIdx.x;
    if (p >= 4096) return;
    int y = p >> 6, x = p & 63;
    float e[9];
    int nidx[9];
    bool val[9];
#pragma unroll
    for (int a = 0; a < 3; a++)
#pragma unroll
        for (int b = 0; b < 3; b++) {
            int k = a * 3 + b;
            int iy = y + 2 * (a - 1), ix = x + 2 * (b - 1);
            val[k] = (unsigned)iy < 64u && (unsigned)ix < 64u;
            nidx[k] = val[k] ? (iy * 64 + ix) : 0;
            e[k] = 0.f;
        }
    for (int c = 0; c < 64; c++) {
        float v = c1r[c * 4096 + p];
        const float* row = c2r + c * 4096;
#pragma unroll
        for (int k = 0; k < 9; k++)
            if (val[k]) e[k] = fmaf(v, row[nidx[k]], e[k]);
    }
    float mx = e[0];
#pragma unroll
    for (int k = 1; k < 9; k++) mx = fmaxf(mx, e[k]);
    float sum = 0.f, ex[9];
#pragma unroll
    for (int k = 0; k < 9; k++) { ex[k] = expf(e[k] - mx); sum += ex[k]; }
    float inv = 1.f / sum;
#pragma unroll
    for (int k = 0; k < 9; k++) att[k * 4096 + p] = ex[k] * inv;
}

__global__ void gap_k(const float* __restrict__ x, float* __restrict__ gap) {
    int c = blockIdx.x * 8 + (threadIdx.x >> 5);
    int lane = threadIdx.x & 31;
    const float* p = x + (size_t)c * 1024;
    float s = 0.f;
    for (int i = lane; i < 1024; i += 32) s += p[i];
#pragma unroll
    for (int o = 16; o; o >>= 1) s += __shfl_xor_sync(0xffffffffu, s, o);
    if (!lane) gap[c] = s * (1.f / 1024.f);
}

__global__ void f4_k(const float* __restrict__ w, const float* __restrict__ s,
                     const float* __restrict__ b, const float* __restrict__ gap,
                     float* __restrict__ f4) {
    int o = blockIdx.x * 8 + (threadIdx.x >> 5);
    int lane = threadIdx.x & 31;
    const float* row = w + (size_t)o * 4096;
    float acc = 0.f;
    for (int i = lane; i < 4096; i += 32) acc = fmaf(row[i], gap[i], acc);
#pragma unroll
    for (int off = 16; off; off >>= 1) acc += __shfl_xor_sync(0xffffffffu, acc, off);
    if (!lane) f4[o] = fmaxf(s[o] * acc + b[o], 0.f);
}

__global__ void bias4_k(const float* __restrict__ apw, const float* __restrict__ f4,
                        float* __restrict__ b4) {
    int o = blockIdx.x * 8 + (threadIdx.x >> 5);
    int lane = threadIdx.x & 31;
    const float* row = apw + (size_t)o * 2560 + 2048;
    float acc = 0.f;
    for (int i = lane; i < 512; i += 32) acc = fmaf(row[i], f4[i], acc);
#pragma unroll
    for (int off = 16; off; off >>= 1) acc += __shfl_xor_sync(0xffffffffu, acc, off);
    if (!lane) b4[o] = acc;
}

__global__ void agg_k(const float* __restrict__ att, const float* __restrict__ zup,
                      const float* __restrict__ c6b, float* __restrict__ out) {
    int p = blockIdx.x * 256 + threadIdx.x;
    if (p >= 4096) return;
    int y = p >> 6, x = p & 63;
    float acc[19];
#pragma unroll
    for (int o = 0; o < 19; o++) acc[o] = c6b[o];
#pragma unroll
    for (int a = 0; a < 3; a++)
#pragma unroll
        for (int b = 0; b < 3; b++) {
            int k = a * 3 + b;
            int iy = y + 2 * (a - 1), ix = x + 2 * (b - 1);
            if ((unsigned)iy < 64u && (unsigned)ix < 64u) {
                float w = att[k * 4096 + p];
                int n = iy * 64 + ix;
#pragma unroll
                for (int o = 0; o < 19; o++) acc[o] = fmaf(w, zup[o * 4096 + n], acc[o]);
            }
        }
#pragma unroll
    for (int o = 0; o < 19; o++) out[o * 4096 + p] = acc[o];
}

// ============================ host driver ============================
static float* g_part_p;
static float* g_part2_p;

static void run_conv(int mt, const float* Wt, int Arow, int wstride, int wofs0, int centerOnly,
                     const float* X, float* Cout,
                     int M, int K, int H, int Wd, int d, int kch,
                     const float* sc, const float* bi, const float* eb, int flags) {
    int ntaps = (d > 0 && !centerOnly) ? 9 : 1;
    int HW = H * Wd;
    int Kc = K / kch;
    dim3 grid((HW + 63) / 64, (M + mt - 1) / mt, ntaps * kch);
    if (mt == 128)
        gemm2<128><<<grid, 256>>>(Wt, Arow, wstride, wofs0, centerOnly, X, g_part2_p,
                                  M, Kc, kch, H, Wd, d);
    else
        gemm2<64><<<grid, 256>>>(Wt, Arow, wstride, wofs0, centerOnly, X, g_part2_p,
                                 M, Kc, kch, H, Wd, d);
    int tot = M * HW;
    reduce_k<<<(tot + 255) / 256, 256>>>(g_part2_p, Cout, M, H, Wd, d, centerOnly,
                                         ntaps, kch, flags, sc, bi, eb);
}

extern "C" void kernel_launch(void* const* d_in, const int* in_sizes, int n_in,
                              void* d_out, int out_size) {
    const float* c1 = (const float*)d_in[0];
    const float* c2 = (const float*)d_in[1];
    const float* x = (const float*)d_in[2];
    const float* rf1_w = (const float*)d_in[3];
    const float* rf1_s = (const float*)d_in[4];
    const float* rf1_b = (const float*)d_in[5];
    const float* rf2_w = (const float*)d_in[6];
    const float* rf2_s = (const float*)d_in[7];
    const float* rf2_b = (const float*)d_in[8];
    const float* r2_w = (const float*)d_in[9];
    const float* r2_s = (const float*)d_in[10];
    const float* r2_b = (const float*)d_in[11];
    const float* a0_w = (const float*)d_in[12];
    const float* a0_s = (const float*)d_in[13];
    const float* a0_b = (const float*)d_in[14];
    const float* a1_w = (const float*)d_in[15];
    const float* a1_s = (const float*)d_in[16];
    const float* a1_b = (const float*)d_in[17];
    const float* a2_w = (const float*)d_in[18];
    const float* a2_s = (const float*)d_in[19];
    const float* a2_b = (const float*)d_in[20];
    const float* a3_w = (const float*)d_in[21];
    const float* a3_s = (const float*)d_in[22];
    const float* a3_b = (const float*)d_in[23];
    const float* a4_w = (const float*)d_in[24];
    const float* a4_s = (const float*)d_in[25];
    const float* a4_b = (const float*)d_in[26];
    const float* ap_w = (const float*)d_in[27];
    const float* ap_s = (const float*)d_in[28];
    const float* ap_b = (const float*)d_in[29];
    const float* c6_w = (const float*)d_in[30];
    const float* c6_b = (const float*)d_in[31];

    float *t2, *c1r, *c2r, *att, *gap, *f4, *b4, *outb, *z, *zup;
    __half *whi, *xthi, *fhi, *c1thi, *c1tlo, *t1thi, *t1tlo;
    cudaGetSymbolAddress((void**)&g_part_p, g_part);
    cudaGetSymbolAddress((void**)&g_part2_p, g_part2);
    cudaGetSymbolAddress((void**)&t2, g_t2);
    cudaGetSymbolAddress((void**)&c1r, g_c1r);
    cudaGetSymbolAddress((void**)&c2r, g_c2r);
    cudaGetSymbolAddress((void**)&att, g_att);
    cudaGetSymbolAddress((void**)&gap, g_gap);
    cudaGetSymbolAddress((void**)&f4, g_f4);
    cudaGetSymbolAddress((void**)&b4, g_b4);
    cudaGetSymbolAddress((void**)&outb, g_outb);
    cudaGetSymbolAddress((void**)&z, g_z);
    cudaGetSymbolAddress((void**)&zup, g_zup);
    cudaGetSymbolAddress((void**)&whi, g_whi);
    cudaGetSymbolAddress((void**)&xthi, g_xthi);
    cudaGetSymbolAddress((void**)&fhi, g_fhi);
    cudaGetSymbolAddress((void**)&c1thi, g_c1thi);
    cudaGetSymbolAddress((void**)&c1tlo, g_c1tlo);
    cudaGetSymbolAddress((void**)&t1thi, g_t1thi);
    cudaGetSymbolAddress((void**)&t1tlo, g_t1tlo);

    const size_t PB = 512 * 1024 * sizeof(float);   // 2MB accumulation slice
    const int SMEM_H1 = 3 * 18432 * 2;
    const int SMEM_H2 = 2 * 27648 * 2;
    cudaFuncSetAttribute(hgemm<0>, cudaFuncAttributeMaxDynamicSharedMemorySize, SMEM_H1);
    cudaFuncSetAttribute(hgemm<1>, cudaFuncAttributeMaxDynamicSharedMemorySize, SMEM_H2);

    // --- conversions + ASPP (RED accumulation; memset before each GEMM) ---
    xtrans_g<<<dim3(32, 128), 256>>>(x, xthi, nullptr, 1024, 4096);
    wconv3x3b<<<dim3(512, 8, 2), 256>>>(a1_w, a2_w, whi + S_A1, whi + S_A2);
    cudaMemsetAsync(g_part_p, 0, PB);
    hgemm<0><<<dim3(8, 4, 36), 256, SMEM_H1>>>(whi + S_A1, xthi, nullptr, g_part_p,
                                               4096, 1024, 4096, 4, 1, 12, 5, 1024, 1);
    reduce_ht<<<dim3(32, 16), 256>>>(g_part_p, 1024, a1_s, a1_b, fhi, nullptr, 2048, 512);
    cudaMemsetAsync(g_part_p, 0, PB);
    hgemm<0><<<dim3(8, 4, 36), 256, SMEM_H1>>>(whi + S_A2, xthi, nullptr, g_part_p,
                                               4096, 1024, 4096, 4, 1, 24, 5, 1024, 1);
    reduce_ht<<<dim3(32, 16), 256>>>(g_part_p, 1024, a2_s, a2_b, fhi, nullptr, 2048, 1024);
    wconv1x1<<<(512 * 4096 / 4 + 255) / 256, 256>>>(a0_w, 4096, 4096, whi + S_A0, 512 * 1024);
    cudaMemsetAsync(g_part_p, 0, PB);
    hgemm<0><<<dim3(8, 4, 16), 256, SMEM_H1>>>(whi + S_A0, xthi, nullptr, g_part_p,
                                               4096, 256, 4096, 16, 0, 0, 5, 1024, 0);
    reduce_ht<<<dim3(32, 16), 256>>>(g_part_p, 1024, a0_s, a0_b, fhi, nullptr, 2048, 0);
    wcenter<<<(512 * 2048 + 255) / 256, 256>>>(a3_w, whi + S_A3);
    cudaMemsetAsync(g_part_p, 0, PB);
    hgemm<0><<<dim3(8, 4, 16), 256, SMEM_H1>>>(whi + S_A3, xthi, nullptr, g_part_p,
                                               4096, 256, 4096, 16, 0, 0, 5, 1024, 0);
    reduce_ht<<<dim3(32, 16), 256>>>(g_part_p, 1024, a3_s, a3_b, fhi, nullptr, 2048, 1536);

    // --- attention branch: refine convs on HMMA (2-pass for accuracy) ---
    xtrans_g<<<dim3(128, 8), 256>>>(c1, c1thi, c1tlo, 4096, 256);
    wrf_k<<<(64 * 256 * 9 + 255) / 256, 256>>>(rf1_w, whi + S_RF1, 64, 256);
    wrf_k<<<(64 * 64 * 9 + 255) / 256, 256>>>(rf2_w, whi + S_RF2, 64, 64);
    cudaMemsetAsync(g_part_p, 0, PB);
    hgemm<1><<<dim3(32, 1, 9), 256, SMEM_H2>>>(whi + S_RF1, c1thi, c1tlo, g_part_p,
                                               256, 256, 256, 1, 1, 2, 6, 4096, 1);
    reduce_ht<<<dim3(128, 2), 256>>>(g_part_p, 4096, rf1_s, rf1_b, t1thi, t1tlo, 64, 0);
    cudaMemsetAsync(g_part_p, 0, PB);
    hgemm<1><<<dim3(32, 1, 9), 256, SMEM_H2>>>(whi + S_RF2, t1thi, t1tlo, g_part_p,
                                               64, 64, 64, 1, 1, 2, 6, 4096, 1);
    reduce_pl<<<(64 * 4096 + 255) / 256, 256>>>(g_part_p, c1r, 4096, 64, 6,
                                                rf2_s, rf2_b, nullptr);
    run_conv(64, r2_w, 512, 1, 0, 1, c2, t2, 64, 512, 32, 32, 0, 4, r2_s, r2_b, nullptr, 2);
    resize_kk<<<(64 * 4096 + 255) / 256, 256>>>(t2, c2r, 64, 32, 32, 64, 64, 1);
    energy_k<<<16, 256>>>(c1r, c2r, att);

    // --- GAP branch + ap (single-pass) ---
    gap_k<<<512, 256>>>(x, gap);
    f4_k<<<64, 256>>>(a4_w, a4_s, a4_b, gap, f4);
    bias4_k<<<64, 256>>>(ap_w, f4, b4);
    wconv1x1<<<(512 * 2048 / 4 + 255) / 256, 256>>>(ap_w, 2560, 2048, whi + S_AP, 512 * 512);
    cudaMemsetAsync(g_part_p, 0, PB);
    hgemm<0><<<dim3(8, 4, 8), 256, SMEM_H1>>>(whi + S_AP, fhi, nullptr, g_part_p,
                                              2048, 256, 2048, 8, 0, 0, 5, 1024, 0);
    reduce_pl<<<2048, 256>>>(g_part_p, outb, 1024, 512, 2 | 4 | 8, ap_s, ap_b, b4);

    // --- final head ---
    run_conv(64, c6_w, 512, 1, 0, 1, outb, z, 19, 512, 32, 32, 0, 4, nullptr, nullptr, nullptr, 0);
    resize_kk<<<(19 * 4096 + 255) / 256, 256>>>(z, zup, 19, 32, 32, 64, 64, 0);
    agg_k<<<16, 256>>>(att, zup, c6_b, (float*)d_out);
}

// round 17
// speedup vs baseline: 1.9205x; 1.0566x over previous
#include <cuda_runtime.h>
#include <cuda_fp16.h>
#include <math.h>
#include <stdint.h>

#define DEV_INLINE __device__ __forceinline__

DEV_INLINE unsigned long long pk2(float lo, float hi) {
    unsigned long long r;
    asm("mov.b64 %0, {%1, %2};" : "=l"(r) : "f"(lo), "f"(hi));
    return r;
}
DEV_INLINE void unpk2(unsigned long long v, float& lo, float& hi) {
    asm("mov.b64 {%0, %1}, %2;" : "=f"(lo), "=f"(hi) : "l"(v));
}
#define FFMA2(d, a, b) asm("fma.rn.f32x2 %0, %1, %2, %0;" : "+l"(d) : "l"(a), "l"(b))

DEV_INLINE void mma_f16(float* c, const uint32_t* a, const uint32_t* b) {
    asm volatile(
        "mma.sync.aligned.m16n8k16.row.col.f32.f16.f16.f32 "
        "{%0,%1,%2,%3}, {%4,%5,%6,%7}, {%8,%9}, {%0,%1,%2,%3};"
        : "+f"(c[0]), "+f"(c[1]), "+f"(c[2]), "+f"(c[3])
        : "r"(a[0]), "r"(a[1]), "r"(a[2]), "r"(a[3]), "r"(b[0]), "r"(b[1]));
}
DEV_INLINE void ldsm_x4(uint32_t& r0, uint32_t& r1, uint32_t& r2, uint32_t& r3, uint32_t a) {
    asm volatile("ldmatrix.sync.aligned.m8n8.x4.shared.b16 {%0,%1,%2,%3}, [%4];"
                 : "=r"(r0), "=r"(r1), "=r"(r2), "=r"(r3) : "r"(a));
}

#define CP_ASYNC_CG(dst, src, sz) \
    asm volatile("cp.async.cg.shared.global [%0], [%1], 16, %2;" \
                 :: "r"(dst), "l"(src), "r"(sz) : "memory")
#define CP_COMMIT() asm volatile("cp.async.commit_group;" ::: "memory")
#define CP_WAIT_N1() asm volatile("cp.async.wait_group 1;" ::: "memory")
#define CP_WAIT_N2() asm volatile("cp.async.wait_group 2;" ::: "memory")

// ============================ scratch ============================
__device__ float g_part[4 * 512 * 1024];      // 4 accumulation slices (one per ASPP layer)
__device__ float g_part2[5 * 1024 * 1024];    // slices for FFMA2 path (r2, c6)
__device__ float g_t2[64 * 1024];
__device__ float g_c1r[64 * 4096];
__device__ float g_c2r[64 * 4096];
__device__ float g_att[9 * 4096];
__device__ float g_gap[4096];
__device__ float g_f4[512];
__device__ float g_b4[512];
__device__ float g_outb[512 * 1024];
__device__ float g_z[19 * 1024];
__device__ float g_zup[19 * 4096];
__device__ __align__(16) __half g_whi[43360256];
__device__ __align__(16) __half g_xthi[1024 * 4096];
__device__ __align__(16) __half g_fhi[1024 * 2048];
__device__ __align__(16) __half g_c1thi[4096 * 256];
__device__ __align__(16) __half g_c1tlo[4096 * 256];
__device__ __align__(16) __half g_t1thi[4096 * 64];
__device__ __align__(16) __half g_t1tlo[4096 * 64];

static const size_t S_A0 = 0;
static const size_t S_A1 = 2097152;
static const size_t S_A2 = 20971520;
static const size_t S_A3 = 39845888;
static const size_t S_AP = 41943040;
static const size_t S_RF1 = 42991616;
static const size_t S_RF2 = 43286528;

// ============================ merged ASPP GEMM ============================
// One launch covers a1(36) + a2(36) + a0(16) + a3(16) = 104 z-slices.
// All layers: Ktot=4096, image 32x32, M=512, single-pass fp16, 3-stage cp.async,
// RED accumulation into per-layer 2MB slice (buffer pre-zeroed).
__global__ void __launch_bounds__(256, 2)
hgemm_aspp(const __half* __restrict__ Wbase, float* __restrict__ partBase,
           const __half* __restrict__ Xhi)
{
    extern __shared__ __half sm[];
    constexpr int NSTAGE = 3;
    const int STG = 18432;
    const uint32_t smB = (uint32_t)__cvta_generic_to_shared(sm);
    const uint32_t STGB = STG * 2;

    const int tid = threadIdx.x;
    const int wid = tid >> 5, lane = tid & 31;
    const int s = blockIdx.z;
    const int m0 = blockIdx.y * 128;
    const int n0 = blockIdx.x * 128;

    // ---- per-slice layer decode (all compile-time constants) ----
    int ls, kch, tapMode, dil, Kc, buf;
    size_t seg;
    if (s < 36)      { ls = s;      kch = 4;  tapMode = 1; dil = 12; Kc = 1024; buf = 0; seg = S_A1; }
    else if (s < 72) { ls = s - 36; kch = 4;  tapMode = 1; dil = 24; Kc = 1024; buf = 1; seg = S_A2; }
    else if (s < 88) { ls = s - 72; kch = 16; tapMode = 0; dil = 0;  Kc = 256;  buf = 2; seg = S_A0; }
    else             { ls = s - 88; kch = 16; tapMode = 0; dil = 0;  Kc = 256;  buf = 3; seg = S_A3; }
    const int ti = ls / kch;
    const int kc = ls - ti * kch;
    float* part = partBase + (size_t)buf * 524288;

    int dy = 0, dx = 0;
    size_t wbase = seg;
    if (tapMode) {
        dy = (ti / 3 - 1) * dil;
        dx = (ti % 3 - 1) * dil;
        wbase += (size_t)ti * 512 * 4096;
        int r0 = n0 >> 5;   // tile covers 4 image rows
        if (r0 + 3 + dy < 0 || r0 + dy > 31) return;   // zero contribution
    }
    const int k0s = kc * Kc;

    const __half* gA[4];
    uint32_t sAo[4];
    const __half* gB[4];
    uint32_t sBo[4];
    int bsz[4];
#pragma unroll
    for (int i = 0; i < 4; i++) {
        int v = tid + 256 * i;
        int mr = v >> 3, ko = (v & 7) * 8;
        gA[i] = Wbase + wbase + (size_t)(m0 + mr) * 4096 + k0s + ko;
        sAo[i] = (mr * 72 + ko) * 2;
        int q = n0 + mr;
        int iy = (q >> 5) + dy, ix = (q & 31) + dx;
        bool ok = (unsigned)iy < 32u && (unsigned)ix < 32u;
        size_t gb = ok ? (size_t)((iy << 5) + ix) * 4096 + k0s + ko : 0;
        gB[i] = Xhi + gb;
        bsz[i] = ok ? 16 : 0;
        sBo[i] = (mr * 72 + ko) * 2;
    }

    const int wm = (wid & 1) * 64;
    const int wn = (wid >> 1) * 32;

    uint32_t aOff[4], bOff[2];
#pragma unroll
    for (int im = 0; im < 4; im++)
        aOff[im] = ((wm + im * 16 + (lane & 15)) * 72 + (lane >> 4) * 8) * 2;
#pragma unroll
    for (int pi = 0; pi < 2; pi++)
        bOff[pi] = ((wn + pi * 16 + ((lane >> 4) & 1) * 8 + (lane & 7)) * 72 +
                    ((lane >> 3) & 1) * 8) * 2 + 18432;

    float acc[4][4][4];
#pragma unroll
    for (int i = 0; i < 4; i++)
#pragma unroll
        for (int j = 0; j < 4; j++)
#pragma unroll
            for (int q = 0; q < 4; q++) acc[i][j][q] = 0.f;

    const int nChunks = Kc / 64;

#define LOADCHUNK_A(sb)                                                          \
    do {                                                                         \
        _Pragma("unroll")                                                        \
        for (int i = 0; i < 4; i++) { CP_ASYNC_CG((sb) + sAo[i], gA[i], 16); gA[i] += 64; } \
        _Pragma("unroll")                                                        \
        for (int i = 0; i < 4; i++) { CP_ASYNC_CG((sb) + 18432 + sBo[i], gB[i], bsz[i]); gB[i] += 64; } \
    } while (0)

    {
        int npro = (NSTAGE - 1 < nChunks) ? NSTAGE - 1 : nChunks;
        for (int p = 0; p < npro; p++) {
            LOADCHUNK_A(smB + p * STGB);
            CP_COMMIT();
        }
        for (int p = npro; p < NSTAGE - 1; p++) CP_COMMIT();
    }

    for (int c = 0; c < nChunks; c++) {
        int pf = c + NSTAGE - 1;
        if (pf < nChunks) LOADCHUNK_A(smB + (pf % NSTAGE) * STGB);
        CP_COMMIT();
        CP_WAIT_N2();
        __syncthreads();

        const uint32_t sbase = smB + (c % NSTAGE) * STGB;

#pragma unroll
        for (int kk = 0; kk < 64; kk += 16) {
            uint32_t af[4][4], bh[4][2];
#pragma unroll
            for (int im = 0; im < 4; im++)
                ldsm_x4(af[im][0], af[im][1], af[im][2], af[im][3],
                        sbase + aOff[im] + kk * 2);
#pragma unroll
            for (int pi = 0; pi < 2; pi++)
                ldsm_x4(bh[2 * pi][0], bh[2 * pi][1], bh[2 * pi + 1][0], bh[2 * pi + 1][1],
                        sbase + bOff[pi] + kk * 2);
#pragma unroll
            for (int im = 0; im < 4; im++)
#pragma unroll
                for (int in_ = 0; in_ < 4; in_++) mma_f16(acc[im][in_], af[im], bh[in_]);
        }
        __syncthreads();
    }
#undef LOADCHUNK_A

    const int r = lane >> 2;
    const int cp = (lane & 3) * 2;
    const int rbase = m0 + wm + r;
    const int cbase = n0 + wn + cp;
#pragma unroll
    for (int im = 0; im < 4; im++)
#pragma unroll
        for (int in_ = 0; in_ < 4; in_++) {
            int m = rbase + im * 16, n = cbase + in_ * 8;
            atomicAdd(&part[(size_t)m * 1024 + n], acc[im][in_][0]);
            atomicAdd(&part[(size_t)m * 1024 + n + 1], acc[im][in_][1]);
            atomicAdd(&part[(size_t)(m + 8) * 1024 + n], acc[im][in_][2]);
            atomicAdd(&part[(size_t)(m + 8) * 1024 + n + 1], acc[im][in_][3]);
        }
}

// ============================ generic HMMA GEMM (rf, ap) ============================
template <int USE_LO>
__global__ void __launch_bounds__(256, 2)
hgemm(const __half* __restrict__ Wh,
      const __half* __restrict__ Xhi, const __half* __restrict__ Xlo,
      float* __restrict__ part,
      int Ktot, int Kc, int Kx, int kch, int tapMode, int dil, int wshift, int HW, int skipEn)
{
    extern __shared__ __half sm[];
    constexpr int NSTAGE = USE_LO ? 2 : 3;
    const int STG = USE_LO ? 27648 : 18432;
    const uint32_t smB = (uint32_t)__cvta_generic_to_shared(sm);
    const uint32_t STGB = STG * 2;

    const int tid = threadIdx.x;
    const int wid = tid >> 5, lane = tid & 31;
    const int s = blockIdx.z;
    const int ti = s / kch;
    const int kc = s - ti * kch;
    const int m0 = blockIdx.y * 128;
    const int n0 = blockIdx.x * 128;
    const int Mpad = gridDim.y * 128;
    const int Wimg = 1 << wshift;

    int dy = 0, dx = 0;
    size_t wbase = 0;
    if (tapMode) {
        dy = (ti / 3 - 1) * dil;
        dx = (ti % 3 - 1) * dil;
        wbase = (size_t)ti * Mpad * Ktot;
        if (skipEn) {
            int tileRows = 128 >> wshift;
            int r0 = n0 >> wshift;
            if (r0 + tileRows - 1 + dy < 0 || r0 + dy >= Wimg) return;
        }
    }
    const int k0s = kc * Kc;

    const __half* gA[4];
    uint32_t sAo[4];
    const __half* gB[4];
    const __half* gBl[4];
    uint32_t sBo[4];
    int bsz[4];
#pragma unroll
    for (int i = 0; i < 4; i++) {
        int v = tid + 256 * i;
        int mr = v >> 3, ko = (v & 7) * 8;
        gA[i] = Wh + wbase + (size_t)(m0 + mr) * Ktot + k0s + ko;
        sAo[i] = (mr * 72 + ko) * 2;
        int q = n0 + mr;
        int iy = (q >> wshift) + dy, ix = (q & (Wimg - 1)) + dx;
        bool ok = (unsigned)iy < (unsigned)Wimg && (unsigned)ix < (unsigned)Wimg;
        size_t gb = ok ? (size_t)((iy << wshift) + ix) * Kx + k0s + ko : 0;
        gB[i] = Xhi + gb;
        gBl[i] = USE_LO ? (Xlo + gb) : Xhi;
        bsz[i] = ok ? 16 : 0;
        sBo[i] = (mr * 72 + ko) * 2;
    }

    const int wm = (wid & 1) * 64;
    const int wn = (wid >> 1) * 32;

    uint32_t aOff[4], bOff[2];
#pragma unroll
    for (int im = 0; im < 4; im++)
        aOff[im] = ((wm + im * 16 + (lane & 15)) * 72 + (lane >> 4) * 8) * 2;
#pragma unroll
    for (int pi = 0; pi < 2; pi++)
        bOff[pi] = ((wn + pi * 16 + ((lane >> 4) & 1) * 8 + (lane & 7)) * 72 +
                    ((lane >> 3) & 1) * 8) * 2 + 18432;

    float acc[4][4][4];
#pragma unroll
    for (int i = 0; i < 4; i++)
#pragma unroll
        for (int j = 0; j < 4; j++)
#pragma unroll
            for (int q = 0; q < 4; q++) acc[i][j][q] = 0.f;

    const int nChunks = Kc / 64;

#define LOADCHUNK(sb)                                                            \
    do {                                                                         \
        _Pragma("unroll")                                                        \
        for (int i = 0; i < 4; i++) { CP_ASYNC_CG((sb) + sAo[i], gA[i], 16); gA[i] += 64; } \
        _Pragma("unroll")                                                        \
        for (int i = 0; i < 4; i++) {                                            \
            CP_ASYNC_CG((sb) + 18432 + sBo[i], gB[i], bsz[i]);                   \
            gB[i] += 64;                                                         \
            if (USE_LO) { CP_ASYNC_CG((sb) + 36864 + sBo[i], gBl[i], bsz[i]); gBl[i] += 64; } \
        }                                                                        \
    } while (0)

    {
        int npro = (NSTAGE - 1 < nChunks) ? NSTAGE - 1 : nChunks;
        for (int p = 0; p < npro; p++) {
            LOADCHUNK(smB + p * STGB);
            CP_COMMIT();
        }
        for (int p = npro; p < NSTAGE - 1; p++) CP_COMMIT();
    }

    for (int c = 0; c < nChunks; c++) {
        int pf = c + NSTAGE - 1;
        if (pf < nChunks) LOADCHUNK(smB + (pf % NSTAGE) * STGB);
        CP_COMMIT();
        if (USE_LO) CP_WAIT_N1(); else CP_WAIT_N2();
        __syncthreads();

        const uint32_t sbase = smB + (c % NSTAGE) * STGB;

#pragma unroll
        for (int kk = 0; kk < 64; kk += 16) {
            uint32_t af[4][4], bh[4][2];
#pragma unroll
            for (int im = 0; im < 4; im++)
                ldsm_x4(af[im][0], af[im][1], af[im][2], af[im][3],
                        sbase + aOff[im] + kk * 2);
#pragma unroll
            for (int pi = 0; pi < 2; pi++)
                ldsm_x4(bh[2 * pi][0], bh[2 * pi][1], bh[2 * pi + 1][0], bh[2 * pi + 1][1],
                        sbase + bOff[pi] + kk * 2);
#pragma unroll
            for (int im = 0; im < 4; im++)
#pragma unroll
                for (int in_ = 0; in_ < 4; in_++) mma_f16(acc[im][in_], af[im], bh[in_]);
            if (USE_LO) {
                uint32_t bl[4][2];
#pragma unroll
                for (int pi = 0; pi < 2; pi++)
                    ldsm_x4(bl[2 * pi][0], bl[2 * pi][1], bl[2 * pi + 1][0], bl[2 * pi + 1][1],
                            sbase + bOff[pi] + 18432 + kk * 2);
#pragma unroll
                for (int im = 0; im < 4; im++)
#pragma unroll
                    for (int in_ = 0; in_ < 4; in_++) mma_f16(acc[im][in_], af[im], bl[in_]);
            }
        }
        __syncthreads();
    }
#undef LOADCHUNK

    const int r = lane >> 2;
    const int cp = (lane & 3) * 2;
    const int rbase = m0 + wm + r;
    const int cbase = n0 + wn + cp;
#pragma unroll
    for (int im = 0; im < 4; im++)
#pragma unroll
        for (int in_ = 0; in_ < 4; in_++) {
            int m = rbase + im * 16, n = cbase + in_ * 8;
            atomicAdd(&part[(size_t)m * HW + n], acc[im][in_][0]);
            atomicAdd(&part[(size_t)m * HW + n + 1], acc[im][in_][1]);
            atomicAdd(&part[(size_t)(m + 8) * HW + n], acc[im][in_][2]);
            atomicAdd(&part[(size_t)(m + 8) * HW + n + 1], acc[im][in_][3]);
        }
}

// bn_relu + TRANSPOSED fp16 hi (+ optional lo) from an accumulated slice
__global__ void reduce_ht(const float* __restrict__ part, int HW,
                          const float* __restrict__ sc, const float* __restrict__ bi,
                          __half* __restrict__ ohi, __half* __restrict__ olo,
                          int ostride, int colOff)
{
    __shared__ float t[32][33];
    int tx = threadIdx.x & 31, ty = threadIdx.x >> 5;
    int q0 = blockIdx.x * 32, m0 = blockIdx.y * 32;
#pragma unroll
    for (int r = 0; r < 4; r++) {
        int ml = ty + 8 * r;
        int m = m0 + ml;
        float a = part[(size_t)m * HW + q0 + tx];
        t[ml][tx] = fmaxf(sc[m] * a + bi[m], 0.f);
    }
    __syncthreads();
#pragma unroll
    for (int r = 0; r < 4; r++) {
        int ql = ty + 8 * r;
        float v = t[tx][ql];
        __half h = __float2half_rn(v);
        size_t o = (size_t)(q0 + ql) * ostride + colOff + m0 + tx;
        ohi[o] = h;
        if (olo) olo[o] = __float2half_rn(v - __half2float(h));
    }
}

__global__ void reduce_pl(const float* __restrict__ part, float* __restrict__ out,
                          int HW, int Mtot, int flags,
                          const float* __restrict__ sc, const float* __restrict__ bi,
                          const float* __restrict__ eb)
{
    int idx = blockIdx.x * 256 + threadIdx.x;
    if (idx >= Mtot * HW) return;
    int m = idx / HW;
    float a = part[idx];
    if (flags & 8) a += eb[m];
    if (flags & 2) a = sc[m] * a + bi[m];
    if (flags & 4) a = fmaxf(a, 0.f);
    out[idx] = a;
}

// ============================ conversion pre-passes ============================
__global__ void xtrans_g(const float* __restrict__ in,
                         __half* __restrict__ ohi, __half* __restrict__ olo,
                         int HW, int K) {
    __shared__ float t[32][33];
    int tx = threadIdx.x & 31, ty = threadIdx.x >> 5;
    int q0 = blockIdx.x * 32, k0 = blockIdx.y * 32;
#pragma unroll
    for (int r = 0; r < 4; r++)
        t[ty + 8 * r][tx] = in[(size_t)(k0 + ty + 8 * r) * HW + q0 + tx];
    __syncthreads();
#pragma unroll
    for (int r = 0; r < 4; r++) {
        int ql = ty + 8 * r;
        float v = t[tx][ql];
        __half h = __float2half_rn(v);
        size_t o = (size_t)(q0 + ql) * K + k0 + tx;
        ohi[o] = h;
        if (olo) olo[o] = __float2half_rn(v - __half2float(h));
    }
}

__global__ void wconv1x1(const float* __restrict__ in, int rowStride, int K,
                         __half* __restrict__ whi, int total4) {
    int i = blockIdx.x * 256 + threadIdx.x;
    if (i >= total4) return;
    int e = i * 4, m = e / K, k = e - m * K;
    float4 v = *(const float4*)(in + (size_t)m * rowStride + k);
    size_t o = (size_t)m * K + k;
    *(__half2*)(whi + o) = __floats2half2_rn(v.x, v.y);
    *(__half2*)(whi + o + 2) = __floats2half2_rn(v.z, v.w);
}

__global__ void wconv3x3b(const float* __restrict__ inA, const float* __restrict__ inB,
                          __half* __restrict__ outA, __half* __restrict__ outB) {
    __shared__ float st[4608];
    int m = blockIdx.x, kb = blockIdx.y;
    const float* src = (blockIdx.z ? inB : inA) + (size_t)m * 36864 + (size_t)kb * 4608;
    __half* dst = blockIdx.z ? outB : outA;
    for (int i = threadIdx.x; i < 1152; i += 256)
        *(float4*)(st + 4 * i) = *(const float4*)(src + 4 * i);
    __syncthreads();
    for (int j = threadIdx.x; j < 576; j += 256) {
        int t = j / 64, k = (j & 63) * 8;
        __half2 h[4];
#pragma unroll
        for (int q = 0; q < 4; q++)
            h[q] = __floats2half2_rn(st[(k + 2 * q) * 9 + t], st[(k + 2 * q + 1) * 9 + t]);
        size_t o = ((size_t)t * 512 + m) * 4096 + kb * 512 + k;
        *(uint4*)(dst + o) = *(uint4*)h;
    }
}

__global__ void wcenter(const float* __restrict__ in, __half* __restrict__ whi) {
    int i = blockIdx.x * 256 + threadIdx.x;
    if (i >= 512 * 2048) return;
    int e = i * 2, m = e >> 12, k = e & 4095;
    const float* p = in + (size_t)m * 36864 + k * 9 + 4;
    *(__half2*)(whi + e) = __floats2half2_rn(p[0], p[9]);
}

__global__ void wrf_k(const float* __restrict__ in, __half* __restrict__ out, int M, int K) {
    int i = blockIdx.x * 256 + threadIdx.x;
    if (i >= M * K * 9) return;
    int m = i / (K * 9);
    int rem = i - m * K * 9;
    int k = rem / 9, t = rem - k * 9;
    out[((size_t)t * 128 + m) * K + k] = __float2half_rn(in[i]);
}

// ============================ FFMA2 path (r2, c6) ============================
DEV_INLINE void tap_rect(int ti, int d, int centerOnly, int H, int W,
                         int& dy, int& dx, int& y0, int& x0, int& rh, int& rw) {
    if (centerOnly || d == 0) { dy = dx = 0; y0 = x0 = 0; rh = H; rw = W; return; }
    dy = (ti / 3 - 1) * d;
    dx = (ti % 3 - 1) * d;
    y0 = dy < 0 ? -dy : 0;
    x0 = dx < 0 ? -dx : 0;
    rh = H - (dy < 0 ? -dy : dy);
    rw = W - (dx < 0 ? -dx : dx);
}

template <int MT>
__global__ void __launch_bounds__(256, 2)
gemm2(const float* __restrict__ W, int Arow, int wstride, int wofs0, int centerOnly,
      const float* __restrict__ X, float* __restrict__ part,
      int M, int Kc, int kch, int H, int Wd, int d)
{
    constexpr int NT = 64, KT = 16;
    constexpr int ROWS = MT / 16;
    __shared__ float sA[KT][MT + 4];
    __shared__ float sB[KT][NT + 4];

    const int tid = threadIdx.x;
    const int s = blockIdx.z;
    const int ti = s / kch;
    const int kc = s - ti * kch;
    int dy, dx, y0, x0, rh, rw;
    tap_rect(ti, d, centerOnly, H, Wd, dy, dx, y0, x0, rh, rw);
    const int rectN = rh * rw;
    const int HW = H * Wd;
    const int n0 = blockIdx.x * NT;
    if (n0 >= rectN) return;
    const int m0 = blockIdx.y * MT;
    const int wofs = centerOnly ? wofs0 : ti;
    const int kcS = kc * Kc;

    const int nB = tid & 63, kB = tid >> 6;
    bool bval = false;
    const float* pB[4];
    {
        int pofs = 0;
        int nn = n0 + nB;
        if (nn < rectN) {
            int yy = nn / rw, xx = nn - yy * rw;
            bval = true;
            pofs = (y0 + yy + dy) * Wd + (x0 + xx + dx);
        }
#pragma unroll
        for (int t = 0; t < 4; t++) pB[t] = X + (size_t)(kcS + kB + 4 * t) * HW + pofs;
    }
    const int kA = tid & 15, mA = tid >> 4;
    const float* pA[ROWS];
    bool aval[ROWS];
#pragma unroll
    for (int t = 0; t < ROWS; t++) {
        int mg = m0 + mA + 16 * t;
        aval[t] = (mg < M);
        pA[t] = W + (aval[t] ? ((size_t)mg * Arow + wofs + (size_t)(kcS + kA) * wstride) : 0);
    }

    unsigned long long acc[ROWS][2];
#pragma unroll
    for (int i = 0; i < ROWS; i++) { acc[i][0] = 0ull; acc[i][1] = 0ull; }

    float rA[ROWS], rB[4];
#pragma unroll
    for (int t = 0; t < ROWS; t++) { rA[t] = aval[t] ? __ldg(pA[t]) : 0.f; pA[t] += (size_t)KT * wstride; }
#pragma unroll
    for (int t = 0; t < 4; t++) { rB[t] = bval ? __ldg(pB[t]) : 0.f; pB[t] += (size_t)KT * HW; }

    const int tx = tid & 15, ty = tid >> 4;

    for (int k0 = 0; k0 < Kc; k0 += KT) {
#pragma unroll
        for (int t = 0; t < ROWS; t++) sA[kA][mA + 16 * t] = rA[t];
#pragma unroll
        for (int t = 0; t < 4; t++) sB[kB + 4 * t][nB] = rB[t];
        __syncthreads();
        if (k0 + KT < Kc) {
#pragma unroll
            for (int t = 0; t < ROWS; t++) { rA[t] = aval[t] ? __ldg(pA[t]) : 0.f; pA[t] += (size_t)KT * wstride; }
#pragma unroll
            for (int t = 0; t < 4; t++) { rB[t] = bval ? __ldg(pB[t]) : 0.f; pB[t] += (size_t)KT * HW; }
        }
#pragma unroll
        for (int kk = 0; kk < KT; kk++) {
            const unsigned long long* bp =
                reinterpret_cast<const unsigned long long*>(&sB[kk][tx * 4]);
            unsigned long long b0 = bp[0], b1 = bp[1];
            const float* ar = &sA[kk][ty * ROWS];
#pragma unroll
            for (int i = 0; i < ROWS; i++) {
                float a = ar[i];
                unsigned long long ap = pk2(a, a);
                FFMA2(acc[i][0], ap, b0);
                FFMA2(acc[i][1], ap, b1);
            }
        }
        __syncthreads();
    }

    float* po = part + (size_t)s * M * HW;
#pragma unroll
    for (int i = 0; i < ROWS; i++) {
        int m = m0 + ty * ROWS + i;
        if (m >= M) continue;
        float vals[4];
        unpk2(acc[i][0], vals[0], vals[1]);
        unpk2(acc[i][1], vals[2], vals[3]);
#pragma unroll
        for (int j = 0; j < 4; j++) {
            int n2 = n0 + tx * 4 + j;
            if (n2 >= rectN) continue;
            int yy = n2 / rw, xx = n2 - yy * rw;
            po[(size_t)m * HW + (y0 + yy) * Wd + (x0 + xx)] = vals[j];
        }
    }
}

__global__ void reduce_k(const float* __restrict__ part, float* __restrict__ out,
                         int M, int H, int W, int d, int centerOnly, int ntaps, int kch,
                         int flags, const float* __restrict__ sc,
                         const float* __restrict__ bi, const float* __restrict__ eb) {
    int HW = H * W;
    int idx = blockIdx.x * 256 + threadIdx.x;
    if (idx >= M * HW) return;
    int m = idx / HW;
    int p = idx - m * HW;
    int y = p / W, x = p - y * W;
    float acc = 0.f;
    for (int s = 0; s < ntaps * kch; s++) {
        int ti = s / kch;
        int dy, dx, y0, x0, rh, rw;
        tap_rect(ti, d, centerOnly, H, W, dy, dx, y0, x0, rh, rw);
        if (y >= y0 && y < y0 + rh && x >= x0 && x < x0 + rw)
            acc += part[(size_t)s * M * HW + idx];
    }
    if (flags & 8) acc += eb[m];
    if (flags & 2) acc = sc[m] * acc + bi[m];
    if (flags & 4) acc = fmaxf(acc, 0.f);
    out[idx] = acc;
}

// ============================ small kernels ============================
__global__ void resize_kk(const float* __restrict__ in, float* __restrict__ out,
                          int C, int Hi, int Wi, int Ho, int Wo, int dorelu) {
    int i = blockIdx.x * 256 + threadIdx.x;
    int total = C * Ho * Wo;
    if (i >= total) return;
    int ox = i % Wo;
    int t = i / Wo;
    int oy = t % Ho;
    int c = t / Ho;
    float ry = (Ho > 1) ? (float)(Hi - 1) / (float)(Ho - 1) : 0.f;
    float rx = (Wo > 1) ? (float)(Wi - 1) / (float)(Wo - 1) : 0.f;
    float tyf = oy * ry;
    int yl = (int)floorf(tyf);
    float fy = tyf - yl;
    int yh = min(yl + 1, Hi - 1);
    float txf = ox * rx;
    int xl = (int)floorf(txf);
    float fx = txf - xl;
    int xh = min(xl + 1, Wi - 1);
    const float* p = in + (size_t)c * Hi * Wi;
    float v00 = p[yl * Wi + xl], v01 = p[yl * Wi + xh];
    float v10 = p[yh * Wi + xl], v11 = p[yh * Wi + xh];
    float v = (v00 * (1.f - fy) + v10 * fy) * (1.f - fx) + (v01 * (1.f - fy) + v11 * fy) * fx;
    if (dorelu) v = fmaxf(v, 0.f);
    out[i] = v;
}

__global__ void energy_k(const float* __restrict__ c1r, const float* __restrict__ c2r,
                         float* __restrict__ att) {
    int p = blockIdx.x * 256 + threadIdx.x;
    if (p >= 4096) return;
    int y = p >> 6, x = p & 63;
    float e[9];
    int nidx[9];
    bool val[9];
#pragma unroll
    for (int a = 0; a < 3; a++)
#pragma unroll
        for (int b = 0; b < 3; b++) {
            int k = a * 3 + b;
            int iy = y + 2 * (a - 1), ix = x + 2 * (b - 1);
            val[k] = (unsigned)iy < 64u && (unsigned)ix < 64u;
            nidx[k] = val[k] ? (iy * 64 + ix) : 0;
            e[k] = 0.f;
        }
    for (int c = 0; c < 64; c++) {
        float v = c1r[c * 4096 + p];
        const float* row = c2r + c * 4096;
#pragma unroll
        for (int k = 0; k < 9; k++)
            if (val[k]) e[k] = fmaf(v, row[nidx[k]], e[k]);
    }
    float mx = e[0];
#pragma unroll
    for (int k = 1; k < 9; k++) mx = fmaxf(mx, e[k]);
    float sum = 0.f, ex[9];
#pragma unroll
    for (int k = 0; k < 9; k++) { ex[k] = expf(e[k] - mx); sum += ex[k]; }
    float inv = 1.f / sum;
#pragma unroll
    for (int k = 0; k < 9; k++) att[k * 4096 + p] = ex[k] * inv;
}

__global__ void gap_k(const float* __restrict__ x, float* __restrict__ gap) {
    int c = blockIdx.x * 8 + (threadIdx.x >> 5);
    int lane = threadIdx.x & 31;
    const float* p = x + (size_t)c * 1024;
    float s = 0.f;
    for (int i = lane; i < 1024; i += 32) s += p[i];
#pragma unroll
    for (int o = 16; o; o >>= 1) s += __shfl_xor_sync(0xffffffffu, s, o);
    if (!lane) gap[c] = s * (1.f / 1024.f);
}

__global__ void f4_k(const float* __restrict__ w, const float* __restrict__ s,
                     const float* __restrict__ b, const float* __restrict__ gap,
                     float* __restrict__ f4) {
    int o = blockIdx.x * 8 + (threadIdx.x >> 5);
    int lane = threadIdx.x & 31;
    const float* row = w + (size_t)o * 4096;
    float acc = 0.f;
    for (int i = lane; i < 4096; i += 32) acc = fmaf(row[i], gap[i], acc);
#pragma unroll
    for (int off = 16; off; off >>= 1) acc += __shfl_xor_sync(0xffffffffu, acc, off);
    if (!lane) f4[o] = fmaxf(s[o] * acc + b[o], 0.f);
}

__global__ void bias4_k(const float* __restrict__ apw, const float* __restrict__ f4,
                        float* __restrict__ b4) {
    int o = blockIdx.x * 8 + (threadIdx.x >> 5);
    int lane = threadIdx.x & 31;
    const float* row = apw + (size_t)o * 2560 + 2048;
    float acc = 0.f;
    for (int i = lane; i < 512; i += 32) acc = fmaf(row[i], f4[i], acc);
#pragma unroll
    for (int off = 16; off; off >>= 1) acc += __shfl_xor_sync(0xffffffffu, acc, off);
    if (!lane) b4[o] = acc;
}

__global__ void agg_k(const float* __restrict__ att, const float* __restrict__ zup,
                      const float* __restrict__ c6b, float* __restrict__ out) {
    int p = blockIdx.x * 256 + threadIdx.x;
    if (p >= 4096) return;
    int y = p >> 6, x = p & 63;
    float acc[19];
#pragma unroll
    for (int o = 0; o < 19; o++) acc[o] = c6b[o];
#pragma unroll
    for (int a = 0; a < 3; a++)
#pragma unroll
        for (int b = 0; b < 3; b++) {
            int k = a * 3 + b;
            int iy = y + 2 * (a - 1), ix = x + 2 * (b - 1);
            if ((unsigned)iy < 64u && (unsigned)ix < 64u) {
                float w = att[k * 4096 + p];
                int n = iy * 64 + ix;
#pragma unroll
                for (int o = 0; o < 19; o++) acc[o] = fmaf(w, zup[o * 4096 + n], acc[o]);
            }
        }
#pragma unroll
    for (int o = 0; o < 19; o++) out[o * 4096 + p] = acc[o];
}

// ============================ host driver ============================
static float* g_part_p;
static float* g_part2_p;

static void run_conv(int mt, const float* Wt, int Arow, int wstride, int wofs0, int centerOnly,
                     const float* X, float* Cout,
                     int M, int K, int H, int Wd, int d, int kch,
                     const float* sc, const float* bi, const float* eb, int flags) {
    int ntaps = (d > 0 && !centerOnly) ? 9 : 1;
    int HW = H * Wd;
    int Kc = K / kch;
    dim3 grid((HW + 63) / 64, (M + mt - 1) / mt, ntaps * kch);
    if (mt == 128)
        gemm2<128><<<grid, 256>>>(Wt, Arow, wstride, wofs0, centerOnly, X, g_part2_p,
                                  M, Kc, kch, H, Wd, d);
    else
        gemm2<64><<<grid, 256>>>(Wt, Arow, wstride, wofs0, centerOnly, X, g_part2_p,
                                 M, Kc, kch, H, Wd, d);
    int tot = M * HW;
    reduce_k<<<(tot + 255) / 256, 256>>>(g_part2_p, Cout, M, H, Wd, d, centerOnly,
                                         ntaps, kch, flags, sc, bi, eb);
}

extern "C" void kernel_launch(void* const* d_in, const int* in_sizes, int n_in,
                              void* d_out, int out_size) {
    const float* c1 = (const float*)d_in[0];
    const float* c2 = (const float*)d_in[1];
    const float* x = (const float*)d_in[2];
    const float* rf1_w = (const float*)d_in[3];
    const float* rf1_s = (const float*)d_in[4];
    const float* rf1_b = (const float*)d_in[5];
    const float* rf2_w = (const float*)d_in[6];
    const float* rf2_s = (const float*)d_in[7];
    const float* rf2_b = (const float*)d_in[8];
    const float* r2_w = (const float*)d_in[9];
    const float* r2_s = (const float*)d_in[10];
    const float* r2_b = (const float*)d_in[11];
    const float* a0_w = (const float*)d_in[12];
    const float* a0_s = (const float*)d_in[13];
    const float* a0_b = (const float*)d_in[14];
    const float* a1_w = (const float*)d_in[15];
    const float* a1_s = (const float*)d_in[16];
    const float* a1_b = (const float*)d_in[17];
    const float* a2_w = (const float*)d_in[18];
    const float* a2_s = (const float*)d_in[19];
    const float* a2_b = (const float*)d_in[20];
    const float* a3_w = (const float*)d_in[21];
    const float* a3_s = (const float*)d_in[22];
    const float* a3_b = (const float*)d_in[23];
    const float* a4_w = (const float*)d_in[24];
    const float* a4_s = (const float*)d_in[25];
    const float* a4_b = (const float*)d_in[26];
    const float* ap_w = (const float*)d_in[27];
    const float* ap_s = (const float*)d_in[28];
    const float* ap_b = (const float*)d_in[29];
    const float* c6_w = (const float*)d_in[30];
    const float* c6_b = (const float*)d_in[31];

    float *t2, *c1r, *c2r, *att, *gap, *f4, *b4, *outb, *z, *zup;
    __half *whi, *xthi, *fhi, *c1thi, *c1tlo, *t1thi, *t1tlo;
    cudaGetSymbolAddress((void**)&g_part_p, g_part);
    cudaGetSymbolAddress((void**)&g_part2_p, g_part2);
    cudaGetSymbolAddress((void**)&t2, g_t2);
    cudaGetSymbolAddress((void**)&c1r, g_c1r);
    cudaGetSymbolAddress((void**)&c2r, g_c2r);
    cudaGetSymbolAddress((void**)&att, g_att);
    cudaGetSymbolAddress((void**)&gap, g_gap);
    cudaGetSymbolAddress((void**)&f4, g_f4);
    cudaGetSymbolAddress((void**)&b4, g_b4);
    cudaGetSymbolAddress((void**)&outb, g_outb);
    cudaGetSymbolAddress((void**)&z, g_z);
    cudaGetSymbolAddress((void**)&zup, g_zup);
    cudaGetSymbolAddress((void**)&whi, g_whi);
    cudaGetSymbolAddress((void**)&xthi, g_xthi);
    cudaGetSymbolAddress((void**)&fhi, g_fhi);
    cudaGetSymbolAddress((void**)&c1thi, g_c1thi);
    cudaGetSymbolAddress((void**)&c1tlo, g_c1tlo);
    cudaGetSymbolAddress((void**)&t1thi, g_t1thi);
    cudaGetSymbolAddress((void**)&t1tlo, g_t1tlo);

    const size_t PB = 512 * 1024 * sizeof(float);   // 2MB per accumulation slice
    const int SMEM_H1 = 3 * 18432 * 2;
    const int SMEM_H2 = 2 * 27648 * 2;
    cudaFuncSetAttribute(hgemm_aspp, cudaFuncAttributeMaxDynamicSharedMemorySize, SMEM_H1);
    cudaFuncSetAttribute(hgemm<0>, cudaFuncAttributeMaxDynamicSharedMemorySize, SMEM_H1);
    cudaFuncSetAttribute(hgemm<1>, cudaFuncAttributeMaxDynamicSharedMemorySize, SMEM_H2);

    // --- conversions + merged ASPP (one GEMM launch, 4 accumulation buffers) ---
    cudaMemsetAsync(g_part_p, 0, 4 * PB);
    xtrans_g<<<dim3(32, 128), 256>>>(x, xthi, nullptr, 1024, 4096);
    wconv3x3b<<<dim3(512, 8, 2), 256>>>(a1_w, a2_w, whi + S_A1, whi + S_A2);
    wconv1x1<<<(512 * 4096 / 4 + 255) / 256, 256>>>(a0_w, 4096, 4096, whi + S_A0, 512 * 1024);
    wcenter<<<(512 * 2048 + 255) / 256, 256>>>(a3_w, whi + S_A3);
    hgemm_aspp<<<dim3(8, 4, 104), 256, SMEM_H1>>>(whi, g_part_p, xthi);
    reduce_ht<<<dim3(32, 16), 256>>>(g_part_p, 1024, a1_s, a1_b, fhi, nullptr, 2048, 512);
    reduce_ht<<<dim3(32, 16), 256>>>(g_part_p + 524288, 1024, a2_s, a2_b, fhi, nullptr, 2048, 1024);
    reduce_ht<<<dim3(32, 16), 256>>>(g_part_p + 2 * 524288, 1024, a0_s, a0_b, fhi, nullptr, 2048, 0);
    reduce_ht<<<dim3(32, 16), 256>>>(g_part_p + 3 * 524288, 1024, a3_s, a3_b, fhi, nullptr, 2048, 1536);

    // --- attention branch: refine convs on HMMA (2-pass for accuracy) ---
    xtrans_g<<<dim3(128, 8), 256>>>(c1, c1thi, c1tlo, 4096, 256);
    wrf_k<<<(64 * 256 * 9 + 255) / 256, 256>>>(rf1_w, whi + S_RF1, 64, 256);
    wrf_k<<<(64 * 64 * 9 + 255) / 256, 256>>>(rf2_w, whi + S_RF2, 64, 64);
    cudaMemsetAsync(g_part_p, 0, PB);
    hgemm<1><<<dim3(32, 1, 9), 256, SMEM_H2>>>(whi + S_RF1, c1thi, c1tlo, g_part_p,
                                               256, 256, 256, 1, 1, 2, 6, 4096, 1);
    reduce_ht<<<dim3(128, 2), 256>>>(g_part_p, 4096, rf1_s, rf1_b, t1thi, t1tlo, 64, 0);
    cudaMemsetAsync(g_part_p, 0, PB);
    hgemm<1><<<dim3(32, 1, 9), 256, SMEM_H2>>>(whi + S_RF2, t1thi, t1tlo, g_part_p,
                                               64, 64, 64, 1, 1, 2, 6, 4096, 1);
    reduce_pl<<<(64 * 4096 + 255) / 256, 256>>>(g_part_p, c1r, 4096, 64, 6,
                                                rf2_s, rf2_b, nullptr);
    run_conv(64, r2_w, 512, 1, 0, 1, c2, t2, 64, 512, 32, 32, 0, 4, r2_s, r2_b, nullptr, 2);
    resize_kk<<<(64 * 4096 + 255) / 256, 256>>>(t2, c2r, 64, 32, 32, 64, 64, 1);
    energy_k<<<16, 256>>>(c1r, c2r, att);

    // --- GAP branch + ap (single-pass) ---
    gap_k<<<512, 256>>>(x, gap);
    f4_k<<<64, 256>>>(a4_w, a4_s, a4_b, gap, f4);
    bias4_k<<<64, 256>>>(ap_w, f4, b4);
    wconv1x1<<<(512 * 2048 / 4 + 255) / 256, 256>>>(ap_w, 2560, 2048, whi + S_AP, 512 * 512);
    cudaMemsetAsync(g_part_p, 0, PB);
    hgemm<0><<<dim3(8, 4, 8), 256, SMEM_H1>>>(whi + S_AP, fhi, nullptr, g_part_p,
                                              2048, 256, 2048, 8, 0, 0, 5, 1024, 0);
    reduce_pl<<<2048, 256>>>(g_part_p, outb, 1024, 512, 2 | 4 | 8, ap_s, ap_b, b4);

    // --- final head ---
    run_conv(64, c6_w, 512, 1, 0, 1, outb, z, 19, 512, 32, 32, 0, 4, nullptr, nullptr, nullptr, 0);
    resize_kk<<<(19 * 4096 + 255) / 256, 256>>>(z, zup, 19, 32, 32, 64, 64, 0);
    agg_k<<<16, 256>>>(att, zup, c6_b, (float*)d_out);
}